// round 5
// baseline (speedup 1.0000x reference)
#include <cuda_runtime.h>
#include <math.h>
#include <stdint.h>

#define BB 2
#define NN 1024
#define DD 512
#define HH 8
#define DHH 64
#define HD 512
#define FFD 2048
#define DEPTH 4

// ---------------- device scratch ----------------
__device__ float g_x  [BB*NN*DD];
__device__ float g_xn [BB*NN*DD];
__device__ float g_qkv[BB*NN*3*HD];
__device__ float g_ws [BB*NN*HD];
__device__ float g_AC [(size_t)BB*HH*NN*NN];
__device__ float g_BD [(size_t)BB*HH*NN*NN];
__device__ float g_attn[(size_t)BB*HH*NN*NN];
__device__ float g_av [BB*NN*HD];
__device__ float g_h1 [BB*NN*FFD];
__device__ float g_rcat [BB*NN * 3*DD];            // [r_t | r_c | r_p] packed, K=1536
__device__ float g_wqkvT[DEPTH * 3*HD * DD];
__device__ float g_wcatT[DEPTH * HD * 3*DD];       // [w_kt; w_kc; w_kp] transposed+concat
__device__ float g_woutT[DEPTH * DD * HD];
__device__ float g_wff1T[DEPTH * FFD * DD];
__device__ float g_wff2T[DEPTH * DD * FFD];

__device__ __forceinline__ uint32_t tf32r(float x) {
    uint32_t y; asm("cvt.rna.tf32.f32 %0, %1;" : "=r"(y) : "f"(x)); return y;
}
__device__ __forceinline__ float tf32f(float x) {
    return __uint_as_float(tf32r(x));
}
__device__ __forceinline__ void mma8(float* d, const uint32_t* a, const uint32_t* b) {
    asm volatile("mma.sync.aligned.m16n8k8.row.col.f32.tf32.tf32.f32 "
        "{%0,%1,%2,%3}, {%4,%5,%6,%7}, {%8,%9}, {%0,%1,%2,%3};"
        : "+f"(d[0]), "+f"(d[1]), "+f"(d[2]), "+f"(d[3])
        : "r"(a[0]), "r"(a[1]), "r"(a[2]), "r"(a[3]), "r"(b[0]), "r"(b[1]));
}

// ---------------- simple copies / packing ----------------
__global__ void copy_in_kernel(const float* __restrict__ src) {
    int i = blockIdx.x * 256 + threadIdx.x;
    g_x[i] = src[i];
}
__global__ void copy_out_kernel(float* __restrict__ dst) {
    int i = blockIdx.x * 256 + threadIdx.x;
    dst[i] = g_x[i];
}
__global__ void pack_r_kernel(const float* __restrict__ rt, const float* __restrict__ rc,
                              const float* __restrict__ rp) {
    int idx = blockIdx.x * 256 + threadIdx.x;      // over BB*NN*1536
    int m = idx / (3 * DD), k = idx % (3 * DD);
    float v;
    if (k < DD)            v = rt[m * DD + k];
    else if (k < 2 * DD)   v = rc[m * DD + k - DD];
    else                   v = rp[m * DD + k - 2 * DD];
    g_rcat[idx] = v;
}

// ---------------- weight transpose: src [R,C] (per layer) -> dst [C, dstStride] at colBase ----------------
__global__ void transpose_batch(const float* __restrict__ src, float* __restrict__ dst,
                                int R, int C, int dstStride, int colBase, size_t dstLayer) {
    __shared__ float t[32][33];
    size_t soff = (size_t)blockIdx.z * R * C;
    size_t doff = (size_t)blockIdx.z * dstLayer;
    int c0 = blockIdx.x * 32, r0 = blockIdx.y * 32;
    int x = threadIdx.x, y = threadIdx.y;
#pragma unroll
    for (int i = 0; i < 32; i += 8)
        t[y + i][x] = src[soff + (size_t)(r0 + y + i) * C + c0 + x];
    __syncthreads();
#pragma unroll
    for (int i = 0; i < 32; i += 8)
        dst[doff + (size_t)(c0 + y + i) * dstStride + colBase + r0 + x] = t[x][y + i];
}

// ---------------- layernorm ----------------
__global__ void ln_kernel(const float* __restrict__ x, const float* __restrict__ g,
                          const float* __restrict__ bta, float* __restrict__ y) {
    __shared__ float red[128];
    int row = blockIdx.x;
    int tid = threadIdx.x;
    const float4* xr = (const float4*)(x + (size_t)row * DD);
    float4 v = xr[tid];
    red[tid] = v.x + v.y + v.z + v.w;
    __syncthreads();
    for (int o = 64; o > 0; o >>= 1) { if (tid < o) red[tid] += red[tid + o]; __syncthreads(); }
    float mean = red[0] * (1.0f / DD);
    __syncthreads();
    float dx = v.x - mean, dy = v.y - mean, dz = v.z - mean, dw = v.w - mean;
    red[tid] = dx*dx + dy*dy + dz*dz + dw*dw;
    __syncthreads();
    for (int o = 64; o > 0; o >>= 1) { if (tid < o) red[tid] += red[tid + o]; __syncthreads(); }
    float rstd = rsqrtf(red[0] * (1.0f / DD) + 1e-5f);
    float4 gv = ((const float4*)g)[tid];
    float4 bv = ((const float4*)bta)[tid];
    float4 o4;
    o4.x = dx * rstd * gv.x + bv.x;
    o4.y = dy * rstd * gv.y + bv.y;
    o4.z = dz * rstd * gv.z + bv.z;
    o4.w = dw * rstd * gv.w + bv.w;
    ((float4*)(y + (size_t)row * DD))[tid] = o4;
}

__device__ __forceinline__ float gelu_exact(float v) {
    return 0.5f * v * (1.0f + erff(v * 0.70710678118654752f));
}

// ---------------- mma.sync tf32 GEMM: 64x64 tile, 128 threads, BK=32 ----------------
#define S64 72
#define BUF64 (32 * S64)                 // 2304 words per buffer
#define MG64_SMEM (4 * BUF64 * 4)        // 36864 bytes

template<bool ACCUM, bool BIAS, bool RES, bool GELU_>
__global__ void __launch_bounds__(128, 4)
mgemm64(const float* __restrict__ A, const float* __restrict__ Bt, float* __restrict__ C,
        int Nc, int K, const float* __restrict__ bias, const float* __restrict__ res) {
    extern __shared__ float sm[];
    float* sA[2] = { sm, sm + BUF64 };
    float* sB[2] = { sm + 2 * BUF64, sm + 3 * BUF64 };

    const int tid = threadIdx.x;
    const int wid = tid >> 5, lid = tid & 31;
    const int row0 = blockIdx.y * 64;
    const int col0 = blockIdx.x * 64;

    const int arow = tid & 63;            // row (A) / n-row (B)
    const int akb  = (tid >> 6) * 16;     // k base
    const float* gA = A  + (size_t)(row0 + arow) * K + akb;
    const float* gB = Bt + (size_t)(col0 + arow) * K + akb;

    float acc[2][4][4];
#pragma unroll
    for (int mt = 0; mt < 2; mt++)
#pragma unroll
        for (int nt = 0; nt < 4; nt++)
#pragma unroll
            for (int r = 0; r < 4; r++) acc[mt][nt][r] = 0.f;

    float ar[16], br[16];
    const int nch = K >> 5;

#pragma unroll
    for (int i = 0; i < 4; i++) {
        float4 va = *(const float4*)(gA + i * 4);
        ar[4*i] = va.x; ar[4*i+1] = va.y; ar[4*i+2] = va.z; ar[4*i+3] = va.w;
        float4 vb = *(const float4*)(gB + i * 4);
        br[4*i] = vb.x; br[4*i+1] = vb.y; br[4*i+2] = vb.z; br[4*i+3] = vb.w;
    }
#pragma unroll
    for (int i = 0; i < 16; i++) {
        sA[0][(akb + i) * S64 + arow] = tf32f(ar[i]);
        sB[0][(akb + i) * S64 + arow] = tf32f(br[i]);
    }
    __syncthreads();

    const int wm = (wid & 1) * 32;
    const int wn = (wid >> 1) * 32;
    const int g  = lid >> 2;
    const int tg = lid & 3;

    int p = 0;
    for (int c = 0; c < nch; c++) {
        if (c + 1 < nch) {
            const float* pa = gA + (size_t)(c + 1) * 32;
            const float* pb = gB + (size_t)(c + 1) * 32;
#pragma unroll
            for (int i = 0; i < 4; i++) {
                float4 va = *(const float4*)(pa + i * 4);
                ar[4*i] = va.x; ar[4*i+1] = va.y; ar[4*i+2] = va.z; ar[4*i+3] = va.w;
                float4 vb = *(const float4*)(pb + i * 4);
                br[4*i] = vb.x; br[4*i+1] = vb.y; br[4*i+2] = vb.z; br[4*i+3] = vb.w;
            }
        }
        const float* cA = sA[p];
        const float* cB = sB[p];
#pragma unroll
        for (int s = 0; s < 4; s++) {
            const int k0 = s * 8;
            uint32_t afr[2][4];
#pragma unroll
            for (int mt = 0; mt < 2; mt++) {
                int row = wm + mt * 16 + g;
                afr[mt][0] = __float_as_uint(cA[(k0 + tg)     * S64 + row]);
                afr[mt][1] = __float_as_uint(cA[(k0 + tg)     * S64 + row + 8]);
                afr[mt][2] = __float_as_uint(cA[(k0 + tg + 4) * S64 + row]);
                afr[mt][3] = __float_as_uint(cA[(k0 + tg + 4) * S64 + row + 8]);
            }
            uint32_t bfr[4][2];
#pragma unroll
            for (int nt = 0; nt < 4; nt++) {
                int cn = wn + nt * 8 + g;
                bfr[nt][0] = __float_as_uint(cB[(k0 + tg)     * S64 + cn]);
                bfr[nt][1] = __float_as_uint(cB[(k0 + tg + 4) * S64 + cn]);
            }
#pragma unroll
            for (int mt = 0; mt < 2; mt++)
#pragma unroll
                for (int nt = 0; nt < 4; nt++)
                    mma8(acc[mt][nt], afr[mt], bfr[nt]);
        }
        if (c + 1 < nch) {
            float* dA = sA[1 - p];
            float* dB = sB[1 - p];
#pragma unroll
            for (int i = 0; i < 16; i++) {
                dA[(akb + i) * S64 + arow] = tf32f(ar[i]);
                dB[(akb + i) * S64 + arow] = tf32f(br[i]);
            }
        }
        __syncthreads();
        p ^= 1;
    }

#pragma unroll
    for (int mt = 0; mt < 2; mt++) {
#pragma unroll
        for (int rh = 0; rh < 2; rh++) {
            int row = row0 + wm + mt * 16 + g + rh * 8;
#pragma unroll
            for (int nt = 0; nt < 4; nt++) {
                int col = col0 + wn + nt * 8 + tg * 2;
                size_t idx = (size_t)row * Nc + col;
                float v0 = acc[mt][nt][rh * 2 + 0];
                float v1 = acc[mt][nt][rh * 2 + 1];
                if (ACCUM) { float2 o = *(const float2*)(C + idx); v0 += o.x; v1 += o.y; }
                if (BIAS)  { float2 bv = *(const float2*)(bias + col); v0 += bv.x; v1 += bv.y; }
                if (RES)   { float2 rv = *(const float2*)(res + idx); v0 += rv.x; v1 += rv.y; }
                if (GELU_) { v0 = gelu_exact(v0); v1 = gelu_exact(v1); }
                float2 o2 = make_float2(v0, v1);
                *(float2*)(C + idx) = o2;
            }
        }
    }
}

// ---------------- scores via mma: AC = Q.K^T, BD = Q.Ws^T (per b,h; K=64) ----------------
#define SC_STRIDE 72
#define SC_SMEM (3 * 64 * SC_STRIDE * 4)
__global__ void __launch_bounds__(256, 4)
scores_mma(const float* __restrict__ qkv, const float* __restrict__ ws,
           const float* __restrict__ bias_pf,
           float* __restrict__ AC, float* __restrict__ BD) {
    extern __shared__ float sm[];
    float* Qs = sm;
    float* Ks = sm + 64 * SC_STRIDE;
    float* Ws = sm + 128 * SC_STRIDE;
    const int bh = blockIdx.z;
    const int b = bh >> 3, h = bh & 7;
    const int i0 = blockIdx.y << 6, j0 = blockIdx.x << 6;
    const int tid = threadIdx.x;

    const int r  = tid >> 2;
    const int d0 = (tid & 3) << 4;
    const float* qb = qkv + (size_t)(b * NN + i0 + r) * (3 * HD) + h * DHH + d0;
    const float* kb = qkv + (size_t)(b * NN + j0 + r) * (3 * HD) + HD + h * DHH + d0;
    const float* wb = ws  + (size_t)(b * NN + j0 + r) * HD + h * DHH + d0;
    const float* pf = bias_pf + h * DHH + d0;
#pragma unroll
    for (int t = 0; t < 4; t++) {
        float4 q4 = *(const float4*)(qb + t * 4);
        float4 p4 = *(const float4*)(pf + t * 4);
        int d = d0 + t * 4;
        Qs[(d + 0) * SC_STRIDE + r] = tf32f(q4.x + p4.x);
        Qs[(d + 1) * SC_STRIDE + r] = tf32f(q4.y + p4.y);
        Qs[(d + 2) * SC_STRIDE + r] = tf32f(q4.z + p4.z);
        Qs[(d + 3) * SC_STRIDE + r] = tf32f(q4.w + p4.w);
        float4 k4 = *(const float4*)(kb + t * 4);
        Ks[(d + 0) * SC_STRIDE + r] = tf32f(k4.x);
        Ks[(d + 1) * SC_STRIDE + r] = tf32f(k4.y);
        Ks[(d + 2) * SC_STRIDE + r] = tf32f(k4.z);
        Ks[(d + 3) * SC_STRIDE + r] = tf32f(k4.w);
        float4 w4 = *(const float4*)(wb + t * 4);
        Ws[(d + 0) * SC_STRIDE + r] = tf32f(w4.x);
        Ws[(d + 1) * SC_STRIDE + r] = tf32f(w4.y);
        Ws[(d + 2) * SC_STRIDE + r] = tf32f(w4.z);
        Ws[(d + 3) * SC_STRIDE + r] = tf32f(w4.w);
    }
    __syncthreads();

    const int wid = tid >> 5, lid = tid & 31;
    const int grp = wid >> 2;
    const int w2  = wid & 3;
    const int wm  = (w2 & 1) * 32;
    const int wn  = (w2 >> 1) * 32;
    const float* Bm = grp ? Ws : Ks;
    const int g = lid >> 2, tg = lid & 3;

    float acc[2][4][4];
#pragma unroll
    for (int mt = 0; mt < 2; mt++)
#pragma unroll
        for (int nt = 0; nt < 4; nt++)
#pragma unroll
            for (int q = 0; q < 4; q++) acc[mt][nt][q] = 0.f;

#pragma unroll
    for (int s = 0; s < 8; s++) {
        const int k0 = s * 8;
        uint32_t afr[2][4];
#pragma unroll
        for (int mt = 0; mt < 2; mt++) {
            int row = wm + mt * 16 + g;
            afr[mt][0] = __float_as_uint(Qs[(k0 + tg)     * SC_STRIDE + row]);
            afr[mt][1] = __float_as_uint(Qs[(k0 + tg)     * SC_STRIDE + row + 8]);
            afr[mt][2] = __float_as_uint(Qs[(k0 + tg + 4) * SC_STRIDE + row]);
            afr[mt][3] = __float_as_uint(Qs[(k0 + tg + 4) * SC_STRIDE + row + 8]);
        }
        uint32_t bfr[4][2];
#pragma unroll
        for (int nt = 0; nt < 4; nt++) {
            int cn = wn + nt * 8 + g;
            bfr[nt][0] = __float_as_uint(Bm[(k0 + tg)     * SC_STRIDE + cn]);
            bfr[nt][1] = __float_as_uint(Bm[(k0 + tg + 4) * SC_STRIDE + cn]);
        }
#pragma unroll
        for (int mt = 0; mt < 2; mt++)
#pragma unroll
            for (int nt = 0; nt < 4; nt++)
                mma8(acc[mt][nt], afr[mt], bfr[nt]);
    }

    float* Out = grp ? BD : AC;
    const size_t base = ((size_t)bh << 20);
#pragma unroll
    for (int mt = 0; mt < 2; mt++) {
#pragma unroll
        for (int rh = 0; rh < 2; rh++) {
            int i = i0 + wm + mt * 16 + g + rh * 8;
#pragma unroll
            for (int nt = 0; nt < 4; nt++) {
                int j = j0 + wn + nt * 8 + tg * 2;
                float2 o2 = make_float2(acc[mt][nt][rh * 2 + 0], acc[mt][nt][rh * 2 + 1]);
                *(float2*)(Out + base + ((size_t)i << 10) + j) = o2;
            }
        }
    }
}

// ---------------- dots + rel_shift + softmax over heads ----------------
__global__ void softmax_kernel(const float* __restrict__ AC, const float* __restrict__ BD,
                               float* __restrict__ attn) {
    int idx = blockIdx.x * 256 + threadIdx.x;
    int b = idx >> 20;
    int ij = idx & ((1 << 20) - 1);
    int i = ij >> 10, j = ij & 1023;
    int m  = (i + 1) * NN + j;
    int i2 = m / (NN + 1);
    int k  = m - i2 * (NN + 1);
    size_t pb = ((size_t)(b * HH)) << 20;
    size_t shifted = ((size_t)i2 << 10) + (k - 1);
    float vals[8];
#pragma unroll
    for (int h = 0; h < 8; h++) {
        float ac = AC[pb + ((size_t)h << 20) + ij];
        float bd = (k != 0) ? BD[pb + ((size_t)h << 20) + shifted] : 0.f;
        vals[h] = (ac + bd * (1.0f / 3.0f)) * 0.125f;
    }
    float mx = vals[0];
#pragma unroll
    for (int h = 1; h < 8; h++) mx = fmaxf(mx, vals[h]);
    float s = 0.f;
#pragma unroll
    for (int h = 0; h < 8; h++) { vals[h] = expf(vals[h] - mx); s += vals[h]; }
    float inv = 1.0f / s;
#pragma unroll
    for (int h = 0; h < 8; h++) attn[pb + ((size_t)h << 20) + ij] = vals[h] * inv;
}

// ---------------- attn @ v via mma: 64x64 tile, 128 threads ----------------
__global__ void __launch_bounds__(128, 4)
attnv64(const float* __restrict__ attn, const float* __restrict__ qkv,
        float* __restrict__ av) {
    extern __shared__ float sm[];
    float* sA[2] = { sm, sm + BUF64 };
    float* sB[2] = { sm + 2 * BUF64, sm + 3 * BUF64 };

    const int bh = blockIdx.y;
    const int b = bh >> 3, h = bh & 7;
    const int i0 = blockIdx.x << 6;
    const int tid = threadIdx.x;
    const int wid = tid >> 5, lid = tid & 31;

    const int arow = tid & 63;
    const int akb  = (tid >> 6) * 16;
    const int bj0  = tid >> 4;            // 0..7 (j row group)
    const int bd4  = (tid & 15) * 4;      // 0..60 (d offset)
    const float* gA = attn + ((size_t)bh << 20) + ((size_t)(i0 + arow) << 10) + akb;
    const float* gV = qkv + 2 * HD + h * DHH + bd4;

    float acc[2][4][4];
#pragma unroll
    for (int mt = 0; mt < 2; mt++)
#pragma unroll
        for (int nt = 0; nt < 4; nt++)
#pragma unroll
            for (int q = 0; q < 4; q++) acc[mt][nt][q] = 0.f;

    float ar[16];
    float4 br4[4];
    const int nch = NN >> 5;  // 32

    {
#pragma unroll
        for (int i = 0; i < 4; i++) {
            float4 v = *(const float4*)(gA + i * 4);
            ar[4*i] = v.x; ar[4*i+1] = v.y; ar[4*i+2] = v.z; ar[4*i+3] = v.w;
        }
#pragma unroll
        for (int rr = 0; rr < 4; rr++)
            br4[rr] = *(const float4*)(gV + (size_t)(b * NN + bj0 + rr * 8) * (3 * HD));
#pragma unroll
        for (int i = 0; i < 16; i++)
            sA[0][(akb + i) * S64 + arow] = tf32f(ar[i]);
#pragma unroll
        for (int rr = 0; rr < 4; rr++) {
            float4 t = make_float4(tf32f(br4[rr].x), tf32f(br4[rr].y),
                                   tf32f(br4[rr].z), tf32f(br4[rr].w));
            *(float4*)&sB[0][(bj0 + rr * 8) * S64 + bd4] = t;
        }
    }
    __syncthreads();

    const int wm = (wid & 1) * 32;
    const int wn = (wid >> 1) * 32;
    const int g  = lid >> 2;
    const int tg = lid & 3;

    int p = 0;
    for (int c = 0; c < nch; c++) {
        if (c + 1 < nch) {
            const float* pa = gA + (size_t)(c + 1) * 32;
#pragma unroll
            for (int i = 0; i < 4; i++) {
                float4 v = *(const float4*)(pa + i * 4);
                ar[4*i] = v.x; ar[4*i+1] = v.y; ar[4*i+2] = v.z; ar[4*i+3] = v.w;
            }
#pragma unroll
            for (int rr = 0; rr < 4; rr++)
                br4[rr] = *(const float4*)(gV + (size_t)(b * NN + (c + 1) * 32 + bj0 + rr * 8) * (3 * HD));
        }
        const float* cA = sA[p];
        const float* cB = sB[p];
#pragma unroll
        for (int s = 0; s < 4; s++) {
            const int k0 = s * 8;
            uint32_t afr[2][4];
#pragma unroll
            for (int mt = 0; mt < 2; mt++) {
                int row = wm + mt * 16 + g;
                afr[mt][0] = __float_as_uint(cA[(k0 + tg)     * S64 + row]);
                afr[mt][1] = __float_as_uint(cA[(k0 + tg)     * S64 + row + 8]);
                afr[mt][2] = __float_as_uint(cA[(k0 + tg + 4) * S64 + row]);
                afr[mt][3] = __float_as_uint(cA[(k0 + tg + 4) * S64 + row + 8]);
            }
            uint32_t bfr[4][2];
#pragma unroll
            for (int nt = 0; nt < 4; nt++) {
                int cn = wn + nt * 8 + g;
                bfr[nt][0] = __float_as_uint(cB[(k0 + tg)     * S64 + cn]);
                bfr[nt][1] = __float_as_uint(cB[(k0 + tg + 4) * S64 + cn]);
            }
#pragma unroll
            for (int mt = 0; mt < 2; mt++)
#pragma unroll
                for (int nt = 0; nt < 4; nt++)
                    mma8(acc[mt][nt], afr[mt], bfr[nt]);
        }
        if (c + 1 < nch) {
            float* dA = sA[1 - p];
            float* dB = sB[1 - p];
#pragma unroll
            for (int i = 0; i < 16; i++)
                dA[(akb + i) * S64 + arow] = tf32f(ar[i]);
#pragma unroll
            for (int rr = 0; rr < 4; rr++) {
                float4 t = make_float4(tf32f(br4[rr].x), tf32f(br4[rr].y),
                                       tf32f(br4[rr].z), tf32f(br4[rr].w));
                *(float4*)&dB[(bj0 + rr * 8) * S64 + bd4] = t;
            }
        }
        __syncthreads();
        p ^= 1;
    }

#pragma unroll
    for (int mt = 0; mt < 2; mt++) {
#pragma unroll
        for (int rh = 0; rh < 2; rh++) {
            int row = i0 + wm + mt * 16 + g + rh * 8;
#pragma unroll
            for (int nt = 0; nt < 4; nt++) {
                int col = wn + nt * 8 + tg * 2;
                float2 o2 = make_float2(acc[mt][nt][rh * 2 + 0], acc[mt][nt][rh * 2 + 1]);
                *(float2*)(av + (size_t)(b * NN + row) * HD + h * DHH + col) = o2;
            }
        }
    }
}

// ---------------- host orchestration ----------------
extern "C" void kernel_launch(void* const* d_in, const int* in_sizes, int n_in,
                              void* d_out, int out_size) {
    (void)in_sizes; (void)n_in; (void)out_size;
    const float* in_x   = (const float*)d_in[0];
    const float* r_t    = (const float*)d_in[1];
    const float* r_c    = (const float*)d_in[2];
    const float* r_p    = (const float*)d_in[3];
    const float* bias_pf= (const float*)d_in[4];
    const float* ln1_g  = (const float*)d_in[5];
    const float* ln1_b  = (const float*)d_in[6];
    const float* w_qkv  = (const float*)d_in[7];
    const float* w_out  = (const float*)d_in[8];
    const float* b_out  = (const float*)d_in[9];
    const float* w_kt   = (const float*)d_in[10];
    const float* w_kc   = (const float*)d_in[11];
    const float* w_kp   = (const float*)d_in[12];
    const float* ln2_g  = (const float*)d_in[13];
    const float* ln2_b  = (const float*)d_in[14];
    const float* w_ff1  = (const float*)d_in[15];
    const float* b_ff1  = (const float*)d_in[16];
    const float* w_ff2  = (const float*)d_in[17];
    const float* b_ff2  = (const float*)d_in[18];

    float* out_x    = (float*)d_out;
    float* out_attn = out_x + (size_t)BB * NN * DD;

    float *p_x, *p_xn, *p_qkv, *p_ws, *p_AC, *p_BD, *p_attn, *p_av, *p_h1, *p_rcat;
    float *p_wqkvT, *p_wcatT, *p_woutT, *p_wff1T, *p_wff2T;
    cudaGetSymbolAddress((void**)&p_x,   g_x);
    cudaGetSymbolAddress((void**)&p_xn,  g_xn);
    cudaGetSymbolAddress((void**)&p_qkv, g_qkv);
    cudaGetSymbolAddress((void**)&p_ws,  g_ws);
    cudaGetSymbolAddress((void**)&p_AC,  g_AC);
    cudaGetSymbolAddress((void**)&p_BD,  g_BD);
    cudaGetSymbolAddress((void**)&p_attn,g_attn);
    cudaGetSymbolAddress((void**)&p_av,  g_av);
    cudaGetSymbolAddress((void**)&p_h1,  g_h1);
    cudaGetSymbolAddress((void**)&p_rcat, g_rcat);
    cudaGetSymbolAddress((void**)&p_wqkvT, g_wqkvT);
    cudaGetSymbolAddress((void**)&p_wcatT, g_wcatT);
    cudaGetSymbolAddress((void**)&p_woutT, g_woutT);
    cudaGetSymbolAddress((void**)&p_wff1T, g_wff1T);
    cudaGetSymbolAddress((void**)&p_wff2T, g_wff2T);

    cudaFuncSetAttribute(mgemm64<false,false,false,false>, cudaFuncAttributeMaxDynamicSharedMemorySize, MG64_SMEM);
    cudaFuncSetAttribute(mgemm64<false,true,true,false>,   cudaFuncAttributeMaxDynamicSharedMemorySize, MG64_SMEM);
    cudaFuncSetAttribute(mgemm64<false,true,false,true>,   cudaFuncAttributeMaxDynamicSharedMemorySize, MG64_SMEM);
    cudaFuncSetAttribute(scores_mma, cudaFuncAttributeMaxDynamicSharedMemorySize, SC_SMEM);
    cudaFuncSetAttribute(attnv64,    cudaFuncAttributeMaxDynamicSharedMemorySize, MG64_SMEM);

    const int M = BB * NN;   // 2048
    dim3 t32(32, 8);

    // one-time packing / transposes
    pack_r_kernel<<<(BB * NN * 3 * DD) / 256, 256>>>(r_t, r_c, r_p);
    transpose_batch<<<dim3(48, 16, DEPTH), t32>>>(w_qkv, p_wqkvT, DD, 3*HD, DD, 0, (size_t)3*HD*DD);
    transpose_batch<<<dim3(16, 16, DEPTH), t32>>>(w_kt, p_wcatT, DD, HD, 3*DD, 0,      (size_t)HD*3*DD);
    transpose_batch<<<dim3(16, 16, DEPTH), t32>>>(w_kc, p_wcatT, DD, HD, 3*DD, DD,     (size_t)HD*3*DD);
    transpose_batch<<<dim3(16, 16, DEPTH), t32>>>(w_kp, p_wcatT, DD, HD, 3*DD, 2*DD,   (size_t)HD*3*DD);
    transpose_batch<<<dim3(16, 16, DEPTH), t32>>>(w_out, p_woutT, HD, DD, HD, 0,       (size_t)DD*HD);
    transpose_batch<<<dim3(64, 16, DEPTH), t32>>>(w_ff1, p_wff1T, DD, FFD, DD, 0,      (size_t)FFD*DD);
    transpose_batch<<<dim3(16, 64, DEPTH), t32>>>(w_ff2, p_wff2T, FFD, DD, FFD, 0,     (size_t)DD*FFD);

    copy_in_kernel<<<(BB * NN * DD) / 256, 256>>>(in_x);

    for (int l = 0; l < DEPTH; l++) {
        ln_kernel<<<M, 128>>>(p_x, ln1_g + l * DD, ln1_b + l * DD, p_xn);
        // qkv = xn @ w_qkv[l]
        mgemm64<false,false,false,false><<<dim3(24, 32), 128, MG64_SMEM>>>(
            p_xn, p_wqkvT + (size_t)l * 3*HD * DD, p_qkv, 3 * HD, DD, nullptr, nullptr);
        // ws = [r_t|r_c|r_p] @ [w_kt; w_kc; w_kp]  (single K=1536 GEMM)
        mgemm64<false,false,false,false><<<dim3(8, 32), 128, MG64_SMEM>>>(
            p_rcat, p_wcatT + (size_t)l * HD * 3*DD, p_ws, HD, 3 * DD, nullptr, nullptr);
        // AC / BD batched scores
        scores_mma<<<dim3(16, 16, BB * HH), 256, SC_SMEM>>>(p_qkv, p_ws, bias_pf, p_AC, p_BD);
        // dots + rel_shift gather + softmax over heads
        float* attn_dst = (l == DEPTH - 1) ? out_attn : p_attn;
        softmax_kernel<<<(BB * NN * NN) / 256, 256>>>(p_AC, p_BD, attn_dst);
        // attn @ v
        attnv64<<<dim3(16, BB * HH), 128, MG64_SMEM>>>(attn_dst, p_qkv, p_av);
        // out projection + bias + residual
        mgemm64<false,true,true,false><<<dim3(8, 32), 128, MG64_SMEM>>>(
            p_av, p_woutT + (size_t)l * DD * HD, p_x, DD, HD, b_out + l * DD, p_x);
        ln_kernel<<<M, 128>>>(p_x, ln2_g + l * DD, ln2_b + l * DD, p_xn);
        // FF1 + bias + exact GELU
        mgemm64<false,true,false,true><<<dim3(32, 32), 128, MG64_SMEM>>>(
            p_xn, p_wff1T + (size_t)l * FFD * DD, p_h1, FFD, DD, b_ff1 + l * FFD, nullptr);
        // FF2 + bias + residual
        mgemm64<false,true,true,false><<<dim3(8, 32), 128, MG64_SMEM>>>(
            p_h1, p_wff2T + (size_t)l * DD * FFD, p_x, DD, FFD, b_ff2 + l * DD, p_x);
    }

    copy_out_kernel<<<(BB * NN * DD) / 256, 256>>>(out_x);
}

// round 7
// speedup vs baseline: 1.2508x; 1.2508x over previous
#include <cuda_runtime.h>
#include <math.h>
#include <stdint.h>

#define BB 2
#define NN 1024
#define DD 512
#define HH 8
#define DHH 64
#define HD 512
#define FFD 2048
#define DEPTH 4

// ---------------- device scratch ----------------
__device__ float g_x  [BB*NN*DD];
__device__ float g_xn [BB*NN*DD];
__device__ float g_qkv[BB*NN*3*HD];
__device__ float g_ws [BB*NN*HD];
__device__ float g_AC [(size_t)BB*HH*NN*NN];
__device__ float g_BD [(size_t)BB*HH*NN*NN];
__device__ float g_attn[(size_t)BB*HH*NN*NN];
__device__ float g_av [BB*NN*HD];
__device__ float g_h1 [BB*NN*FFD];
__device__ float g_rcat [BB*NN * 3*DD];            // [r_t | r_c | r_p] packed, K=1536
__device__ float g_wqkvT[DEPTH * 3*HD * DD];
__device__ float g_wcatT[DEPTH * HD * 3*DD];       // [w_kt; w_kc; w_kp] transposed+concat
__device__ float g_woutT[DEPTH * DD * HD];
__device__ float g_wff1T[DEPTH * FFD * DD];
__device__ float g_wff2T[DEPTH * DD * FFD];

__device__ __forceinline__ uint32_t tf32r(float x) {
    uint32_t y; asm("cvt.rna.tf32.f32 %0, %1;" : "=r"(y) : "f"(x)); return y;
}
__device__ __forceinline__ float tf32f(float x) {
    return __uint_as_float(tf32r(x));
}
__device__ __forceinline__ void mma8(float* d, const uint32_t* a, const uint32_t* b) {
    asm volatile("mma.sync.aligned.m16n8k8.row.col.f32.tf32.tf32.f32 "
        "{%0,%1,%2,%3}, {%4,%5,%6,%7}, {%8,%9}, {%0,%1,%2,%3};"
        : "+f"(d[0]), "+f"(d[1]), "+f"(d[2]), "+f"(d[3])
        : "r"(a[0]), "r"(a[1]), "r"(a[2]), "r"(a[3]), "r"(b[0]), "r"(b[1]));
}

// ---------------- simple copies / packing ----------------
__global__ void copy_in_kernel(const float* __restrict__ src) {
    int i = blockIdx.x * 256 + threadIdx.x;
    g_x[i] = src[i];
}
__global__ void copy_out_kernel(float* __restrict__ dst) {
    int i = blockIdx.x * 256 + threadIdx.x;
    dst[i] = g_x[i];
}
__global__ void pack_r_kernel(const float* __restrict__ rt, const float* __restrict__ rc,
                              const float* __restrict__ rp) {
    int idx = blockIdx.x * 256 + threadIdx.x;      // over BB*NN*1536
    int m = idx / (3 * DD), k = idx % (3 * DD);
    float v;
    if (k < DD)            v = rt[m * DD + k];
    else if (k < 2 * DD)   v = rc[m * DD + k - DD];
    else                   v = rp[m * DD + k - 2 * DD];
    g_rcat[idx] = v;
}

// ---------------- weight transpose: src [R,C] (per layer) -> dst [C, dstStride] at colBase ----------------
__global__ void transpose_batch(const float* __restrict__ src, float* __restrict__ dst,
                                int R, int C, int dstStride, int colBase, size_t dstLayer) {
    __shared__ float t[32][33];
    size_t soff = (size_t)blockIdx.z * R * C;
    size_t doff = (size_t)blockIdx.z * dstLayer;
    int c0 = blockIdx.x * 32, r0 = blockIdx.y * 32;
    int x = threadIdx.x, y = threadIdx.y;
#pragma unroll
    for (int i = 0; i < 32; i += 8)
        t[y + i][x] = src[soff + (size_t)(r0 + y + i) * C + c0 + x];
    __syncthreads();
#pragma unroll
    for (int i = 0; i < 32; i += 8)
        dst[doff + (size_t)(c0 + y + i) * dstStride + colBase + r0 + x] = t[x][y + i];
}

// ---------------- layernorm ----------------
__global__ void ln_kernel(const float* __restrict__ x, const float* __restrict__ g,
                          const float* __restrict__ bta, float* __restrict__ y) {
    __shared__ float red[128];
    int row = blockIdx.x;
    int tid = threadIdx.x;
    const float4* xr = (const float4*)(x + (size_t)row * DD);
    float4 v = xr[tid];
    red[tid] = v.x + v.y + v.z + v.w;
    __syncthreads();
    for (int o = 64; o > 0; o >>= 1) { if (tid < o) red[tid] += red[tid + o]; __syncthreads(); }
    float mean = red[0] * (1.0f / DD);
    __syncthreads();
    float dx = v.x - mean, dy = v.y - mean, dz = v.z - mean, dw = v.w - mean;
    red[tid] = dx*dx + dy*dy + dz*dz + dw*dw;
    __syncthreads();
    for (int o = 64; o > 0; o >>= 1) { if (tid < o) red[tid] += red[tid + o]; __syncthreads(); }
    float rstd = rsqrtf(red[0] * (1.0f / DD) + 1e-5f);
    float4 gv = ((const float4*)g)[tid];
    float4 bv = ((const float4*)bta)[tid];
    float4 o4;
    o4.x = dx * rstd * gv.x + bv.x;
    o4.y = dy * rstd * gv.y + bv.y;
    o4.z = dz * rstd * gv.z + bv.z;
    o4.w = dw * rstd * gv.w + bv.w;
    ((float4*)(y + (size_t)row * DD))[tid] = o4;
}

__device__ __forceinline__ float gelu_exact(float v) {
    return 0.5f * v * (1.0f + erff(v * 0.70710678118654752f));
}

// ---------------- mma.sync tf32 GEMM: C[M,Nc] = A[M,K] @ Bt[Nc,K]^T ----------------
// 128x64 CTA tile, 256 threads, BK=32 (round-4 proven config)
#define AS_STRIDE 136
#define BS_STRIDE 72
#define A_BUF_W  (32 * AS_STRIDE)
#define B_BUF_W  (32 * BS_STRIDE)
#define MG_SMEM  ((2 * A_BUF_W + 2 * B_BUF_W) * 4)

template<bool BIAS, bool RES, bool GELU_>
__global__ void __launch_bounds__(256, 2)
mgemm(const float* __restrict__ A, const float* __restrict__ Bt, float* __restrict__ C,
      int Nc, int K, const float* __restrict__ bias, const float* __restrict__ res) {
    extern __shared__ float sm[];
    float* sA[2] = { sm, sm + A_BUF_W };
    float* sB[2] = { sm + 2 * A_BUF_W, sm + 2 * A_BUF_W + B_BUF_W };

    const int tid = threadIdx.x;
    const int wid = tid >> 5, lid = tid & 31;
    const int row0 = blockIdx.y * 128;
    const int col0 = blockIdx.x * 64;

    const int arow = tid >> 1;
    const int akb  = (tid & 1) * 16;
    const int brow = tid >> 2;
    const int bkb  = (tid & 3) * 8;
    const float* gA = A  + (size_t)(row0 + arow) * K + akb;
    const float* gB = Bt + (size_t)(col0 + brow) * K + bkb;

    float acc[2][4][4];
#pragma unroll
    for (int mt = 0; mt < 2; mt++)
#pragma unroll
        for (int nt = 0; nt < 4; nt++)
#pragma unroll
            for (int r = 0; r < 4; r++) acc[mt][nt][r] = 0.f;

    float ar[16], br[8];
    const int nch = K >> 5;

#pragma unroll
    for (int i = 0; i < 4; i++) {
        float4 v = *(const float4*)(gA + i * 4);
        ar[4*i] = v.x; ar[4*i+1] = v.y; ar[4*i+2] = v.z; ar[4*i+3] = v.w;
    }
#pragma unroll
    for (int i = 0; i < 2; i++) {
        float4 v = *(const float4*)(gB + i * 4);
        br[4*i] = v.x; br[4*i+1] = v.y; br[4*i+2] = v.z; br[4*i+3] = v.w;
    }
#pragma unroll
    for (int i = 0; i < 16; i++)
        sA[0][(akb + i) * AS_STRIDE + arow] = tf32f(ar[i]);
#pragma unroll
    for (int i = 0; i < 8; i++)
        sB[0][(bkb + i) * BS_STRIDE + brow] = tf32f(br[i]);
    __syncthreads();

    const int wm = (wid & 3) * 32;
    const int wn = (wid >> 2) * 32;
    const int g  = lid >> 2;
    const int tg = lid & 3;

    int p = 0;
    for (int c = 0; c < nch; c++) {
        if (c + 1 < nch) {
            const float* pa = gA + (size_t)(c + 1) * 32;
            const float* pb = gB + (size_t)(c + 1) * 32;
#pragma unroll
            for (int i = 0; i < 4; i++) {
                float4 v = *(const float4*)(pa + i * 4);
                ar[4*i] = v.x; ar[4*i+1] = v.y; ar[4*i+2] = v.z; ar[4*i+3] = v.w;
            }
#pragma unroll
            for (int i = 0; i < 2; i++) {
                float4 v = *(const float4*)(pb + i * 4);
                br[4*i] = v.x; br[4*i+1] = v.y; br[4*i+2] = v.z; br[4*i+3] = v.w;
            }
        }
        const float* cA = sA[p];
        const float* cB = sB[p];
#pragma unroll
        for (int s = 0; s < 4; s++) {
            const int k0 = s * 8;
            uint32_t afr[2][4];
#pragma unroll
            for (int mt = 0; mt < 2; mt++) {
                int row = wm + mt * 16 + g;
                afr[mt][0] = __float_as_uint(cA[(k0 + tg)     * AS_STRIDE + row]);
                afr[mt][1] = __float_as_uint(cA[(k0 + tg)     * AS_STRIDE + row + 8]);
                afr[mt][2] = __float_as_uint(cA[(k0 + tg + 4) * AS_STRIDE + row]);
                afr[mt][3] = __float_as_uint(cA[(k0 + tg + 4) * AS_STRIDE + row + 8]);
            }
            uint32_t bfr[4][2];
#pragma unroll
            for (int nt = 0; nt < 4; nt++) {
                int cn = wn + nt * 8 + g;
                bfr[nt][0] = __float_as_uint(cB[(k0 + tg)     * BS_STRIDE + cn]);
                bfr[nt][1] = __float_as_uint(cB[(k0 + tg + 4) * BS_STRIDE + cn]);
            }
#pragma unroll
            for (int mt = 0; mt < 2; mt++)
#pragma unroll
                for (int nt = 0; nt < 4; nt++)
                    mma8(acc[mt][nt], afr[mt], bfr[nt]);
        }
        if (c + 1 < nch) {
            float* dA = sA[1 - p];
            float* dB = sB[1 - p];
#pragma unroll
            for (int i = 0; i < 16; i++)
                dA[(akb + i) * AS_STRIDE + arow] = tf32f(ar[i]);
#pragma unroll
            for (int i = 0; i < 8; i++)
                dB[(bkb + i) * BS_STRIDE + brow] = tf32f(br[i]);
        }
        __syncthreads();
        p ^= 1;
    }

#pragma unroll
    for (int mt = 0; mt < 2; mt++) {
#pragma unroll
        for (int rh = 0; rh < 2; rh++) {
            int row = row0 + wm + mt * 16 + g + rh * 8;
#pragma unroll
            for (int nt = 0; nt < 4; nt++) {
                int col = col0 + wn + nt * 8 + tg * 2;
                size_t idx = (size_t)row * Nc + col;
                float v0 = acc[mt][nt][rh * 2 + 0];
                float v1 = acc[mt][nt][rh * 2 + 1];
                if (BIAS)  { float2 bv = *(const float2*)(bias + col); v0 += bv.x; v1 += bv.y; }
                if (RES)   { float2 rv = *(const float2*)(res + idx); v0 += rv.x; v1 += rv.y; }
                if (GELU_) { v0 = gelu_exact(v0); v1 = gelu_exact(v1); }
                float2 o2 = make_float2(v0, v1);
                *(float2*)(C + idx) = o2;
            }
        }
    }
}

// ---------------- scores via mma: AC = Q.K^T, BD = Q.Ws^T (per b,h; K=64) ----------------
#define SC_STRIDE 72
#define SC_SMEM (3 * 64 * SC_STRIDE * 4)
__global__ void __launch_bounds__(256, 4)
scores_mma(const float* __restrict__ qkv, const float* __restrict__ ws,
           const float* __restrict__ bias_pf,
           float* __restrict__ AC, float* __restrict__ BD) {
    extern __shared__ float sm[];
    float* Qs = sm;
    float* Ks = sm + 64 * SC_STRIDE;
    float* Ws = sm + 128 * SC_STRIDE;
    const int bh = blockIdx.z;
    const int b = bh >> 3, h = bh & 7;
    const int i0 = blockIdx.y << 6, j0 = blockIdx.x << 6;
    const int tid = threadIdx.x;

    const int r  = tid >> 2;
    const int d0 = (tid & 3) << 4;
    const float* qb = qkv + (size_t)(b * NN + i0 + r) * (3 * HD) + h * DHH + d0;
    const float* kb = qkv + (size_t)(b * NN + j0 + r) * (3 * HD) + HD + h * DHH + d0;
    const float* wb = ws  + (size_t)(b * NN + j0 + r) * HD + h * DHH + d0;
    const float* pf = bias_pf + h * DHH + d0;
#pragma unroll
    for (int t = 0; t < 4; t++) {
        float4 q4 = *(const float4*)(qb + t * 4);
        float4 p4 = *(const float4*)(pf + t * 4);
        int d = d0 + t * 4;
        Qs[(d + 0) * SC_STRIDE + r] = tf32f(q4.x + p4.x);
        Qs[(d + 1) * SC_STRIDE + r] = tf32f(q4.y + p4.y);
        Qs[(d + 2) * SC_STRIDE + r] = tf32f(q4.z + p4.z);
        Qs[(d + 3) * SC_STRIDE + r] = tf32f(q4.w + p4.w);
        float4 k4 = *(const float4*)(kb + t * 4);
        Ks[(d + 0) * SC_STRIDE + r] = tf32f(k4.x);
        Ks[(d + 1) * SC_STRIDE + r] = tf32f(k4.y);
        Ks[(d + 2) * SC_STRIDE + r] = tf32f(k4.z);
        Ks[(d + 3) * SC_STRIDE + r] = tf32f(k4.w);
        float4 w4 = *(const float4*)(wb + t * 4);
        Ws[(d + 0) * SC_STRIDE + r] = tf32f(w4.x);
        Ws[(d + 1) * SC_STRIDE + r] = tf32f(w4.y);
        Ws[(d + 2) * SC_STRIDE + r] = tf32f(w4.z);
        Ws[(d + 3) * SC_STRIDE + r] = tf32f(w4.w);
    }
    __syncthreads();

    const int wid = tid >> 5, lid = tid & 31;
    const int grp = wid >> 2;
    const int w2  = wid & 3;
    const int wm  = (w2 & 1) * 32;
    const int wn  = (w2 >> 1) * 32;
    const float* Bm = grp ? Ws : Ks;
    const int g = lid >> 2, tg = lid & 3;

    float acc[2][4][4];
#pragma unroll
    for (int mt = 0; mt < 2; mt++)
#pragma unroll
        for (int nt = 0; nt < 4; nt++)
#pragma unroll
            for (int q = 0; q < 4; q++) acc[mt][nt][q] = 0.f;

#pragma unroll
    for (int s = 0; s < 8; s++) {
        const int k0 = s * 8;
        uint32_t afr[2][4];
#pragma unroll
        for (int mt = 0; mt < 2; mt++) {
            int row = wm + mt * 16 + g;
            afr[mt][0] = __float_as_uint(Qs[(k0 + tg)     * SC_STRIDE + row]);
            afr[mt][1] = __float_as_uint(Qs[(k0 + tg)     * SC_STRIDE + row + 8]);
            afr[mt][2] = __float_as_uint(Qs[(k0 + tg + 4) * SC_STRIDE + row]);
            afr[mt][3] = __float_as_uint(Qs[(k0 + tg + 4) * SC_STRIDE + row + 8]);
        }
        uint32_t bfr[4][2];
#pragma unroll
        for (int nt = 0; nt < 4; nt++) {
            int cn = wn + nt * 8 + g;
            bfr[nt][0] = __float_as_uint(Bm[(k0 + tg)     * SC_STRIDE + cn]);
            bfr[nt][1] = __float_as_uint(Bm[(k0 + tg + 4) * SC_STRIDE + cn]);
        }
#pragma unroll
        for (int mt = 0; mt < 2; mt++)
#pragma unroll
            for (int nt = 0; nt < 4; nt++)
                mma8(acc[mt][nt], afr[mt], bfr[nt]);
    }

    float* Out = grp ? BD : AC;
    const size_t base = ((size_t)bh << 20);
#pragma unroll
    for (int mt = 0; mt < 2; mt++) {
#pragma unroll
        for (int rh = 0; rh < 2; rh++) {
            int i = i0 + wm + mt * 16 + g + rh * 8;
#pragma unroll
            for (int nt = 0; nt < 4; nt++) {
                int j = j0 + wn + nt * 8 + tg * 2;
                float2 o2 = make_float2(acc[mt][nt][rh * 2 + 0], acc[mt][nt][rh * 2 + 1]);
                *(float2*)(Out + base + ((size_t)i << 10) + j) = o2;
            }
        }
    }
}

// ---------------- dots + rel_shift + softmax over heads ----------------
__global__ void softmax_kernel(const float* __restrict__ AC, const float* __restrict__ BD,
                               float* __restrict__ attn) {
    int idx = blockIdx.x * 256 + threadIdx.x;
    int b = idx >> 20;
    int ij = idx & ((1 << 20) - 1);
    int i = ij >> 10, j = ij & 1023;
    int m  = (i + 1) * NN + j;
    int i2 = m / (NN + 1);
    int k  = m - i2 * (NN + 1);
    size_t pb = ((size_t)(b * HH)) << 20;
    size_t shifted = ((size_t)i2 << 10) + (k - 1);
    float vals[8];
#pragma unroll
    for (int h = 0; h < 8; h++) {
        float ac = AC[pb + ((size_t)h << 20) + ij];
        float bd = (k != 0) ? BD[pb + ((size_t)h << 20) + shifted] : 0.f;
        vals[h] = (ac + bd * (1.0f / 3.0f)) * 0.125f;
    }
    float mx = vals[0];
#pragma unroll
    for (int h = 1; h < 8; h++) mx = fmaxf(mx, vals[h]);
    float s = 0.f;
#pragma unroll
    for (int h = 0; h < 8; h++) { vals[h] = __expf(vals[h] - mx); s += vals[h]; }
    float inv = 1.0f / s;
#pragma unroll
    for (int h = 0; h < 8; h++) attn[pb + ((size_t)h << 20) + ij] = vals[h] * inv;
}

// ---------------- attn @ v via mma (per b,h; M=1024, N=64, K=1024) ----------------
__global__ void __launch_bounds__(256, 2)
attnv_mma(const float* __restrict__ attn, const float* __restrict__ qkv,
          float* __restrict__ av) {
    extern __shared__ float sm[];
    float* sA[2] = { sm, sm + A_BUF_W };
    float* sB[2] = { sm + 2 * A_BUF_W, sm + 2 * A_BUF_W + B_BUF_W };

    const int bh = blockIdx.y;
    const int b = bh >> 3, h = bh & 7;
    const int i0 = blockIdx.x << 7;
    const int tid = threadIdx.x;
    const int wid = tid >> 5, lid = tid & 31;

    const int arow = tid >> 1;
    const int akb  = (tid & 1) * 16;
    const int bj   = tid >> 3;
    const int bd0  = (tid & 7) * 8;
    const float* gA = attn + ((size_t)bh << 20) + ((size_t)(i0 + arow) << 10) + akb;
    const float* gBbase = qkv + 2 * HD + h * DHH + bd0;

    float acc[2][4][4];
#pragma unroll
    for (int mt = 0; mt < 2; mt++)
#pragma unroll
        for (int nt = 0; nt < 4; nt++)
#pragma unroll
            for (int q = 0; q < 4; q++) acc[mt][nt][q] = 0.f;

    float ar[16], br[8];
    const int nch = NN >> 5;

    {
        const float* gB = gBbase + (size_t)(b * NN + bj) * (3 * HD);
#pragma unroll
        for (int i = 0; i < 4; i++) {
            float4 v = *(const float4*)(gA + i * 4);
            ar[4*i] = v.x; ar[4*i+1] = v.y; ar[4*i+2] = v.z; ar[4*i+3] = v.w;
        }
#pragma unroll
        for (int i = 0; i < 2; i++) {
            float4 v = *(const float4*)(gB + i * 4);
            br[4*i] = v.x; br[4*i+1] = v.y; br[4*i+2] = v.z; br[4*i+3] = v.w;
        }
#pragma unroll
        for (int i = 0; i < 16; i++)
            sA[0][(akb + i) * AS_STRIDE + arow] = tf32f(ar[i]);
#pragma unroll
        for (int i = 0; i < 8; i++)
            sB[0][bj * BS_STRIDE + bd0 + i] = tf32f(br[i]);
    }
    __syncthreads();

    const int wm = (wid & 3) * 32;
    const int wn = (wid >> 2) * 32;
    const int g  = lid >> 2;
    const int tg = lid & 3;

    int p = 0;
    for (int c = 0; c < nch; c++) {
        if (c + 1 < nch) {
            const float* pa = gA + (size_t)(c + 1) * 32;
            const float* pb = gBbase + (size_t)(b * NN + (c + 1) * 32 + bj) * (3 * HD);
#pragma unroll
            for (int i = 0; i < 4; i++) {
                float4 v = *(const float4*)(pa + i * 4);
                ar[4*i] = v.x; ar[4*i+1] = v.y; ar[4*i+2] = v.z; ar[4*i+3] = v.w;
            }
#pragma unroll
            for (int i = 0; i < 2; i++) {
                float4 v = *(const float4*)(pb + i * 4);
                br[4*i] = v.x; br[4*i+1] = v.y; br[4*i+2] = v.z; br[4*i+3] = v.w;
            }
        }
        const float* cA = sA[p];
        const float* cB = sB[p];
#pragma unroll
        for (int s = 0; s < 4; s++) {
            const int k0 = s * 8;
            uint32_t afr[2][4];
#pragma unroll
            for (int mt = 0; mt < 2; mt++) {
                int row = wm + mt * 16 + g;
                afr[mt][0] = __float_as_uint(cA[(k0 + tg)     * AS_STRIDE + row]);
                afr[mt][1] = __float_as_uint(cA[(k0 + tg)     * AS_STRIDE + row + 8]);
                afr[mt][2] = __float_as_uint(cA[(k0 + tg + 4) * AS_STRIDE + row]);
                afr[mt][3] = __float_as_uint(cA[(k0 + tg + 4) * AS_STRIDE + row + 8]);
            }
            uint32_t bfr[4][2];
#pragma unroll
            for (int nt = 0; nt < 4; nt++) {
                int cn = wn + nt * 8 + g;
                bfr[nt][0] = __float_as_uint(cB[(k0 + tg)     * BS_STRIDE + cn]);
                bfr[nt][1] = __float_as_uint(cB[(k0 + tg + 4) * BS_STRIDE + cn]);
            }
#pragma unroll
            for (int mt = 0; mt < 2; mt++)
#pragma unroll
                for (int nt = 0; nt < 4; nt++)
                    mma8(acc[mt][nt], afr[mt], bfr[nt]);
        }
        if (c + 1 < nch) {
            float* dA = sA[1 - p];
            float* dB = sB[1 - p];
#pragma unroll
            for (int i = 0; i < 16; i++)
                dA[(akb + i) * AS_STRIDE + arow] = tf32f(ar[i]);
#pragma unroll
            for (int i = 0; i < 8; i++)
                dB[bj * BS_STRIDE + bd0 + i] = tf32f(br[i]);
        }
        __syncthreads();
        p ^= 1;
    }

#pragma unroll
    for (int mt = 0; mt < 2; mt++) {
#pragma unroll
        for (int rh = 0; rh < 2; rh++) {
            int row = i0 + wm + mt * 16 + g + rh * 8;
#pragma unroll
            for (int nt = 0; nt < 4; nt++) {
                int col = wn + nt * 8 + tg * 2;
                float2 o2 = make_float2(acc[mt][nt][rh * 2 + 0], acc[mt][nt][rh * 2 + 1]);
                *(float2*)(av + (size_t)(b * NN + row) * HD + h * DHH + col) = o2;
            }
        }
    }
}

// ---------------- host orchestration ----------------
extern "C" void kernel_launch(void* const* d_in, const int* in_sizes, int n_in,
                              void* d_out, int out_size) {
    (void)in_sizes; (void)n_in; (void)out_size;
    const float* in_x   = (const float*)d_in[0];
    const float* r_t    = (const float*)d_in[1];
    const float* r_c    = (const float*)d_in[2];
    const float* r_p    = (const float*)d_in[3];
    const float* bias_pf= (const float*)d_in[4];
    const float* ln1_g  = (const float*)d_in[5];
    const float* ln1_b  = (const float*)d_in[6];
    const float* w_qkv  = (const float*)d_in[7];
    const float* w_out  = (const float*)d_in[8];
    const float* b_out  = (const float*)d_in[9];
    const float* w_kt   = (const float*)d_in[10];
    const float* w_kc   = (const float*)d_in[11];
    const float* w_kp   = (const float*)d_in[12];
    const float* ln2_g  = (const float*)d_in[13];
    const float* ln2_b  = (const float*)d_in[14];
    const float* w_ff1  = (const float*)d_in[15];
    const float* b_ff1  = (const float*)d_in[16];
    const float* w_ff2  = (const float*)d_in[17];
    const float* b_ff2  = (const float*)d_in[18];

    float* out_x    = (float*)d_out;
    float* out_attn = out_x + (size_t)BB * NN * DD;

    float *p_x, *p_xn, *p_qkv, *p_ws, *p_AC, *p_BD, *p_attn, *p_av, *p_h1, *p_rcat;
    float *p_wqkvT, *p_wcatT, *p_woutT, *p_wff1T, *p_wff2T;
    cudaGetSymbolAddress((void**)&p_x,   g_x);
    cudaGetSymbolAddress((void**)&p_xn,  g_xn);
    cudaGetSymbolAddress((void**)&p_qkv, g_qkv);
    cudaGetSymbolAddress((void**)&p_ws,  g_ws);
    cudaGetSymbolAddress((void**)&p_AC,  g_AC);
    cudaGetSymbolAddress((void**)&p_BD,  g_BD);
    cudaGetSymbolAddress((void**)&p_attn,g_attn);
    cudaGetSymbolAddress((void**)&p_av,  g_av);
    cudaGetSymbolAddress((void**)&p_h1,  g_h1);
    cudaGetSymbolAddress((void**)&p_rcat, g_rcat);
    cudaGetSymbolAddress((void**)&p_wqkvT, g_wqkvT);
    cudaGetSymbolAddress((void**)&p_wcatT, g_wcatT);
    cudaGetSymbolAddress((void**)&p_woutT, g_woutT);
    cudaGetSymbolAddress((void**)&p_wff1T, g_wff1T);
    cudaGetSymbolAddress((void**)&p_wff2T, g_wff2T);

    cudaFuncSetAttribute(mgemm<false,false,false>, cudaFuncAttributeMaxDynamicSharedMemorySize, MG_SMEM);
    cudaFuncSetAttribute(mgemm<true,true,false>,   cudaFuncAttributeMaxDynamicSharedMemorySize, MG_SMEM);
    cudaFuncSetAttribute(mgemm<true,false,true>,   cudaFuncAttributeMaxDynamicSharedMemorySize, MG_SMEM);
    cudaFuncSetAttribute(scores_mma, cudaFuncAttributeMaxDynamicSharedMemorySize, SC_SMEM);
    cudaFuncSetAttribute(attnv_mma,  cudaFuncAttributeMaxDynamicSharedMemorySize, MG_SMEM);

    const int M = BB * NN;   // 2048
    dim3 t32(32, 8);

    // one-time packing / transposes
    pack_r_kernel<<<(BB * NN * 3 * DD) / 256, 256>>>(r_t, r_c, r_p);
    transpose_batch<<<dim3(48, 16, DEPTH), t32>>>(w_qkv, p_wqkvT, DD, 3*HD, DD, 0, (size_t)3*HD*DD);
    transpose_batch<<<dim3(16, 16, DEPTH), t32>>>(w_kt, p_wcatT, DD, HD, 3*DD, 0,      (size_t)HD*3*DD);
    transpose_batch<<<dim3(16, 16, DEPTH), t32>>>(w_kc, p_wcatT, DD, HD, 3*DD, DD,     (size_t)HD*3*DD);
    transpose_batch<<<dim3(16, 16, DEPTH), t32>>>(w_kp, p_wcatT, DD, HD, 3*DD, 2*DD,   (size_t)HD*3*DD);
    transpose_batch<<<dim3(16, 16, DEPTH), t32>>>(w_out, p_woutT, HD, DD, HD, 0,       (size_t)DD*HD);
    transpose_batch<<<dim3(64, 16, DEPTH), t32>>>(w_ff1, p_wff1T, DD, FFD, DD, 0,      (size_t)FFD*DD);
    transpose_batch<<<dim3(16, 64, DEPTH), t32>>>(w_ff2, p_wff2T, FFD, DD, FFD, 0,     (size_t)DD*FFD);

    copy_in_kernel<<<(BB * NN * DD) / 256, 256>>>(in_x);

    for (int l = 0; l < DEPTH; l++) {
        ln_kernel<<<M, 128>>>(p_x, ln1_g + l * DD, ln1_b + l * DD, p_xn);
        // qkv = xn @ w_qkv[l]
        mgemm<false,false,false><<<dim3(24, 16), 256, MG_SMEM>>>(
            p_xn, p_wqkvT + (size_t)l * 3*HD * DD, p_qkv, 3 * HD, DD, nullptr, nullptr);
        // ws = [r_t|r_c|r_p] @ [w_kt; w_kc; w_kp]  (single K=1536 GEMM)
        mgemm<false,false,false><<<dim3(8, 16), 256, MG_SMEM>>>(
            p_rcat, p_wcatT + (size_t)l * HD * 3*DD, p_ws, HD, 3 * DD, nullptr, nullptr);
        // AC / BD batched scores
        scores_mma<<<dim3(16, 16, BB * HH), 256, SC_SMEM>>>(p_qkv, p_ws, bias_pf, p_AC, p_BD);
        // dots + rel_shift gather + softmax over heads
        float* attn_dst = (l == DEPTH - 1) ? out_attn : p_attn;
        softmax_kernel<<<(BB * NN * NN) / 256, 256>>>(p_AC, p_BD, attn_dst);
        // attn @ v
        attnv_mma<<<dim3(8, BB * HH), 256, MG_SMEM>>>(attn_dst, p_qkv, p_av);
        // out projection + bias + residual
        mgemm<true,true,false><<<dim3(8, 16), 256, MG_SMEM>>>(
            p_av, p_woutT + (size_t)l * DD * HD, p_x, DD, HD, b_out + l * DD, p_x);
        ln_kernel<<<M, 128>>>(p_x, ln2_g + l * DD, ln2_b + l * DD, p_xn);
        // FF1 + bias + exact GELU
        mgemm<true,false,true><<<dim3(32, 16), 256, MG_SMEM>>>(
            p_xn, p_wff1T + (size_t)l * FFD * DD, p_h1, FFD, DD, b_ff1 + l * FFD, nullptr);
        // FF2 + bias + residual
        mgemm<true,true,false><<<dim3(8, 16), 256, MG_SMEM>>>(
            p_h1, p_wff2T + (size_t)l * DD * FFD, p_x, DD, FFD, b_ff2 + l * DD, p_x);
    }

    copy_out_kernel<<<(BB * NN * DD) / 256, 256>>>(out_x);
}

// round 8
// speedup vs baseline: 1.3000x; 1.0393x over previous
#include <cuda_runtime.h>
#include <cuda_fp16.h>
#include <math.h>
#include <stdint.h>

#define BB 2
#define NN 1024
#define DD 512
#define HH 8
#define DHH 64
#define HD 512
#define FFD 2048
#define DEPTH 4

// ---------------- device scratch ----------------
__device__ float g_x  [BB*NN*DD];
__device__ float g_xn [BB*NN*DD];
__device__ float g_qkv[BB*NN*3*HD];
__device__ float g_ws [BB*NN*HD];
__device__ __half g_AC16 [(size_t)BB*HH*NN*NN];
__device__ __half g_BD16 [(size_t)BB*HH*NN*NN];
__device__ __half g_attn16[(size_t)BB*HH*NN*NN];
__device__ float g_av [BB*NN*HD];
__device__ float g_h1 [BB*NN*FFD];
__device__ float g_rcat [BB*NN * 3*DD];            // [r_t | r_c | r_p] packed, K=1536
__device__ float g_wqkvT[DEPTH * 3*HD * DD];
__device__ float g_wcatT[DEPTH * HD * 3*DD];       // [w_kt; w_kc; w_kp] transposed+concat
__device__ float g_woutT[DEPTH * DD * HD];
__device__ float g_wff1T[DEPTH * FFD * DD];
__device__ float g_wff2T[DEPTH * DD * FFD];

__device__ __forceinline__ uint32_t tf32r(float x) {
    uint32_t y; asm("cvt.rna.tf32.f32 %0, %1;" : "=r"(y) : "f"(x)); return y;
}
__device__ __forceinline__ float tf32f(float x) {
    return __uint_as_float(tf32r(x));
}
__device__ __forceinline__ void mma8(float* d, const uint32_t* a, const uint32_t* b) {
    asm volatile("mma.sync.aligned.m16n8k8.row.col.f32.tf32.tf32.f32 "
        "{%0,%1,%2,%3}, {%4,%5,%6,%7}, {%8,%9}, {%0,%1,%2,%3};"
        : "+f"(d[0]), "+f"(d[1]), "+f"(d[2]), "+f"(d[3])
        : "r"(a[0]), "r"(a[1]), "r"(a[2]), "r"(a[3]), "r"(b[0]), "r"(b[1]));
}

// ---------------- simple copies / packing ----------------
__global__ void copy_in_kernel(const float* __restrict__ src) {
    int i = blockIdx.x * 256 + threadIdx.x;
    g_x[i] = src[i];
}
__global__ void copy_out_kernel(float* __restrict__ dst) {
    int i = blockIdx.x * 256 + threadIdx.x;
    dst[i] = g_x[i];
}
__global__ void pack_r_kernel(const float* __restrict__ rt, const float* __restrict__ rc,
                              const float* __restrict__ rp) {
    int idx = blockIdx.x * 256 + threadIdx.x;      // over BB*NN*1536
    int m = idx / (3 * DD), k = idx % (3 * DD);
    float v;
    if (k < DD)            v = rt[m * DD + k];
    else if (k < 2 * DD)   v = rc[m * DD + k - DD];
    else                   v = rp[m * DD + k - 2 * DD];
    g_rcat[idx] = v;
}

// ---------------- weight transpose: src [R,C] (per layer) -> dst [C, dstStride] at colBase ----------------
__global__ void transpose_batch(const float* __restrict__ src, float* __restrict__ dst,
                                int R, int C, int dstStride, int colBase, size_t dstLayer) {
    __shared__ float t[32][33];
    size_t soff = (size_t)blockIdx.z * R * C;
    size_t doff = (size_t)blockIdx.z * dstLayer;
    int c0 = blockIdx.x * 32, r0 = blockIdx.y * 32;
    int x = threadIdx.x, y = threadIdx.y;
#pragma unroll
    for (int i = 0; i < 32; i += 8)
        t[y + i][x] = src[soff + (size_t)(r0 + y + i) * C + c0 + x];
    __syncthreads();
#pragma unroll
    for (int i = 0; i < 32; i += 8)
        dst[doff + (size_t)(c0 + y + i) * dstStride + colBase + r0 + x] = t[x][y + i];
}

// ---------------- layernorm ----------------
__global__ void ln_kernel(const float* __restrict__ x, const float* __restrict__ g,
                          const float* __restrict__ bta, float* __restrict__ y) {
    __shared__ float red[128];
    int row = blockIdx.x;
    int tid = threadIdx.x;
    const float4* xr = (const float4*)(x + (size_t)row * DD);
    float4 v = xr[tid];
    red[tid] = v.x + v.y + v.z + v.w;
    __syncthreads();
    for (int o = 64; o > 0; o >>= 1) { if (tid < o) red[tid] += red[tid + o]; __syncthreads(); }
    float mean = red[0] * (1.0f / DD);
    __syncthreads();
    float dx = v.x - mean, dy = v.y - mean, dz = v.z - mean, dw = v.w - mean;
    red[tid] = dx*dx + dy*dy + dz*dz + dw*dw;
    __syncthreads();
    for (int o = 64; o > 0; o >>= 1) { if (tid < o) red[tid] += red[tid + o]; __syncthreads(); }
    float rstd = rsqrtf(red[0] * (1.0f / DD) + 1e-5f);
    float4 gv = ((const float4*)g)[tid];
    float4 bv = ((const float4*)bta)[tid];
    float4 o4;
    o4.x = dx * rstd * gv.x + bv.x;
    o4.y = dy * rstd * gv.y + bv.y;
    o4.z = dz * rstd * gv.z + bv.z;
    o4.w = dw * rstd * gv.w + bv.w;
    ((float4*)(y + (size_t)row * DD))[tid] = o4;
}

__device__ __forceinline__ float gelu_exact(float v) {
    return 0.5f * v * (1.0f + erff(v * 0.70710678118654752f));
}

// ---------------- mma.sync tf32 GEMM: C[M,Nc] = A[M,K] @ Bt[Nc,K]^T ----------------
// 128x64 CTA tile, 256 threads, BK=32 (proven config)
#define AS_STRIDE 136
#define BS_STRIDE 72
#define A_BUF_W  (32 * AS_STRIDE)
#define B_BUF_W  (32 * BS_STRIDE)
#define MG_SMEM  ((2 * A_BUF_W + 2 * B_BUF_W) * 4)

template<bool BIAS, bool RES, bool GELU_>
__global__ void __launch_bounds__(256, 2)
mgemm(const float* __restrict__ A, const float* __restrict__ Bt, float* __restrict__ C,
      int Nc, int K, const float* __restrict__ bias, const float* __restrict__ res) {
    extern __shared__ float sm[];
    float* sA[2] = { sm, sm + A_BUF_W };
    float* sB[2] = { sm + 2 * A_BUF_W, sm + 2 * A_BUF_W + B_BUF_W };

    const int tid = threadIdx.x;
    const int wid = tid >> 5, lid = tid & 31;
    const int row0 = blockIdx.y * 128;
    const int col0 = blockIdx.x * 64;

    const int arow = tid >> 1;
    const int akb  = (tid & 1) * 16;
    const int brow = tid >> 2;
    const int bkb  = (tid & 3) * 8;
    const float* gA = A  + (size_t)(row0 + arow) * K + akb;
    const float* gB = Bt + (size_t)(col0 + brow) * K + bkb;

    float acc[2][4][4];
#pragma unroll
    for (int mt = 0; mt < 2; mt++)
#pragma unroll
        for (int nt = 0; nt < 4; nt++)
#pragma unroll
            for (int r = 0; r < 4; r++) acc[mt][nt][r] = 0.f;

    float ar[16], br[8];
    const int nch = K >> 5;

#pragma unroll
    for (int i = 0; i < 4; i++) {
        float4 v = *(const float4*)(gA + i * 4);
        ar[4*i] = v.x; ar[4*i+1] = v.y; ar[4*i+2] = v.z; ar[4*i+3] = v.w;
    }
#pragma unroll
    for (int i = 0; i < 2; i++) {
        float4 v = *(const float4*)(gB + i * 4);
        br[4*i] = v.x; br[4*i+1] = v.y; br[4*i+2] = v.z; br[4*i+3] = v.w;
    }
#pragma unroll
    for (int i = 0; i < 16; i++)
        sA[0][(akb + i) * AS_STRIDE + arow] = tf32f(ar[i]);
#pragma unroll
    for (int i = 0; i < 8; i++)
        sB[0][(bkb + i) * BS_STRIDE + brow] = tf32f(br[i]);
    __syncthreads();

    const int wm = (wid & 3) * 32;
    const int wn = (wid >> 2) * 32;
    const int g  = lid >> 2;
    const int tg = lid & 3;

    int p = 0;
    for (int c = 0; c < nch; c++) {
        if (c + 1 < nch) {
            const float* pa = gA + (size_t)(c + 1) * 32;
            const float* pb = gB + (size_t)(c + 1) * 32;
#pragma unroll
            for (int i = 0; i < 4; i++) {
                float4 v = *(const float4*)(pa + i * 4);
                ar[4*i] = v.x; ar[4*i+1] = v.y; ar[4*i+2] = v.z; ar[4*i+3] = v.w;
            }
#pragma unroll
            for (int i = 0; i < 2; i++) {
                float4 v = *(const float4*)(pb + i * 4);
                br[4*i] = v.x; br[4*i+1] = v.y; br[4*i+2] = v.z; br[4*i+3] = v.w;
            }
        }
        const float* cA = sA[p];
        const float* cB = sB[p];
#pragma unroll
        for (int s = 0; s < 4; s++) {
            const int k0 = s * 8;
            uint32_t afr[2][4];
#pragma unroll
            for (int mt = 0; mt < 2; mt++) {
                int row = wm + mt * 16 + g;
                afr[mt][0] = __float_as_uint(cA[(k0 + tg)     * AS_STRIDE + row]);
                afr[mt][1] = __float_as_uint(cA[(k0 + tg)     * AS_STRIDE + row + 8]);
                afr[mt][2] = __float_as_uint(cA[(k0 + tg + 4) * AS_STRIDE + row]);
                afr[mt][3] = __float_as_uint(cA[(k0 + tg + 4) * AS_STRIDE + row + 8]);
            }
            uint32_t bfr[4][2];
#pragma unroll
            for (int nt = 0; nt < 4; nt++) {
                int cn = wn + nt * 8 + g;
                bfr[nt][0] = __float_as_uint(cB[(k0 + tg)     * BS_STRIDE + cn]);
                bfr[nt][1] = __float_as_uint(cB[(k0 + tg + 4) * BS_STRIDE + cn]);
            }
#pragma unroll
            for (int mt = 0; mt < 2; mt++)
#pragma unroll
                for (int nt = 0; nt < 4; nt++)
                    mma8(acc[mt][nt], afr[mt], bfr[nt]);
        }
        if (c + 1 < nch) {
            float* dA = sA[1 - p];
            float* dB = sB[1 - p];
#pragma unroll
            for (int i = 0; i < 16; i++)
                dA[(akb + i) * AS_STRIDE + arow] = tf32f(ar[i]);
#pragma unroll
            for (int i = 0; i < 8; i++)
                dB[(bkb + i) * BS_STRIDE + brow] = tf32f(br[i]);
        }
        __syncthreads();
        p ^= 1;
    }

#pragma unroll
    for (int mt = 0; mt < 2; mt++) {
#pragma unroll
        for (int rh = 0; rh < 2; rh++) {
            int row = row0 + wm + mt * 16 + g + rh * 8;
#pragma unroll
            for (int nt = 0; nt < 4; nt++) {
                int col = col0 + wn + nt * 8 + tg * 2;
                size_t idx = (size_t)row * Nc + col;
                float v0 = acc[mt][nt][rh * 2 + 0];
                float v1 = acc[mt][nt][rh * 2 + 1];
                if (BIAS)  { float2 bv = *(const float2*)(bias + col); v0 += bv.x; v1 += bv.y; }
                if (RES)   { float2 rv = *(const float2*)(res + idx); v0 += rv.x; v1 += rv.y; }
                if (GELU_) { v0 = gelu_exact(v0); v1 = gelu_exact(v1); }
                float2 o2 = make_float2(v0, v1);
                *(float2*)(C + idx) = o2;
            }
        }
    }
}

// ---------------- scores via mma: AC = Q.K^T, BD = Q.Ws^T (per b,h; K=64), fp16 out ----------------
#define SC_STRIDE 72
#define SC_SMEM (3 * 64 * SC_STRIDE * 4)
__global__ void __launch_bounds__(256, 4)
scores_mma(const float* __restrict__ qkv, const float* __restrict__ ws,
           const float* __restrict__ bias_pf,
           __half* __restrict__ AC, __half* __restrict__ BD) {
    extern __shared__ float sm[];
    float* Qs = sm;
    float* Ks = sm + 64 * SC_STRIDE;
    float* Ws = sm + 128 * SC_STRIDE;
    const int bh = blockIdx.z;
    const int b = bh >> 3, h = bh & 7;
    const int i0 = blockIdx.y << 6, j0 = blockIdx.x << 6;
    const int tid = threadIdx.x;

    const int r  = tid >> 2;
    const int d0 = (tid & 3) << 4;
    const float* qb = qkv + (size_t)(b * NN + i0 + r) * (3 * HD) + h * DHH + d0;
    const float* kb = qkv + (size_t)(b * NN + j0 + r) * (3 * HD) + HD + h * DHH + d0;
    const float* wb = ws  + (size_t)(b * NN + j0 + r) * HD + h * DHH + d0;
    const float* pf = bias_pf + h * DHH + d0;
#pragma unroll
    for (int t = 0; t < 4; t++) {
        float4 q4 = *(const float4*)(qb + t * 4);
        float4 p4 = *(const float4*)(pf + t * 4);
        int d = d0 + t * 4;
        Qs[(d + 0) * SC_STRIDE + r] = tf32f(q4.x + p4.x);
        Qs[(d + 1) * SC_STRIDE + r] = tf32f(q4.y + p4.y);
        Qs[(d + 2) * SC_STRIDE + r] = tf32f(q4.z + p4.z);
        Qs[(d + 3) * SC_STRIDE + r] = tf32f(q4.w + p4.w);
        float4 k4 = *(const float4*)(kb + t * 4);
        Ks[(d + 0) * SC_STRIDE + r] = tf32f(k4.x);
        Ks[(d + 1) * SC_STRIDE + r] = tf32f(k4.y);
        Ks[(d + 2) * SC_STRIDE + r] = tf32f(k4.z);
        Ks[(d + 3) * SC_STRIDE + r] = tf32f(k4.w);
        float4 w4 = *(const float4*)(wb + t * 4);
        Ws[(d + 0) * SC_STRIDE + r] = tf32f(w4.x);
        Ws[(d + 1) * SC_STRIDE + r] = tf32f(w4.y);
        Ws[(d + 2) * SC_STRIDE + r] = tf32f(w4.z);
        Ws[(d + 3) * SC_STRIDE + r] = tf32f(w4.w);
    }
    __syncthreads();

    const int wid = tid >> 5, lid = tid & 31;
    const int grp = wid >> 2;
    const int w2  = wid & 3;
    const int wm  = (w2 & 1) * 32;
    const int wn  = (w2 >> 1) * 32;
    const float* Bm = grp ? Ws : Ks;
    const int g = lid >> 2, tg = lid & 3;

    float acc[2][4][4];
#pragma unroll
    for (int mt = 0; mt < 2; mt++)
#pragma unroll
        for (int nt = 0; nt < 4; nt++)
#pragma unroll
            for (int q = 0; q < 4; q++) acc[mt][nt][q] = 0.f;

#pragma unroll
    for (int s = 0; s < 8; s++) {
        const int k0 = s * 8;
        uint32_t afr[2][4];
#pragma unroll
        for (int mt = 0; mt < 2; mt++) {
            int row = wm + mt * 16 + g;
            afr[mt][0] = __float_as_uint(Qs[(k0 + tg)     * SC_STRIDE + row]);
            afr[mt][1] = __float_as_uint(Qs[(k0 + tg)     * SC_STRIDE + row + 8]);
            afr[mt][2] = __float_as_uint(Qs[(k0 + tg + 4) * SC_STRIDE + row]);
            afr[mt][3] = __float_as_uint(Qs[(k0 + tg + 4) * SC_STRIDE + row + 8]);
        }
        uint32_t bfr[4][2];
#pragma unroll
        for (int nt = 0; nt < 4; nt++) {
            int cn = wn + nt * 8 + g;
            bfr[nt][0] = __float_as_uint(Bm[(k0 + tg)     * SC_STRIDE + cn]);
            bfr[nt][1] = __float_as_uint(Bm[(k0 + tg + 4) * SC_STRIDE + cn]);
        }
#pragma unroll
        for (int mt = 0; mt < 2; mt++)
#pragma unroll
            for (int nt = 0; nt < 4; nt++)
                mma8(acc[mt][nt], afr[mt], bfr[nt]);
    }

    __half* Out = grp ? BD : AC;
    const size_t base = ((size_t)bh << 20);
#pragma unroll
    for (int mt = 0; mt < 2; mt++) {
#pragma unroll
        for (int rh = 0; rh < 2; rh++) {
            int i = i0 + wm + mt * 16 + g + rh * 8;
#pragma unroll
            for (int nt = 0; nt < 4; nt++) {
                int j = j0 + wn + nt * 8 + tg * 2;
                __half2 h2 = __floats2half2_rn(acc[mt][nt][rh * 2 + 0], acc[mt][nt][rh * 2 + 1]);
                *(__half2*)(Out + base + ((size_t)i << 10) + j) = h2;
            }
        }
    }
}

// ---------------- dots + rel_shift + softmax over heads (fp16 in/out, x2 vectorized) ----------------
template<bool LAST>
__global__ void softmax16(const __half* __restrict__ AC, const __half* __restrict__ BD,
                          __half* __restrict__ attn, float* __restrict__ out_attn) {
    int gid = blockIdx.x * 256 + threadIdx.x;      // pair index over BB*NN*NN/2
    int b = gid >> 19;
    int ijp = gid & ((1 << 19) - 1);
    int ij = ijp << 1;
    int i = ij >> 10, j = ij & 1023;

    int m0 = (i + 1) * NN + j;
    int i2a = m0 / (NN + 1);
    int ka  = m0 - i2a * (NN + 1);
    int i2b, kb;
    if (ka == NN) { i2b = i2a + 1; kb = 0; }
    else          { i2b = i2a;     kb = ka + 1; }

    size_t pb = ((size_t)(b * HH)) << 20;
    size_t sa = ((size_t)i2a << 10) + (ka - 1);
    size_t sb = ((size_t)i2b << 10) + (kb - 1);

    float va[8], vb[8];
#pragma unroll
    for (int h = 0; h < 8; h++) {
        size_t hp = pb + ((size_t)h << 20);
        __half2 ac2 = *(const __half2*)(AC + hp + ij);
        float bda = (ka != 0) ? __half2float(BD[hp + sa]) : 0.f;
        float bdb = (kb != 0) ? __half2float(BD[hp + sb]) : 0.f;
        va[h] = (__low2float(ac2)  + bda * (1.0f / 3.0f)) * 0.125f;
        vb[h] = (__high2float(ac2) + bdb * (1.0f / 3.0f)) * 0.125f;
    }
    float mxa = va[0], mxb = vb[0];
#pragma unroll
    for (int h = 1; h < 8; h++) { mxa = fmaxf(mxa, va[h]); mxb = fmaxf(mxb, vb[h]); }
    float sa_ = 0.f, sb_ = 0.f;
#pragma unroll
    for (int h = 0; h < 8; h++) {
        va[h] = __expf(va[h] - mxa); sa_ += va[h];
        vb[h] = __expf(vb[h] - mxb); sb_ += vb[h];
    }
    float ia = 1.0f / sa_, ib = 1.0f / sb_;
#pragma unroll
    for (int h = 0; h < 8; h++) {
        size_t hp = pb + ((size_t)h << 20);
        float oa = va[h] * ia, ob = vb[h] * ib;
        *(__half2*)(attn + hp + ij) = __floats2half2_rn(oa, ob);
        if (LAST) {
            float2 o2 = make_float2(oa, ob);
            *(float2*)(out_attn + hp + ij) = o2;
        }
    }
}

// ---------------- attn(fp16) @ v via mma (per b,h; M=1024, N=64, K=1024) ----------------
__global__ void __launch_bounds__(256, 2)
attnv_mma(const __half* __restrict__ attn, const float* __restrict__ qkv,
          float* __restrict__ av) {
    extern __shared__ float sm[];
    float* sA[2] = { sm, sm + A_BUF_W };
    float* sB[2] = { sm + 2 * A_BUF_W, sm + 2 * A_BUF_W + B_BUF_W };

    const int bh = blockIdx.y;
    const int b = bh >> 3, h = bh & 7;
    const int i0 = blockIdx.x << 7;
    const int tid = threadIdx.x;
    const int wid = tid >> 5, lid = tid & 31;

    const int arow = tid >> 1;
    const int akb  = (tid & 1) * 16;
    const int bj   = tid >> 3;
    const int bd0  = (tid & 7) * 8;
    const __half* gA = attn + ((size_t)bh << 20) + ((size_t)(i0 + arow) << 10) + akb;
    const float* gBbase = qkv + 2 * HD + h * DHH + bd0;

    float acc[2][4][4];
#pragma unroll
    for (int mt = 0; mt < 2; mt++)
#pragma unroll
        for (int nt = 0; nt < 4; nt++)
#pragma unroll
            for (int q = 0; q < 4; q++) acc[mt][nt][q] = 0.f;

    float ar[16], br[8];
    const int nch = NN >> 5;

    // half16 -> float16 loader (fp16 exactly representable in tf32: no rounding needed)
    auto loadA = [&](const __half* src) {
        uint4 r0 = *(const uint4*)(src);
        uint4 r1 = *(const uint4*)(src + 8);
        const __half2* h0 = (const __half2*)&r0;
        const __half2* h1 = (const __half2*)&r1;
#pragma unroll
        for (int t = 0; t < 4; t++) {
            float2 f0 = __half22float2(h0[t]);
            ar[2*t]     = f0.x; ar[2*t + 1] = f0.y;
            float2 f1 = __half22float2(h1[t]);
            ar[8 + 2*t] = f1.x; ar[8 + 2*t + 1] = f1.y;
        }
    };

    {
        const float* gB = gBbase + (size_t)(b * NN + bj) * (3 * HD);
        loadA(gA);
#pragma unroll
        for (int i = 0; i < 2; i++) {
            float4 v = *(const float4*)(gB + i * 4);
            br[4*i] = v.x; br[4*i+1] = v.y; br[4*i+2] = v.z; br[4*i+3] = v.w;
        }
#pragma unroll
        for (int i = 0; i < 16; i++)
            sA[0][(akb + i) * AS_STRIDE + arow] = ar[i];
#pragma unroll
        for (int i = 0; i < 8; i++)
            sB[0][bj * BS_STRIDE + bd0 + i] = tf32f(br[i]);
    }
    __syncthreads();

    const int wm = (wid & 3) * 32;
    const int wn = (wid >> 2) * 32;
    const int g  = lid >> 2;
    const int tg = lid & 3;

    int p = 0;
    for (int c = 0; c < nch; c++) {
        if (c + 1 < nch) {
            const float* pb = gBbase + (size_t)(b * NN + (c + 1) * 32 + bj) * (3 * HD);
            loadA(gA + (size_t)(c + 1) * 32);
#pragma unroll
            for (int i = 0; i < 2; i++) {
                float4 v = *(const float4*)(pb + i * 4);
                br[4*i] = v.x; br[4*i+1] = v.y; br[4*i+2] = v.z; br[4*i+3] = v.w;
            }
        }
        const float* cA = sA[p];
        const float* cB = sB[p];
#pragma unroll
        for (int s = 0; s < 4; s++) {
            const int k0 = s * 8;
            uint32_t afr[2][4];
#pragma unroll
            for (int mt = 0; mt < 2; mt++) {
                int row = wm + mt * 16 + g;
                afr[mt][0] = __float_as_uint(cA[(k0 + tg)     * AS_STRIDE + row]);
                afr[mt][1] = __float_as_uint(cA[(k0 + tg)     * AS_STRIDE + row + 8]);
                afr[mt][2] = __float_as_uint(cA[(k0 + tg + 4) * AS_STRIDE + row]);
                afr[mt][3] = __float_as_uint(cA[(k0 + tg + 4) * AS_STRIDE + row + 8]);
            }
            uint32_t bfr[4][2];
#pragma unroll
            for (int nt = 0; nt < 4; nt++) {
                int cn = wn + nt * 8 + g;
                bfr[nt][0] = __float_as_uint(cB[(k0 + tg)     * BS_STRIDE + cn]);
                bfr[nt][1] = __float_as_uint(cB[(k0 + tg + 4) * BS_STRIDE + cn]);
            }
#pragma unroll
            for (int mt = 0; mt < 2; mt++)
#pragma unroll
                for (int nt = 0; nt < 4; nt++)
                    mma8(acc[mt][nt], afr[mt], bfr[nt]);
        }
        if (c + 1 < nch) {
            float* dA = sA[1 - p];
            float* dB = sB[1 - p];
#pragma unroll
            for (int i = 0; i < 16; i++)
                dA[(akb + i) * AS_STRIDE + arow] = ar[i];
#pragma unroll
            for (int i = 0; i < 8; i++)
                dB[bj * BS_STRIDE + bd0 + i] = tf32f(br[i]);
        }
        __syncthreads();
        p ^= 1;
    }

#pragma unroll
    for (int mt = 0; mt < 2; mt++) {
#pragma unroll
        for (int rh = 0; rh < 2; rh++) {
            int row = i0 + wm + mt * 16 + g + rh * 8;
#pragma unroll
            for (int nt = 0; nt < 4; nt++) {
                int col = wn + nt * 8 + tg * 2;
                float2 o2 = make_float2(acc[mt][nt][rh * 2 + 0], acc[mt][nt][rh * 2 + 1]);
                *(float2*)(av + (size_t)(b * NN + row) * HD + h * DHH + col) = o2;
            }
        }
    }
}

// ---------------- host orchestration ----------------
extern "C" void kernel_launch(void* const* d_in, const int* in_sizes, int n_in,
                              void* d_out, int out_size) {
    (void)in_sizes; (void)n_in; (void)out_size;
    const float* in_x   = (const float*)d_in[0];
    const float* r_t    = (const float*)d_in[1];
    const float* r_c    = (const float*)d_in[2];
    const float* r_p    = (const float*)d_in[3];
    const float* bias_pf= (const float*)d_in[4];
    const float* ln1_g  = (const float*)d_in[5];
    const float* ln1_b  = (const float*)d_in[6];
    const float* w_qkv  = (const float*)d_in[7];
    const float* w_out  = (const float*)d_in[8];
    const float* b_out  = (const float*)d_in[9];
    const float* w_kt   = (const float*)d_in[10];
    const float* w_kc   = (const float*)d_in[11];
    const float* w_kp   = (const float*)d_in[12];
    const float* ln2_g  = (const float*)d_in[13];
    const float* ln2_b  = (const float*)d_in[14];
    const float* w_ff1  = (const float*)d_in[15];
    const float* b_ff1  = (const float*)d_in[16];
    const float* w_ff2  = (const float*)d_in[17];
    const float* b_ff2  = (const float*)d_in[18];

    float* out_x    = (float*)d_out;
    float* out_attn = out_x + (size_t)BB * NN * DD;

    float *p_x, *p_xn, *p_qkv, *p_ws, *p_av, *p_h1, *p_rcat;
    __half *p_AC, *p_BD, *p_attn;
    float *p_wqkvT, *p_wcatT, *p_woutT, *p_wff1T, *p_wff2T;
    cudaGetSymbolAddress((void**)&p_x,   g_x);
    cudaGetSymbolAddress((void**)&p_xn,  g_xn);
    cudaGetSymbolAddress((void**)&p_qkv, g_qkv);
    cudaGetSymbolAddress((void**)&p_ws,  g_ws);
    cudaGetSymbolAddress((void**)&p_AC,  g_AC16);
    cudaGetSymbolAddress((void**)&p_BD,  g_BD16);
    cudaGetSymbolAddress((void**)&p_attn,g_attn16);
    cudaGetSymbolAddress((void**)&p_av,  g_av);
    cudaGetSymbolAddress((void**)&p_h1,  g_h1);
    cudaGetSymbolAddress((void**)&p_rcat, g_rcat);
    cudaGetSymbolAddress((void**)&p_wqkvT, g_wqkvT);
    cudaGetSymbolAddress((void**)&p_wcatT, g_wcatT);
    cudaGetSymbolAddress((void**)&p_woutT, g_woutT);
    cudaGetSymbolAddress((void**)&p_wff1T, g_wff1T);
    cudaGetSymbolAddress((void**)&p_wff2T, g_wff2T);

    cudaFuncSetAttribute(mgemm<false,false,false>, cudaFuncAttributeMaxDynamicSharedMemorySize, MG_SMEM);
    cudaFuncSetAttribute(mgemm<true,true,false>,   cudaFuncAttributeMaxDynamicSharedMemorySize, MG_SMEM);
    cudaFuncSetAttribute(mgemm<true,false,true>,   cudaFuncAttributeMaxDynamicSharedMemorySize, MG_SMEM);
    cudaFuncSetAttribute(scores_mma, cudaFuncAttributeMaxDynamicSharedMemorySize, SC_SMEM);
    cudaFuncSetAttribute(attnv_mma,  cudaFuncAttributeMaxDynamicSharedMemorySize, MG_SMEM);

    const int M = BB * NN;   // 2048
    dim3 t32(32, 8);

    // one-time packing / transposes
    pack_r_kernel<<<(BB * NN * 3 * DD) / 256, 256>>>(r_t, r_c, r_p);
    transpose_batch<<<dim3(48, 16, DEPTH), t32>>>(w_qkv, p_wqkvT, DD, 3*HD, DD, 0, (size_t)3*HD*DD);
    transpose_batch<<<dim3(16, 16, DEPTH), t32>>>(w_kt, p_wcatT, DD, HD, 3*DD, 0,      (size_t)HD*3*DD);
    transpose_batch<<<dim3(16, 16, DEPTH), t32>>>(w_kc, p_wcatT, DD, HD, 3*DD, DD,     (size_t)HD*3*DD);
    transpose_batch<<<dim3(16, 16, DEPTH), t32>>>(w_kp, p_wcatT, DD, HD, 3*DD, 2*DD,   (size_t)HD*3*DD);
    transpose_batch<<<dim3(16, 16, DEPTH), t32>>>(w_out, p_woutT, HD, DD, HD, 0,       (size_t)DD*HD);
    transpose_batch<<<dim3(64, 16, DEPTH), t32>>>(w_ff1, p_wff1T, DD, FFD, DD, 0,      (size_t)FFD*DD);
    transpose_batch<<<dim3(16, 64, DEPTH), t32>>>(w_ff2, p_wff2T, FFD, DD, FFD, 0,     (size_t)DD*FFD);

    copy_in_kernel<<<(BB * NN * DD) / 256, 256>>>(in_x);

    for (int l = 0; l < DEPTH; l++) {
        ln_kernel<<<M, 128>>>(p_x, ln1_g + l * DD, ln1_b + l * DD, p_xn);
        // qkv = xn @ w_qkv[l]
        mgemm<false,false,false><<<dim3(24, 16), 256, MG_SMEM>>>(
            p_xn, p_wqkvT + (size_t)l * 3*HD * DD, p_qkv, 3 * HD, DD, nullptr, nullptr);
        // ws = [r_t|r_c|r_p] @ [w_kt; w_kc; w_kp]  (single K=1536 GEMM)
        mgemm<false,false,false><<<dim3(8, 16), 256, MG_SMEM>>>(
            p_rcat, p_wcatT + (size_t)l * HD * 3*DD, p_ws, HD, 3 * DD, nullptr, nullptr);
        // AC / BD batched scores (fp16 out)
        scores_mma<<<dim3(16, 16, BB * HH), 256, SC_SMEM>>>(p_qkv, p_ws, bias_pf, p_AC, p_BD);
        // dots + rel_shift gather + softmax over heads (fp16 attn; fp32 copy at last layer)
        if (l == DEPTH - 1)
            softmax16<true><<<(BB * NN * NN / 2) / 256, 256>>>(p_AC, p_BD, p_attn, out_attn);
        else
            softmax16<false><<<(BB * NN * NN / 2) / 256, 256>>>(p_AC, p_BD, p_attn, nullptr);
        // attn @ v
        attnv_mma<<<dim3(8, BB * HH), 256, MG_SMEM>>>(p_attn, p_qkv, p_av);
        // out projection + bias + residual
        mgemm<true,true,false><<<dim3(8, 16), 256, MG_SMEM>>>(
            p_av, p_woutT + (size_t)l * DD * HD, p_x, DD, HD, b_out + l * DD, p_x);
        ln_kernel<<<M, 128>>>(p_x, ln2_g + l * DD, ln2_b + l * DD, p_xn);
        // FF1 + bias + exact GELU
        mgemm<true,false,true><<<dim3(32, 16), 256, MG_SMEM>>>(
            p_xn, p_wff1T + (size_t)l * FFD * DD, p_h1, FFD, DD, b_ff1 + l * FFD, nullptr);
        // FF2 + bias + residual
        mgemm<true,true,false><<<dim3(8, 16), 256, MG_SMEM>>>(
            p_h1, p_wff2T + (size_t)l * DD * FFD, p_x, DD, FFD, b_ff2 + l * DD, p_x);
    }

    copy_out_kernel<<<(BB * NN * DD) / 256, 256>>>(out_x);
}

// round 9
// speedup vs baseline: 1.7863x; 1.3740x over previous
#include <cuda_runtime.h>
#include <cuda_fp16.h>
#include <math.h>
#include <stdint.h>

#define BB 2
#define NN 1024
#define DD 512
#define HH 8
#define DHH 64
#define HD 512
#define FFD 2048
#define DEPTH 4

// ---------------- device scratch ----------------
__device__ float  g_x  [BB*NN*DD];
__device__ float  g_xn [BB*NN*DD];
__device__ float  g_qkv[BB*NN*3*HD];
__device__ float  g_ws [BB*NN*HD];
__device__ __half g_AC16 [(size_t)BB*HH*NN*NN];
__device__ __half g_BD16 [(size_t)BB*HH*NN*NN];
__device__ __half g_attn16[(size_t)BB*HH*NN*NN];
__device__ float  g_av [BB*NN*HD];
__device__ float  g_h1 [BB*NN*FFD];
__device__ __half g_rcat [BB*NN * 3*DD];           // fp16 packed [r_t|r_c|r_p]
__device__ __half g_wqkvT[DEPTH * 3*HD * DD];      // fp16 transposed weights
__device__ __half g_wcatT[DEPTH * HD * 3*DD];
__device__ __half g_woutT[DEPTH * DD * HD];
__device__ __half g_wff1T[DEPTH * FFD * DD];
__device__ __half g_wff2T[DEPTH * DD * FFD];

__device__ __forceinline__ uint32_t f22h(float a, float b) {
    __half2 h = __floats2half2_rn(a, b);
    return *reinterpret_cast<uint32_t*>(&h);
}
__device__ __forceinline__ void mma16(float* d, const uint32_t* a, const uint32_t* b) {
    asm volatile("mma.sync.aligned.m16n8k16.row.col.f32.f16.f16.f32 "
        "{%0,%1,%2,%3}, {%4,%5,%6,%7}, {%8,%9}, {%0,%1,%2,%3};"
        : "+f"(d[0]), "+f"(d[1]), "+f"(d[2]), "+f"(d[3])
        : "r"(a[0]), "r"(a[1]), "r"(a[2]), "r"(a[3]), "r"(b[0]), "r"(b[1]));
}

// ---------------- simple copies / packing ----------------
__global__ void copy_in_kernel(const float* __restrict__ src) {
    int i = blockIdx.x * 256 + threadIdx.x;
    g_x[i] = src[i];
}
__global__ void copy_out_kernel(float* __restrict__ dst) {
    int i = blockIdx.x * 256 + threadIdx.x;
    dst[i] = g_x[i];
}
__global__ void pack_r_kernel(const float* __restrict__ rt, const float* __restrict__ rc,
                              const float* __restrict__ rp) {
    int idx = blockIdx.x * 256 + threadIdx.x;      // over BB*NN*1536
    int m = idx / (3 * DD), k = idx % (3 * DD);
    float v;
    if (k < DD)            v = rt[m * DD + k];
    else if (k < 2 * DD)   v = rc[m * DD + k - DD];
    else                   v = rp[m * DD + k - 2 * DD];
    g_rcat[idx] = __float2half(v);
}

// ---------------- weight transpose: src [R,C] fp32 -> dst [C, dstStride] fp16 ----------------
__global__ void transpose_batch(const float* __restrict__ src, __half* __restrict__ dst,
                                int R, int C, int dstStride, int colBase, size_t dstLayer) {
    __shared__ float t[32][33];
    size_t soff = (size_t)blockIdx.z * R * C;
    size_t doff = (size_t)blockIdx.z * dstLayer;
    int c0 = blockIdx.x * 32, r0 = blockIdx.y * 32;
    int x = threadIdx.x, y = threadIdx.y;
#pragma unroll
    for (int i = 0; i < 32; i += 8)
        t[y + i][x] = src[soff + (size_t)(r0 + y + i) * C + c0 + x];
    __syncthreads();
#pragma unroll
    for (int i = 0; i < 32; i += 8)
        dst[doff + (size_t)(c0 + y + i) * dstStride + colBase + r0 + x] = __float2half(t[x][y + i]);
}

// ---------------- layernorm ----------------
__global__ void ln_kernel(const float* __restrict__ x, const float* __restrict__ g,
                          const float* __restrict__ bta, float* __restrict__ y) {
    __shared__ float red[128];
    int row = blockIdx.x;
    int tid = threadIdx.x;
    const float4* xr = (const float4*)(x + (size_t)row * DD);
    float4 v = xr[tid];
    red[tid] = v.x + v.y + v.z + v.w;
    __syncthreads();
    for (int o = 64; o > 0; o >>= 1) { if (tid < o) red[tid] += red[tid + o]; __syncthreads(); }
    float mean = red[0] * (1.0f / DD);
    __syncthreads();
    float dx = v.x - mean, dy = v.y - mean, dz = v.z - mean, dw = v.w - mean;
    red[tid] = dx*dx + dy*dy + dz*dz + dw*dw;
    __syncthreads();
    for (int o = 64; o > 0; o >>= 1) { if (tid < o) red[tid] += red[tid + o]; __syncthreads(); }
    float rstd = rsqrtf(red[0] * (1.0f / DD) + 1e-5f);
    float4 gv = ((const float4*)g)[tid];
    float4 bv = ((const float4*)bta)[tid];
    float4 o4;
    o4.x = dx * rstd * gv.x + bv.x;
    o4.y = dy * rstd * gv.y + bv.y;
    o4.z = dz * rstd * gv.z + bv.z;
    o4.w = dw * rstd * gv.w + bv.w;
    ((float4*)(y + (size_t)row * DD))[tid] = o4;
}

__device__ __forceinline__ float gelu_exact(float v) {
    return 0.5f * v * (1.0f + erff(v * 0.70710678118654752f));
}

// ---------------- fp16 mma GEMM: C[M,Nc] = A[M,K] @ Bt[Nc,K]^T ----------------
// 128x64 CTA tile, 256 threads, BK=32 k-elements (16 half2 rows). fp32 accumulate.
#define AST 136
#define BST 72
#define ABUF (16 * AST)    // 2176 u32
#define BBUF (16 * BST)    // 1152 u32
#define MG_SMEM ((2 * ABUF + 2 * BBUF) * 4)   // 26624 B

template<class AT, bool BIAS, bool RES, bool GELU_>
__global__ void __launch_bounds__(256, 2)
mgemm(const AT* __restrict__ A, const __half* __restrict__ Bt, float* __restrict__ C,
      int Nc, int K, const float* __restrict__ bias, const float* __restrict__ res) {
    extern __shared__ uint32_t smu[];
    uint32_t* sA[2] = { smu, smu + ABUF };
    uint32_t* sB[2] = { smu + 2 * ABUF, smu + 2 * ABUF + BBUF };

    const int tid = threadIdx.x;
    const int wid = tid >> 5, lid = tid & 31;
    const int row0 = blockIdx.y * 128;
    const int col0 = blockIdx.x * 64;

    const int arow = tid >> 1;
    const int akb  = (tid & 1) * 16;     // k element base (16 per thread)
    const int akb2 = (tid & 1) * 8;      // half2 row base
    const int brow = tid >> 2;
    const int bkb  = (tid & 3) * 8;      // k element base (8 per thread)
    const int bkb2 = (tid & 3) * 4;
    const AT*     gA = A  + (size_t)(row0 + arow) * K + akb;
    const __half* gB = Bt + (size_t)(col0 + brow) * K + bkb;

    float acc[2][4][4];
#pragma unroll
    for (int mt = 0; mt < 2; mt++)
#pragma unroll
        for (int nt = 0; nt < 4; nt++)
#pragma unroll
            for (int r = 0; r < 4; r++) acc[mt][nt][r] = 0.f;

    uint32_t ar2[8], br2[4];
    auto loadA = [&](const AT* src) {
        if constexpr (sizeof(AT) == 2) {
            uint4 r0 = *(const uint4*)src;
            uint4 r1 = *(const uint4*)((const __half*)src + 8);
            ar2[0] = r0.x; ar2[1] = r0.y; ar2[2] = r0.z; ar2[3] = r0.w;
            ar2[4] = r1.x; ar2[5] = r1.y; ar2[6] = r1.z; ar2[7] = r1.w;
        } else {
            const float* s = (const float*)src;
            float4 v0 = *(const float4*)(s);
            float4 v1 = *(const float4*)(s + 4);
            float4 v2 = *(const float4*)(s + 8);
            float4 v3 = *(const float4*)(s + 12);
            ar2[0] = f22h(v0.x, v0.y); ar2[1] = f22h(v0.z, v0.w);
            ar2[2] = f22h(v1.x, v1.y); ar2[3] = f22h(v1.z, v1.w);
            ar2[4] = f22h(v2.x, v2.y); ar2[5] = f22h(v2.z, v2.w);
            ar2[6] = f22h(v3.x, v3.y); ar2[7] = f22h(v3.z, v3.w);
        }
    };
    auto loadB = [&](const __half* src) {
        uint4 r = *(const uint4*)src;
        br2[0] = r.x; br2[1] = r.y; br2[2] = r.z; br2[3] = r.w;
    };

    const int nch = K >> 5;
    loadA(gA);
    loadB(gB);
#pragma unroll
    for (int i = 0; i < 8; i++) sA[0][(akb2 + i) * AST + arow] = ar2[i];
#pragma unroll
    for (int i = 0; i < 4; i++) sB[0][(bkb2 + i) * BST + brow] = br2[i];
    __syncthreads();

    const int wm = (wid & 3) * 32;
    const int wn = (wid >> 2) * 32;
    const int g  = lid >> 2;
    const int tg = lid & 3;

    int p = 0;
    for (int c = 0; c < nch; c++) {
        if (c + 1 < nch) {
            loadA(gA + (size_t)(c + 1) * 32);
            loadB(gB + (size_t)(c + 1) * 32);
        }
        const uint32_t* cA = sA[p];
        const uint32_t* cB = sB[p];
#pragma unroll
        for (int s = 0; s < 2; s++) {
            const int k0 = s * 8;
            uint32_t afr[2][4];
#pragma unroll
            for (int mt = 0; mt < 2; mt++) {
                int row = wm + mt * 16 + g;
                afr[mt][0] = cA[(k0 + tg)     * AST + row];
                afr[mt][1] = cA[(k0 + tg)     * AST + row + 8];
                afr[mt][2] = cA[(k0 + tg + 4) * AST + row];
                afr[mt][3] = cA[(k0 + tg + 4) * AST + row + 8];
            }
            uint32_t bfr[4][2];
#pragma unroll
            for (int nt = 0; nt < 4; nt++) {
                int cn = wn + nt * 8 + g;
                bfr[nt][0] = cB[(k0 + tg)     * BST + cn];
                bfr[nt][1] = cB[(k0 + tg + 4) * BST + cn];
            }
#pragma unroll
            for (int mt = 0; mt < 2; mt++)
#pragma unroll
                for (int nt = 0; nt < 4; nt++)
                    mma16(acc[mt][nt], afr[mt], bfr[nt]);
        }
        if (c + 1 < nch) {
            uint32_t* dA = sA[1 - p];
            uint32_t* dB = sB[1 - p];
#pragma unroll
            for (int i = 0; i < 8; i++) dA[(akb2 + i) * AST + arow] = ar2[i];
#pragma unroll
            for (int i = 0; i < 4; i++) dB[(bkb2 + i) * BST + brow] = br2[i];
        }
        __syncthreads();
        p ^= 1;
    }

#pragma unroll
    for (int mt = 0; mt < 2; mt++) {
#pragma unroll
        for (int rh = 0; rh < 2; rh++) {
            int row = row0 + wm + mt * 16 + g + rh * 8;
#pragma unroll
            for (int nt = 0; nt < 4; nt++) {
                int col = col0 + wn + nt * 8 + tg * 2;
                size_t idx = (size_t)row * Nc + col;
                float v0 = acc[mt][nt][rh * 2 + 0];
                float v1 = acc[mt][nt][rh * 2 + 1];
                if (BIAS)  { float2 bv = *(const float2*)(bias + col); v0 += bv.x; v1 += bv.y; }
                if (RES)   { float2 rv = *(const float2*)(res + idx); v0 += rv.x; v1 += rv.y; }
                if (GELU_) { v0 = gelu_exact(v0); v1 = gelu_exact(v1); }
                float2 o2 = make_float2(v0, v1);
                *(float2*)(C + idx) = o2;
            }
        }
    }
}

// ---------------- scores via fp16 mma: AC = Q.K^T, BD = Q.Ws^T (per b,h; K=64) ----------------
#define SCBUF (32 * BST)                 // 2304 u32 per matrix
#define SC_SMEM (3 * SCBUF * 4)          // 27648 B
__global__ void __launch_bounds__(256, 4)
scores_mma(const float* __restrict__ qkv, const float* __restrict__ ws,
           const float* __restrict__ bias_pf,
           __half* __restrict__ AC, __half* __restrict__ BD) {
    extern __shared__ uint32_t smu[];
    uint32_t* Qs = smu;
    uint32_t* Ks = smu + SCBUF;
    uint32_t* Ws = smu + 2 * SCBUF;
    const int bh = blockIdx.z;
    const int b = bh >> 3, h = bh & 7;
    const int i0 = blockIdx.y << 6, j0 = blockIdx.x << 6;
    const int tid = threadIdx.x;

    const int r  = tid >> 2;
    const int d0 = (tid & 3) << 4;
    const float* qb = qkv + (size_t)(b * NN + i0 + r) * (3 * HD) + h * DHH + d0;
    const float* kb = qkv + (size_t)(b * NN + j0 + r) * (3 * HD) + HD + h * DHH + d0;
    const float* wb = ws  + (size_t)(b * NN + j0 + r) * HD + h * DHH + d0;
    const float* pf = bias_pf + h * DHH + d0;
#pragma unroll
    for (int t = 0; t < 4; t++) {
        int d2 = (d0 >> 1) + t * 2;
        float4 q4 = *(const float4*)(qb + t * 4);
        float4 p4 = *(const float4*)(pf + t * 4);
        Qs[(d2 + 0) * BST + r] = f22h(q4.x + p4.x, q4.y + p4.y);
        Qs[(d2 + 1) * BST + r] = f22h(q4.z + p4.z, q4.w + p4.w);
        float4 k4 = *(const float4*)(kb + t * 4);
        Ks[(d2 + 0) * BST + r] = f22h(k4.x, k4.y);
        Ks[(d2 + 1) * BST + r] = f22h(k4.z, k4.w);
        float4 w4 = *(const float4*)(wb + t * 4);
        Ws[(d2 + 0) * BST + r] = f22h(w4.x, w4.y);
        Ws[(d2 + 1) * BST + r] = f22h(w4.z, w4.w);
    }
    __syncthreads();

    const int wid = tid >> 5, lid = tid & 31;
    const int grp = wid >> 2;
    const int w2  = wid & 3;
    const int wm  = (w2 & 1) * 32;
    const int wn  = (w2 >> 1) * 32;
    const uint32_t* Bm = grp ? Ws : Ks;
    const int g = lid >> 2, tg = lid & 3;

    float acc[2][4][4];
#pragma unroll
    for (int mt = 0; mt < 2; mt++)
#pragma unroll
        for (int nt = 0; nt < 4; nt++)
#pragma unroll
            for (int q = 0; q < 4; q++) acc[mt][nt][q] = 0.f;

#pragma unroll
    for (int s = 0; s < 4; s++) {
        const int k0 = s * 8;
        uint32_t afr[2][4];
#pragma unroll
        for (int mt = 0; mt < 2; mt++) {
            int row = wm + mt * 16 + g;
            afr[mt][0] = Qs[(k0 + tg)     * BST + row];
            afr[mt][1] = Qs[(k0 + tg)     * BST + row + 8];
            afr[mt][2] = Qs[(k0 + tg + 4) * BST + row];
            afr[mt][3] = Qs[(k0 + tg + 4) * BST + row + 8];
        }
        uint32_t bfr[4][2];
#pragma unroll
        for (int nt = 0; nt < 4; nt++) {
            int cn = wn + nt * 8 + g;
            bfr[nt][0] = Bm[(k0 + tg)     * BST + cn];
            bfr[nt][1] = Bm[(k0 + tg + 4) * BST + cn];
        }
#pragma unroll
        for (int mt = 0; mt < 2; mt++)
#pragma unroll
            for (int nt = 0; nt < 4; nt++)
                mma16(acc[mt][nt], afr[mt], bfr[nt]);
    }

    __half* Out = grp ? BD : AC;
    const size_t base = ((size_t)bh << 20);
#pragma unroll
    for (int mt = 0; mt < 2; mt++) {
#pragma unroll
        for (int rh = 0; rh < 2; rh++) {
            int i = i0 + wm + mt * 16 + g + rh * 8;
#pragma unroll
            for (int nt = 0; nt < 4; nt++) {
                int j = j0 + wn + nt * 8 + tg * 2;
                __half2 h2 = __floats2half2_rn(acc[mt][nt][rh * 2 + 0], acc[mt][nt][rh * 2 + 1]);
                *(__half2*)(Out + base + ((size_t)i << 10) + j) = h2;
            }
        }
    }
}

// ---------------- dots + rel_shift + softmax over heads (fp16 in/out) ----------------
template<bool LAST>
__global__ void softmax16(const __half* __restrict__ AC, const __half* __restrict__ BD,
                          __half* __restrict__ attn, float* __restrict__ out_attn) {
    int gid = blockIdx.x * 256 + threadIdx.x;
    int b = gid >> 19;
    int ijp = gid & ((1 << 19) - 1);
    int ij = ijp << 1;
    int i = ij >> 10, j = ij & 1023;

    int m0 = (i + 1) * NN + j;
    int i2a = m0 / (NN + 1);
    int ka  = m0 - i2a * (NN + 1);
    int i2b, kb;
    if (ka == NN) { i2b = i2a + 1; kb = 0; }
    else          { i2b = i2a;     kb = ka + 1; }

    size_t pb = ((size_t)(b * HH)) << 20;
    size_t sa = ((size_t)i2a << 10) + (ka - 1);
    size_t sb = ((size_t)i2b << 10) + (kb - 1);

    float va[8], vb[8];
#pragma unroll
    for (int h = 0; h < 8; h++) {
        size_t hp = pb + ((size_t)h << 20);
        __half2 ac2 = *(const __half2*)(AC + hp + ij);
        float bda = (ka != 0) ? __half2float(BD[hp + sa]) : 0.f;
        float bdb = (kb != 0) ? __half2float(BD[hp + sb]) : 0.f;
        va[h] = (__low2float(ac2)  + bda * (1.0f / 3.0f)) * 0.125f;
        vb[h] = (__high2float(ac2) + bdb * (1.0f / 3.0f)) * 0.125f;
    }
    float mxa = va[0], mxb = vb[0];
#pragma unroll
    for (int h = 1; h < 8; h++) { mxa = fmaxf(mxa, va[h]); mxb = fmaxf(mxb, vb[h]); }
    float sa_ = 0.f, sb_ = 0.f;
#pragma unroll
    for (int h = 0; h < 8; h++) {
        va[h] = __expf(va[h] - mxa); sa_ += va[h];
        vb[h] = __expf(vb[h] - mxb); sb_ += vb[h];
    }
    float ia = 1.0f / sa_, ib = 1.0f / sb_;
#pragma unroll
    for (int h = 0; h < 8; h++) {
        size_t hp = pb + ((size_t)h << 20);
        float oa = va[h] * ia, ob = vb[h] * ib;
        *(__half2*)(attn + hp + ij) = __floats2half2_rn(oa, ob);
        if (LAST) {
            float2 o2 = make_float2(oa, ob);
            *(float2*)(out_attn + hp + ij) = o2;
        }
    }
}

// ---------------- attn(fp16) @ v via fp16 mma (per b,h; M=1024, N=64, K=1024) ----------------
__global__ void __launch_bounds__(256, 2)
attnv_mma(const __half* __restrict__ attn, const float* __restrict__ qkv,
          float* __restrict__ av) {
    extern __shared__ uint32_t smu[];
    uint32_t* sA[2] = { smu, smu + ABUF };
    uint32_t* sB[2] = { smu + 2 * ABUF, smu + 2 * ABUF + BBUF };

    const int bh = blockIdx.y;
    const int b = bh >> 3, h = bh & 7;
    const int i0 = blockIdx.x << 7;
    const int tid = threadIdx.x;
    const int wid = tid >> 5, lid = tid & 31;

    const int arow = tid >> 1;
    const int akb  = (tid & 1) * 16;
    const int akb2 = (tid & 1) * 8;
    const int jp   = tid >> 4;            // 0..15: j-pair within chunk
    const int d0   = (tid & 15) * 4;      // d offset
    const __half* gA = attn + ((size_t)bh << 20) + ((size_t)(i0 + arow) << 10) + akb;
    const float*  gV = qkv + 2 * HD + h * DHH + d0;

    float acc[2][4][4];
#pragma unroll
    for (int mt = 0; mt < 2; mt++)
#pragma unroll
        for (int nt = 0; nt < 4; nt++)
#pragma unroll
            for (int q = 0; q < 4; q++) acc[mt][nt][q] = 0.f;

    uint32_t ar2[8], bv2[4];
    auto loadA = [&](const __half* src) {
        uint4 r0 = *(const uint4*)src;
        uint4 r1 = *(const uint4*)(src + 8);
        ar2[0] = r0.x; ar2[1] = r0.y; ar2[2] = r0.z; ar2[3] = r0.w;
        ar2[4] = r1.x; ar2[5] = r1.y; ar2[6] = r1.z; ar2[7] = r1.w;
    };
    auto loadV = [&](int jbase) {
        const float* v0 = gV + (size_t)(b * NN + jbase + 2 * jp) * (3 * HD);
        const float* v1 = v0 + 3 * HD;
        float4 a = *(const float4*)v0;
        float4 c = *(const float4*)v1;
        bv2[0] = f22h(a.x, c.x); bv2[1] = f22h(a.y, c.y);
        bv2[2] = f22h(a.z, c.z); bv2[3] = f22h(a.w, c.w);
    };

    const int nch = NN >> 5;  // 32
    loadA(gA);
    loadV(0);
#pragma unroll
    for (int i = 0; i < 8; i++) sA[0][(akb2 + i) * AST + arow] = ar2[i];
    *(uint4*)&sB[0][jp * BST + d0] = make_uint4(bv2[0], bv2[1], bv2[2], bv2[3]);
    __syncthreads();

    const int wm = (wid & 3) * 32;
    const int wn = (wid >> 2) * 32;
    const int g  = lid >> 2;
    const int tg = lid & 3;

    int p = 0;
    for (int c = 0; c < nch; c++) {
        if (c + 1 < nch) {
            loadA(gA + (size_t)(c + 1) * 32);
            loadV((c + 1) * 32);
        }
        const uint32_t* cA = sA[p];
        const uint32_t* cB = sB[p];
#pragma unroll
        for (int s = 0; s < 2; s++) {
            const int k0 = s * 8;
            uint32_t afr[2][4];
#pragma unroll
            for (int mt = 0; mt < 2; mt++) {
                int row = wm + mt * 16 + g;
                afr[mt][0] = cA[(k0 + tg)     * AST + row];
                afr[mt][1] = cA[(k0 + tg)     * AST + row + 8];
                afr[mt][2] = cA[(k0 + tg + 4) * AST + row];
                afr[mt][3] = cA[(k0 + tg + 4) * AST + row + 8];
            }
            uint32_t bfr[4][2];
#pragma unroll
            for (int nt = 0; nt < 4; nt++) {
                int cn = wn + nt * 8 + g;
                bfr[nt][0] = cB[(k0 + tg)     * BST + cn];
                bfr[nt][1] = cB[(k0 + tg + 4) * BST + cn];
            }
#pragma unroll
            for (int mt = 0; mt < 2; mt++)
#pragma unroll
                for (int nt = 0; nt < 4; nt++)
                    mma16(acc[mt][nt], afr[mt], bfr[nt]);
        }
        if (c + 1 < nch) {
            uint32_t* dA = sA[1 - p];
            uint32_t* dB = sB[1 - p];
#pragma unroll
            for (int i = 0; i < 8; i++) dA[(akb2 + i) * AST + arow] = ar2[i];
            *(uint4*)&dB[jp * BST + d0] = make_uint4(bv2[0], bv2[1], bv2[2], bv2[3]);
        }
        __syncthreads();
        p ^= 1;
    }

#pragma unroll
    for (int mt = 0; mt < 2; mt++) {
#pragma unroll
        for (int rh = 0; rh < 2; rh++) {
            int row = i0 + wm + mt * 16 + g + rh * 8;
#pragma unroll
            for (int nt = 0; nt < 4; nt++) {
                int col = wn + nt * 8 + tg * 2;
                float2 o2 = make_float2(acc[mt][nt][rh * 2 + 0], acc[mt][nt][rh * 2 + 1]);
                *(float2*)(av + (size_t)(b * NN + row) * HD + h * DHH + col) = o2;
            }
        }
    }
}

// ---------------- host orchestration ----------------
extern "C" void kernel_launch(void* const* d_in, const int* in_sizes, int n_in,
                              void* d_out, int out_size) {
    (void)in_sizes; (void)n_in; (void)out_size;
    const float* in_x   = (const float*)d_in[0];
    const float* r_t    = (const float*)d_in[1];
    const float* r_c    = (const float*)d_in[2];
    const float* r_p    = (const float*)d_in[3];
    const float* bias_pf= (const float*)d_in[4];
    const float* ln1_g  = (const float*)d_in[5];
    const float* ln1_b  = (const float*)d_in[6];
    const float* w_qkv  = (const float*)d_in[7];
    const float* w_out  = (const float*)d_in[8];
    const float* b_out  = (const float*)d_in[9];
    const float* w_kt   = (const float*)d_in[10];
    const float* w_kc   = (const float*)d_in[11];
    const float* w_kp   = (const float*)d_in[12];
    const float* ln2_g  = (const float*)d_in[13];
    const float* ln2_b  = (const float*)d_in[14];
    const float* w_ff1  = (const float*)d_in[15];
    const float* b_ff1  = (const float*)d_in[16];
    const float* w_ff2  = (const float*)d_in[17];
    const float* b_ff2  = (const float*)d_in[18];

    float* out_x    = (float*)d_out;
    float* out_attn = out_x + (size_t)BB * NN * DD;

    float *p_x, *p_xn, *p_qkv, *p_ws, *p_av, *p_h1;
    __half *p_AC, *p_BD, *p_attn, *p_rcat;
    __half *p_wqkvT, *p_wcatT, *p_woutT, *p_wff1T, *p_wff2T;
    cudaGetSymbolAddress((void**)&p_x,   g_x);
    cudaGetSymbolAddress((void**)&p_xn,  g_xn);
    cudaGetSymbolAddress((void**)&p_qkv, g_qkv);
    cudaGetSymbolAddress((void**)&p_ws,  g_ws);
    cudaGetSymbolAddress((void**)&p_AC,  g_AC16);
    cudaGetSymbolAddress((void**)&p_BD,  g_BD16);
    cudaGetSymbolAddress((void**)&p_attn,g_attn16);
    cudaGetSymbolAddress((void**)&p_av,  g_av);
    cudaGetSymbolAddress((void**)&p_h1,  g_h1);
    cudaGetSymbolAddress((void**)&p_rcat, g_rcat);
    cudaGetSymbolAddress((void**)&p_wqkvT, g_wqkvT);
    cudaGetSymbolAddress((void**)&p_wcatT, g_wcatT);
    cudaGetSymbolAddress((void**)&p_woutT, g_woutT);
    cudaGetSymbolAddress((void**)&p_wff1T, g_wff1T);
    cudaGetSymbolAddress((void**)&p_wff2T, g_wff2T);

    cudaFuncSetAttribute((const void*)mgemm<float,false,false,false>,  cudaFuncAttributeMaxDynamicSharedMemorySize, MG_SMEM);
    cudaFuncSetAttribute((const void*)mgemm<__half,false,false,false>, cudaFuncAttributeMaxDynamicSharedMemorySize, MG_SMEM);
    cudaFuncSetAttribute((const void*)mgemm<float,true,true,false>,    cudaFuncAttributeMaxDynamicSharedMemorySize, MG_SMEM);
    cudaFuncSetAttribute((const void*)mgemm<float,true,false,true>,    cudaFuncAttributeMaxDynamicSharedMemorySize, MG_SMEM);
    cudaFuncSetAttribute((const void*)scores_mma, cudaFuncAttributeMaxDynamicSharedMemorySize, SC_SMEM);
    cudaFuncSetAttribute((const void*)attnv_mma,  cudaFuncAttributeMaxDynamicSharedMemorySize, MG_SMEM);

    const int M = BB * NN;   // 2048
    dim3 t32(32, 8);

    // one-time packing / transposes (fp32 -> fp16)
    pack_r_kernel<<<(BB * NN * 3 * DD) / 256, 256>>>(r_t, r_c, r_p);
    transpose_batch<<<dim3(48, 16, DEPTH), t32>>>(w_qkv, p_wqkvT, DD, 3*HD, DD, 0, (size_t)3*HD*DD);
    transpose_batch<<<dim3(16, 16, DEPTH), t32>>>(w_kt, p_wcatT, DD, HD, 3*DD, 0,      (size_t)HD*3*DD);
    transpose_batch<<<dim3(16, 16, DEPTH), t32>>>(w_kc, p_wcatT, DD, HD, 3*DD, DD,     (size_t)HD*3*DD);
    transpose_batch<<<dim3(16, 16, DEPTH), t32>>>(w_kp, p_wcatT, DD, HD, 3*DD, 2*DD,   (size_t)HD*3*DD);
    transpose_batch<<<dim3(16, 16, DEPTH), t32>>>(w_out, p_woutT, HD, DD, HD, 0,       (size_t)DD*HD);
    transpose_batch<<<dim3(64, 16, DEPTH), t32>>>(w_ff1, p_wff1T, DD, FFD, DD, 0,      (size_t)FFD*DD);
    transpose_batch<<<dim3(16, 64, DEPTH), t32>>>(w_ff2, p_wff2T, FFD, DD, FFD, 0,     (size_t)DD*FFD);

    copy_in_kernel<<<(BB * NN * DD) / 256, 256>>>(in_x);

    for (int l = 0; l < DEPTH; l++) {
        ln_kernel<<<M, 128>>>(p_x, ln1_g + l * DD, ln1_b + l * DD, p_xn);
        // qkv = xn @ w_qkv[l]
        mgemm<float,false,false,false><<<dim3(24, 16), 256, MG_SMEM>>>(
            p_xn, p_wqkvT + (size_t)l * 3*HD * DD, p_qkv, 3 * HD, DD, nullptr, nullptr);
        // ws = [r_t|r_c|r_p] @ [w_kt; w_kc; w_kp]  (single K=1536 GEMM, fp16 A)
        mgemm<__half,false,false,false><<<dim3(8, 16), 256, MG_SMEM>>>(
            p_rcat, p_wcatT + (size_t)l * HD * 3*DD, p_ws, HD, 3 * DD, nullptr, nullptr);
        // AC / BD batched scores (fp16 out)
        scores_mma<<<dim3(16, 16, BB * HH), 256, SC_SMEM>>>(p_qkv, p_ws, bias_pf, p_AC, p_BD);
        // dots + rel_shift + softmax over heads
        if (l == DEPTH - 1)
            softmax16<true><<<(BB * NN * NN / 2) / 256, 256>>>(p_AC, p_BD, p_attn, out_attn);
        else
            softmax16<false><<<(BB * NN * NN / 2) / 256, 256>>>(p_AC, p_BD, p_attn, nullptr);
        // attn @ v
        attnv_mma<<<dim3(8, BB * HH), 256, MG_SMEM>>>(p_attn, p_qkv, p_av);
        // out projection + bias + residual
        mgemm<float,true,true,false><<<dim3(8, 16), 256, MG_SMEM>>>(
            p_av, p_woutT + (size_t)l * DD * HD, p_x, DD, HD, b_out + l * DD, p_x);
        ln_kernel<<<M, 128>>>(p_x, ln2_g + l * DD, ln2_b + l * DD, p_xn);
        // FF1 + bias + exact GELU
        mgemm<float,true,false,true><<<dim3(32, 16), 256, MG_SMEM>>>(
            p_xn, p_wff1T + (size_t)l * FFD * DD, p_h1, FFD, DD, b_ff1 + l * FFD, nullptr);
        // FF2 + bias + residual
        mgemm<float,true,true,false><<<dim3(8, 16), 256, MG_SMEM>>>(
            p_h1, p_wff2T + (size_t)l * DD * FFD, p_x, DD, FFD, b_ff2 + l * DD, p_x);
    }

    copy_out_kernel<<<(BB * NN * DD) / 256, 256>>>(out_x);
}

// round 11
// speedup vs baseline: 2.0711x; 1.1595x over previous
#include <cuda_runtime.h>
#include <cuda_fp16.h>
#include <math.h>
#include <stdint.h>

#define BB 2
#define NN 1024
#define DD 512
#define HH 8
#define DHH 64
#define HD 512
#define FFD 2048
#define DEPTH 4

// ---------------- device scratch ----------------
__device__ float  g_x  [BB*NN*DD];              // fp32 residual stream
__device__ __half g_xn [BB*NN*DD];
__device__ __half g_qkv[BB*NN*3*HD];
__device__ __half g_ws [BB*NN*HD];
__device__ __half g_AC16 [(size_t)BB*HH*NN*NN];
__device__ __half g_BD16 [(size_t)BB*HH*NN*NN];
__device__ __half g_attn16[(size_t)BB*HH*NN*NN];
__device__ __half g_av [BB*NN*HD];
__device__ __half g_h1 [BB*NN*FFD];
__device__ __half g_rcat [BB*NN * 3*DD];
__device__ __half g_pf16 [HD];
__device__ __half g_wqkvT[DEPTH * 3*HD * DD];
__device__ __half g_wcatT[DEPTH * HD * 3*DD];
__device__ __half g_woutT[DEPTH * DD * HD];
__device__ __half g_wff1T[DEPTH * FFD * DD];
__device__ __half g_wff2T[DEPTH * DD * FFD];

__device__ __forceinline__ uint32_t f22h(float a, float b) {
    __half2 h = __floats2half2_rn(a, b);
    return *reinterpret_cast<uint32_t*>(&h);
}
__device__ __forceinline__ uint32_t hadd2u(uint32_t a, uint32_t b) {
    __half2 r = __hadd2(*(__half2*)&a, *(__half2*)&b);
    return *reinterpret_cast<uint32_t*>(&r);
}
__device__ __forceinline__ void mma16(float* d, const uint32_t* a, const uint32_t* b) {
    asm volatile("mma.sync.aligned.m16n8k16.row.col.f32.f16.f16.f32 "
        "{%0,%1,%2,%3}, {%4,%5,%6,%7}, {%8,%9}, {%0,%1,%2,%3};"
        : "+f"(d[0]), "+f"(d[1]), "+f"(d[2]), "+f"(d[3])
        : "r"(a[0]), "r"(a[1]), "r"(a[2]), "r"(a[3]), "r"(b[0]), "r"(b[1]));
}

// ---------------- packing ----------------
__global__ void pack_r_kernel(const float* __restrict__ rt, const float* __restrict__ rc,
                              const float* __restrict__ rp) {
    int idx = blockIdx.x * 256 + threadIdx.x;
    int m = idx / (3 * DD), k = idx % (3 * DD);
    float v;
    if (k < DD)            v = rt[m * DD + k];
    else if (k < 2 * DD)   v = rc[m * DD + k - DD];
    else                   v = rp[m * DD + k - 2 * DD];
    g_rcat[idx] = __float2half(v);
}
__global__ void pack_pf_kernel(const float* __restrict__ pf) {
    int i = blockIdx.x * 256 + threadIdx.x;
    if (i < HD) g_pf16[i] = __float2half(pf[i]);
}

// ---------------- weight transpose: src [R,C] fp32 -> dst [C, dstStride] fp16 ----------------
__global__ void transpose_batch(const float* __restrict__ src, __half* __restrict__ dst,
                                int R, int C, int dstStride, int colBase, size_t dstLayer) {
    __shared__ float t[32][33];
    size_t soff = (size_t)blockIdx.z * R * C;
    size_t doff = (size_t)blockIdx.z * dstLayer;
    int c0 = blockIdx.x * 32, r0 = blockIdx.y * 32;
    int x = threadIdx.x, y = threadIdx.y;
#pragma unroll
    for (int i = 0; i < 32; i += 8)
        t[y + i][x] = src[soff + (size_t)(r0 + y + i) * C + c0 + x];
    __syncthreads();
#pragma unroll
    for (int i = 0; i < 32; i += 8)
        dst[doff + (size_t)(c0 + y + i) * dstStride + colBase + r0 + x] = __float2half(t[x][y + i]);
}

// ---------------- layernorm: fp32 in -> fp16 out ----------------
__global__ void ln_kernel(const float* __restrict__ x, const float* __restrict__ g,
                          const float* __restrict__ bta, __half* __restrict__ y) {
    __shared__ float red[128];
    int row = blockIdx.x;
    int tid = threadIdx.x;
    const float4* xr = (const float4*)(x + (size_t)row * DD);
    float4 v = xr[tid];
    red[tid] = v.x + v.y + v.z + v.w;
    __syncthreads();
    for (int o = 64; o > 0; o >>= 1) { if (tid < o) red[tid] += red[tid + o]; __syncthreads(); }
    float mean = red[0] * (1.0f / DD);
    __syncthreads();
    float dx = v.x - mean, dy = v.y - mean, dz = v.z - mean, dw = v.w - mean;
    red[tid] = dx*dx + dy*dy + dz*dz + dw*dw;
    __syncthreads();
    for (int o = 64; o > 0; o >>= 1) { if (tid < o) red[tid] += red[tid + o]; __syncthreads(); }
    float rstd = rsqrtf(red[0] * (1.0f / DD) + 1e-5f);
    float4 gv = ((const float4*)g)[tid];
    float4 bv = ((const float4*)bta)[tid];
    uint2 o2;
    o2.x = f22h(dx * rstd * gv.x + bv.x, dy * rstd * gv.y + bv.y);
    o2.y = f22h(dz * rstd * gv.z + bv.z, dw * rstd * gv.w + bv.w);
    *(uint2*)(y + (size_t)row * DD + tid * 4) = o2;
}

__device__ __forceinline__ float gelu_exact(float v) {
    return 0.5f * v * (1.0f + erff(v * 0.70710678118654752f));
}

// ---------------- fp16 mma GEMM: C[M,Nc] = A[M,K] @ Bt[Nc,K]^T, A fp16, C fp32/fp16 ----------------
#define AST 136
#define BST 72
#define ABUF (16 * AST)
#define BBUF (16 * BST)
#define MG_SMEM ((2 * ABUF + 2 * BBUF) * 4)   // 26624 B

template<class CT, bool BIAS, bool RES, bool GELU_>
__global__ void __launch_bounds__(256, 2)
mgemm(const __half* __restrict__ A, const __half* __restrict__ Bt, CT* __restrict__ C,
      int Nc, int K, const float* __restrict__ bias, const float* __restrict__ res) {
    extern __shared__ uint32_t smu[];
    uint32_t* sA[2] = { smu, smu + ABUF };
    uint32_t* sB[2] = { smu + 2 * ABUF, smu + 2 * ABUF + BBUF };

    const int tid = threadIdx.x;
    const int wid = tid >> 5, lid = tid & 31;
    const int row0 = blockIdx.y * 128;
    const int col0 = blockIdx.x * 64;

    const int arow = tid >> 1;
    const int akb  = (tid & 1) * 16;
    const int akb2 = (tid & 1) * 8;
    const int brow = tid >> 2;
    const int bkb  = (tid & 3) * 8;
    const int bkb2 = (tid & 3) * 4;
    const __half* gA = A  + (size_t)(row0 + arow) * K + akb;
    const __half* gB = Bt + (size_t)(col0 + brow) * K + bkb;

    float acc[2][4][4];
#pragma unroll
    for (int mt = 0; mt < 2; mt++)
#pragma unroll
        for (int nt = 0; nt < 4; nt++)
#pragma unroll
            for (int r = 0; r < 4; r++) acc[mt][nt][r] = 0.f;

    uint32_t ar2[8], br2[4];
    auto loadA = [&](const __half* src) {
        uint4 r0 = *(const uint4*)src;
        uint4 r1 = *(const uint4*)(src + 8);
        ar2[0] = r0.x; ar2[1] = r0.y; ar2[2] = r0.z; ar2[3] = r0.w;
        ar2[4] = r1.x; ar2[5] = r1.y; ar2[6] = r1.z; ar2[7] = r1.w;
    };
    auto loadB = [&](const __half* src) {
        uint4 r = *(const uint4*)src;
        br2[0] = r.x; br2[1] = r.y; br2[2] = r.z; br2[3] = r.w;
    };

    const int nch = K >> 5;
    loadA(gA);
    loadB(gB);
#pragma unroll
    for (int i = 0; i < 8; i++) sA[0][(akb2 + i) * AST + arow] = ar2[i];
#pragma unroll
    for (int i = 0; i < 4; i++) sB[0][(bkb2 + i) * BST + brow] = br2[i];
    __syncthreads();

    const int wm = (wid & 3) * 32;
    const int wn = (wid >> 2) * 32;
    const int g  = lid >> 2;
    const int tg = lid & 3;

    int p = 0;
    for (int c = 0; c < nch; c++) {
        if (c + 1 < nch) {
            loadA(gA + (size_t)(c + 1) * 32);
            loadB(gB + (size_t)(c + 1) * 32);
        }
        const uint32_t* cA = sA[p];
        const uint32_t* cB = sB[p];
#pragma unroll
        for (int s = 0; s < 2; s++) {
            const int k0 = s * 8;
            uint32_t afr[2][4];
#pragma unroll
            for (int mt = 0; mt < 2; mt++) {
                int row = wm + mt * 16 + g;
                afr[mt][0] = cA[(k0 + tg)     * AST + row];
                afr[mt][1] = cA[(k0 + tg)     * AST + row + 8];
                afr[mt][2] = cA[(k0 + tg + 4) * AST + row];
                afr[mt][3] = cA[(k0 + tg + 4) * AST + row + 8];
            }
            uint32_t bfr[4][2];
#pragma unroll
            for (int nt = 0; nt < 4; nt++) {
                int cn = wn + nt * 8 + g;
                bfr[nt][0] = cB[(k0 + tg)     * BST + cn];
                bfr[nt][1] = cB[(k0 + tg + 4) * BST + cn];
            }
#pragma unroll
            for (int mt = 0; mt < 2; mt++)
#pragma unroll
                for (int nt = 0; nt < 4; nt++)
                    mma16(acc[mt][nt], afr[mt], bfr[nt]);
        }
        if (c + 1 < nch) {
            uint32_t* dA = sA[1 - p];
            uint32_t* dB = sB[1 - p];
#pragma unroll
            for (int i = 0; i < 8; i++) dA[(akb2 + i) * AST + arow] = ar2[i];
#pragma unroll
            for (int i = 0; i < 4; i++) dB[(bkb2 + i) * BST + brow] = br2[i];
        }
        __syncthreads();
        p ^= 1;
    }

#pragma unroll
    for (int mt = 0; mt < 2; mt++) {
#pragma unroll
        for (int rh = 0; rh < 2; rh++) {
            int row = row0 + wm + mt * 16 + g + rh * 8;
#pragma unroll
            for (int nt = 0; nt < 4; nt++) {
                int col = col0 + wn + nt * 8 + tg * 2;
                size_t idx = (size_t)row * Nc + col;
                float v0 = acc[mt][nt][rh * 2 + 0];
                float v1 = acc[mt][nt][rh * 2 + 1];
                if (BIAS)  { float2 bv = *(const float2*)(bias + col); v0 += bv.x; v1 += bv.y; }
                if (RES)   { float2 rv = *(const float2*)(res + idx); v0 += rv.x; v1 += rv.y; }
                if (GELU_) { v0 = gelu_exact(v0); v1 = gelu_exact(v1); }
                if constexpr (sizeof(CT) == 2) {
                    *(__half2*)((__half*)C + idx) = __floats2half2_rn(v0, v1);
                } else {
                    *(float2*)((float*)C + idx) = make_float2(v0, v1);
                }
            }
        }
    }
}

// ---------------- scores via fp16 mma: AC = Q.K^T, BD = Q.Ws^T (per b,h; K=64) ----------------
#define SCBUF (32 * BST)
#define SC_SMEM (3 * SCBUF * 4)
__global__ void __launch_bounds__(256, 4)
scores_mma(const __half* __restrict__ qkv, const __half* __restrict__ ws,
           __half* __restrict__ AC, __half* __restrict__ BD) {
    extern __shared__ uint32_t smu[];
    uint32_t* Qs = smu;
    uint32_t* Ks = smu + SCBUF;
    uint32_t* Ws = smu + 2 * SCBUF;
    const int bh = blockIdx.z;
    const int b = bh >> 3, h = bh & 7;
    const int i0 = blockIdx.y << 6, j0 = blockIdx.x << 6;
    const int tid = threadIdx.x;

    const int r  = tid >> 2;
    const int d0 = (tid & 3) << 4;     // half base (16 per thread)
    const int d2b = (tid & 3) << 3;    // half2 row base
    const __half* qb = qkv + (size_t)(b * NN + i0 + r) * (3 * HD) + h * DHH + d0;
    const __half* kb = qkv + (size_t)(b * NN + j0 + r) * (3 * HD) + HD + h * DHH + d0;
    const __half* wb = ws  + (size_t)(b * NN + j0 + r) * HD + h * DHH + d0;
    const __half* pf = g_pf16 + h * DHH + d0;
    {
        uint4 q0 = *(const uint4*)qb, q1 = *(const uint4*)(qb + 8);
        uint4 p0 = *(const uint4*)pf, p1 = *(const uint4*)(pf + 8);
        uint4 k0 = *(const uint4*)kb, k1 = *(const uint4*)(kb + 8);
        uint4 w0 = *(const uint4*)wb, w1 = *(const uint4*)(wb + 8);
        uint32_t qq[8] = {q0.x,q0.y,q0.z,q0.w,q1.x,q1.y,q1.z,q1.w};
        uint32_t pp[8] = {p0.x,p0.y,p0.z,p0.w,p1.x,p1.y,p1.z,p1.w};
        uint32_t kk[8] = {k0.x,k0.y,k0.z,k0.w,k1.x,k1.y,k1.z,k1.w};
        uint32_t ww[8] = {w0.x,w0.y,w0.z,w0.w,w1.x,w1.y,w1.z,w1.w};
#pragma unroll
        for (int i = 0; i < 8; i++) {
            Qs[(d2b + i) * BST + r] = hadd2u(qq[i], pp[i]);
            Ks[(d2b + i) * BST + r] = kk[i];
            Ws[(d2b + i) * BST + r] = ww[i];
        }
    }
    __syncthreads();

    const int wid = tid >> 5, lid = tid & 31;
    const int grp = wid >> 2;
    const int w2  = wid & 3;
    const int wm  = (w2 & 1) * 32;
    const int wn  = (w2 >> 1) * 32;
    const uint32_t* Bm = grp ? Ws : Ks;
    const int g = lid >> 2, tg = lid & 3;

    float acc[2][4][4];
#pragma unroll
    for (int mt = 0; mt < 2; mt++)
#pragma unroll
        for (int nt = 0; nt < 4; nt++)
#pragma unroll
            for (int q = 0; q < 4; q++) acc[mt][nt][q] = 0.f;

#pragma unroll
    for (int s = 0; s < 4; s++) {
        const int k0 = s * 8;
        uint32_t afr[2][4];
#pragma unroll
        for (int mt = 0; mt < 2; mt++) {
            int row = wm + mt * 16 + g;
            afr[mt][0] = Qs[(k0 + tg)     * BST + row];
            afr[mt][1] = Qs[(k0 + tg)     * BST + row + 8];
            afr[mt][2] = Qs[(k0 + tg + 4) * BST + row];
            afr[mt][3] = Qs[(k0 + tg + 4) * BST + row + 8];
        }
        uint32_t bfr[4][2];
#pragma unroll
        for (int nt = 0; nt < 4; nt++) {
            int cn = wn + nt * 8 + g;
            bfr[nt][0] = Bm[(k0 + tg)     * BST + cn];
            bfr[nt][1] = Bm[(k0 + tg + 4) * BST + cn];
        }
#pragma unroll
        for (int mt = 0; mt < 2; mt++)
#pragma unroll
            for (int nt = 0; nt < 4; nt++)
                mma16(acc[mt][nt], afr[mt], bfr[nt]);
    }

    __half* Out = grp ? BD : AC;
    const size_t base = ((size_t)bh << 20);
#pragma unroll
    for (int mt = 0; mt < 2; mt++) {
#pragma unroll
        for (int rh = 0; rh < 2; rh++) {
            int i = i0 + wm + mt * 16 + g + rh * 8;
#pragma unroll
            for (int nt = 0; nt < 4; nt++) {
                int j = j0 + wn + nt * 8 + tg * 2;
                __half2 h2 = __floats2half2_rn(acc[mt][nt][rh * 2 + 0], acc[mt][nt][rh * 2 + 1]);
                *(__half2*)(Out + base + ((size_t)i << 10) + j) = h2;
            }
        }
    }
}

// ---------------- dots + rel_shift + softmax over heads (fp16 in/out) ----------------
template<bool LAST>
__global__ void softmax16(const __half* __restrict__ AC, const __half* __restrict__ BD,
                          __half* __restrict__ attn, float* __restrict__ out_attn) {
    int gid = blockIdx.x * 256 + threadIdx.x;
    int b = gid >> 19;
    int ijp = gid & ((1 << 19) - 1);
    int ij = ijp << 1;
    int i = ij >> 10, j = ij & 1023;

    int m0 = (i + 1) * NN + j;
    int i2a = m0 / (NN + 1);
    int ka  = m0 - i2a * (NN + 1);
    int i2b, kb;
    if (ka == NN) { i2b = i2a + 1; kb = 0; }
    else          { i2b = i2a;     kb = ka + 1; }

    size_t pb = ((size_t)(b * HH)) << 20;
    size_t sa = ((size_t)i2a << 10) + (ka - 1);
    size_t sb = ((size_t)i2b << 10) + (kb - 1);

    float va[8], vb[8];
#pragma unroll
    for (int h = 0; h < 8; h++) {
        size_t hp = pb + ((size_t)h << 20);
        __half2 ac2 = *(const __half2*)(AC + hp + ij);
        float bda = (ka != 0) ? __half2float(BD[hp + sa]) : 0.f;
        float bdb = (kb != 0) ? __half2float(BD[hp + sb]) : 0.f;
        va[h] = (__low2float(ac2)  + bda * (1.0f / 3.0f)) * 0.125f;
        vb[h] = (__high2float(ac2) + bdb * (1.0f / 3.0f)) * 0.125f;
    }
    float mxa = va[0], mxb = vb[0];
#pragma unroll
    for (int h = 1; h < 8; h++) { mxa = fmaxf(mxa, va[h]); mxb = fmaxf(mxb, vb[h]); }
    float sa_ = 0.f, sb_ = 0.f;
#pragma unroll
    for (int h = 0; h < 8; h++) {
        va[h] = __expf(va[h] - mxa); sa_ += va[h];
        vb[h] = __expf(vb[h] - mxb); sb_ += vb[h];
    }
    float ia = 1.0f / sa_, ib = 1.0f / sb_;
#pragma unroll
    for (int h = 0; h < 8; h++) {
        size_t hp = pb + ((size_t)h << 20);
        float oa = va[h] * ia, ob = vb[h] * ib;
        *(__half2*)(attn + hp + ij) = __floats2half2_rn(oa, ob);
        if (LAST) {
            float2 o2 = make_float2(oa, ob);
            *(float2*)(out_attn + hp + ij) = o2;
        }
    }
}

// ---------------- attn(fp16) @ v(fp16) -> av(fp16) via fp16 mma ----------------
__global__ void __launch_bounds__(256, 2)
attnv_mma(const __half* __restrict__ attn, const __half* __restrict__ qkv,
          __half* __restrict__ av) {
    extern __shared__ uint32_t smu[];
    uint32_t* sA[2] = { smu, smu + ABUF };
    uint32_t* sB[2] = { smu + 2 * ABUF, smu + 2 * ABUF + BBUF };

    const int bh = blockIdx.y;
    const int b = bh >> 3, h = bh & 7;
    const int i0 = blockIdx.x << 7;
    const int tid = threadIdx.x;
    const int wid = tid >> 5, lid = tid & 31;

    const int arow = tid >> 1;
    const int akb  = (tid & 1) * 16;
    const int akb2 = (tid & 1) * 8;
    const int jp   = tid >> 4;
    const int d0   = (tid & 15) * 4;
    const __half* gA = attn + ((size_t)bh << 20) + ((size_t)(i0 + arow) << 10) + akb;
    const __half* gV = qkv + 2 * HD + h * DHH + d0;

    float acc[2][4][4];
#pragma unroll
    for (int mt = 0; mt < 2; mt++)
#pragma unroll
        for (int nt = 0; nt < 4; nt++)
#pragma unroll
            for (int q = 0; q < 4; q++) acc[mt][nt][q] = 0.f;

    uint32_t ar2[8], bv2[4];
    auto loadA = [&](const __half* src) {
        uint4 r0 = *(const uint4*)src;
        uint4 r1 = *(const uint4*)(src + 8);
        ar2[0] = r0.x; ar2[1] = r0.y; ar2[2] = r0.z; ar2[3] = r0.w;
        ar2[4] = r1.x; ar2[5] = r1.y; ar2[6] = r1.z; ar2[7] = r1.w;
    };
    auto loadV = [&](int jbase) {
        const __half* v0 = gV + (size_t)(b * NN + jbase + 2 * jp) * (3 * HD);
        const __half* v1 = v0 + 3 * HD;
        uint2 a = *(const uint2*)v0;
        uint2 c = *(const uint2*)v1;
        __half2 a0 = *(__half2*)&a.x, a1 = *(__half2*)&a.y;
        __half2 c0 = *(__half2*)&c.x, c1 = *(__half2*)&c.y;
        __half2 r0 = __halves2half2(__low2half(a0),  __low2half(c0));
        __half2 r1 = __halves2half2(__high2half(a0), __high2half(c0));
        __half2 r2 = __halves2half2(__low2half(a1),  __low2half(c1));
        __half2 r3 = __halves2half2(__high2half(a1), __high2half(c1));
        bv2[0] = *(uint32_t*)&r0; bv2[1] = *(uint32_t*)&r1;
        bv2[2] = *(uint32_t*)&r2; bv2[3] = *(uint32_t*)&r3;
    };

    const int nch = NN >> 5;
    loadA(gA);
    loadV(0);
#pragma unroll
    for (int i = 0; i < 8; i++) sA[0][(akb2 + i) * AST + arow] = ar2[i];
    *(uint4*)&sB[0][jp * BST + d0] = make_uint4(bv2[0], bv2[1], bv2[2], bv2[3]);
    __syncthreads();

    const int wm = (wid & 3) * 32;
    const int wn = (wid >> 2) * 32;
    const int g  = lid >> 2;
    const int tg = lid & 3;

    int p = 0;
    for (int c = 0; c < nch; c++) {
        if (c + 1 < nch) {
            loadA(gA + (size_t)(c + 1) * 32);
            loadV((c + 1) * 32);
        }
        const uint32_t* cA = sA[p];
        const uint32_t* cB = sB[p];
#pragma unroll
        for (int s = 0; s < 2; s++) {
            const int k0 = s * 8;
            uint32_t afr[2][4];
#pragma unroll
            for (int mt = 0; mt < 2; mt++) {
                int row = wm + mt * 16 + g;
                afr[mt][0] = cA[(k0 + tg)     * AST + row];
                afr[mt][1] = cA[(k0 + tg)     * AST + row + 8];
                afr[mt][2] = cA[(k0 + tg + 4) * AST + row];
                afr[mt][3] = cA[(k0 + tg + 4) * AST + row + 8];
            }
            uint32_t bfr[4][2];
#pragma unroll
            for (int nt = 0; nt < 4; nt++) {
                int cn = wn + nt * 8 + g;
                bfr[nt][0] = cB[(k0 + tg)     * BST + cn];
                bfr[nt][1] = cB[(k0 + tg + 4) * BST + cn];
            }
#pragma unroll
            for (int mt = 0; mt < 2; mt++)
#pragma unroll
                for (int nt = 0; nt < 4; nt++)
                    mma16(acc[mt][nt], afr[mt], bfr[nt]);
        }
        if (c + 1 < nch) {
            uint32_t* dA = sA[1 - p];
            uint32_t* dB = sB[1 - p];
#pragma unroll
            for (int i = 0; i < 8; i++) dA[(akb2 + i) * AST + arow] = ar2[i];
            *(uint4*)&dB[jp * BST + d0] = make_uint4(bv2[0], bv2[1], bv2[2], bv2[3]);
        }
        __syncthreads();
        p ^= 1;
    }

#pragma unroll
    for (int mt = 0; mt < 2; mt++) {
#pragma unroll
        for (int rh = 0; rh < 2; rh++) {
            int row = i0 + wm + mt * 16 + g + rh * 8;
#pragma unroll
            for (int nt = 0; nt < 4; nt++) {
                int col = wn + nt * 8 + tg * 2;
                __half2 h2 = __floats2half2_rn(acc[mt][nt][rh * 2 + 0], acc[mt][nt][rh * 2 + 1]);
                *(__half2*)(av + (size_t)(b * NN + row) * HD + h * DHH + col) = h2;
            }
        }
    }
}

// ---------------- host orchestration ----------------
extern "C" void kernel_launch(void* const* d_in, const int* in_sizes, int n_in,
                              void* d_out, int out_size) {
    (void)in_sizes; (void)n_in; (void)out_size;
    const float* in_x   = (const float*)d_in[0];
    const float* r_t    = (const float*)d_in[1];
    const float* r_c    = (const float*)d_in[2];
    const float* r_p    = (const float*)d_in[3];
    const float* bias_pf= (const float*)d_in[4];
    const float* ln1_g  = (const float*)d_in[5];
    const float* ln1_b  = (const float*)d_in[6];
    const float* w_qkv  = (const float*)d_in[7];
    const float* w_out  = (const float*)d_in[8];
    const float* b_out  = (const float*)d_in[9];
    const float* w_kt   = (const float*)d_in[10];
    const float* w_kc   = (const float*)d_in[11];
    const float* w_kp   = (const float*)d_in[12];
    const float* ln2_g  = (const float*)d_in[13];
    const float* ln2_b  = (const float*)d_in[14];
    const float* w_ff1  = (const float*)d_in[15];
    const float* b_ff1  = (const float*)d_in[16];
    const float* w_ff2  = (const float*)d_in[17];
    const float* b_ff2  = (const float*)d_in[18];

    float* out_x    = (float*)d_out;
    float* out_attn = out_x + (size_t)BB * NN * DD;

    float *p_x;
    __half *p_xn, *p_qkv, *p_ws, *p_av, *p_h1;
    __half *p_AC, *p_BD, *p_attn, *p_rcat;
    __half *p_wqkvT, *p_wcatT, *p_woutT, *p_wff1T, *p_wff2T;
    cudaGetSymbolAddress((void**)&p_x,   g_x);
    cudaGetSymbolAddress((void**)&p_xn,  g_xn);
    cudaGetSymbolAddress((void**)&p_qkv, g_qkv);
    cudaGetSymbolAddress((void**)&p_ws,  g_ws);
    cudaGetSymbolAddress((void**)&p_AC,  g_AC16);
    cudaGetSymbolAddress((void**)&p_BD,  g_BD16);
    cudaGetSymbolAddress((void**)&p_attn,g_attn16);
    cudaGetSymbolAddress((void**)&p_av,  g_av);
    cudaGetSymbolAddress((void**)&p_h1,  g_h1);
    cudaGetSymbolAddress((void**)&p_rcat, g_rcat);
    cudaGetSymbolAddress((void**)&p_wqkvT, g_wqkvT);
    cudaGetSymbolAddress((void**)&p_wcatT, g_wcatT);
    cudaGetSymbolAddress((void**)&p_woutT, g_woutT);
    cudaGetSymbolAddress((void**)&p_wff1T, g_wff1T);
    cudaGetSymbolAddress((void**)&p_wff2T, g_wff2T);

    cudaFuncSetAttribute((const void*)mgemm<__half,false,false,false>, cudaFuncAttributeMaxDynamicSharedMemorySize, MG_SMEM);
    cudaFuncSetAttribute((const void*)mgemm<float,true,true,false>,    cudaFuncAttributeMaxDynamicSharedMemorySize, MG_SMEM);
    cudaFuncSetAttribute((const void*)mgemm<__half,true,false,true>,   cudaFuncAttributeMaxDynamicSharedMemorySize, MG_SMEM);
    cudaFuncSetAttribute((const void*)scores_mma, cudaFuncAttributeMaxDynamicSharedMemorySize, SC_SMEM);
    cudaFuncSetAttribute((const void*)attnv_mma,  cudaFuncAttributeMaxDynamicSharedMemorySize, MG_SMEM);

    const int M = BB * NN;   // 2048
    dim3 t32(32, 8);

    // one-time packing / transposes (fp32 -> fp16)
    pack_r_kernel<<<(BB * NN * 3 * DD) / 256, 256>>>(r_t, r_c, r_p);
    pack_pf_kernel<<<2, 256>>>(bias_pf);
    transpose_batch<<<dim3(48, 16, DEPTH), t32>>>(w_qkv, p_wqkvT, DD, 3*HD, DD, 0, (size_t)3*HD*DD);
    transpose_batch<<<dim3(16, 16, DEPTH), t32>>>(w_kt, p_wcatT, DD, HD, 3*DD, 0,      (size_t)HD*3*DD);
    transpose_batch<<<dim3(16, 16, DEPTH), t32>>>(w_kc, p_wcatT, DD, HD, 3*DD, DD,     (size_t)HD*3*DD);
    transpose_batch<<<dim3(16, 16, DEPTH), t32>>>(w_kp, p_wcatT, DD, HD, 3*DD, 2*DD,   (size_t)HD*3*DD);
    transpose_batch<<<dim3(16, 16, DEPTH), t32>>>(w_out, p_woutT, HD, DD, HD, 0,       (size_t)DD*HD);
    transpose_batch<<<dim3(64, 16, DEPTH), t32>>>(w_ff1, p_wff1T, DD, FFD, DD, 0,      (size_t)FFD*DD);
    transpose_batch<<<dim3(16, 64, DEPTH), t32>>>(w_ff2, p_wff2T, FFD, DD, FFD, 0,     (size_t)DD*FFD);

    for (int l = 0; l < DEPTH; l++) {
        const float* xin = (l == 0) ? in_x : p_x;   // residual stream source
        ln_kernel<<<M, 128>>>(xin, ln1_g + l * DD, ln1_b + l * DD, p_xn);
        // qkv = xn @ w_qkv[l]  (fp16 out)
        mgemm<__half,false,false,false><<<dim3(24, 16), 256, MG_SMEM>>>(
            p_xn, p_wqkvT + (size_t)l * 3*HD * DD, p_qkv, 3 * HD, DD, nullptr, nullptr);
        // ws = [r_t|r_c|r_p] @ [w_kt; w_kc; w_kp]  (fp16 out)
        mgemm<__half,false,false,false><<<dim3(8, 16), 256, MG_SMEM>>>(
            p_rcat, p_wcatT + (size_t)l * HD * 3*DD, p_ws, HD, 3 * DD, nullptr, nullptr);
        // AC / BD batched scores
        scores_mma<<<dim3(16, 16, BB * HH), 256, SC_SMEM>>>(p_qkv, p_ws, p_AC, p_BD);
        // dots + rel_shift + softmax over heads
        if (l == DEPTH - 1)
            softmax16<true><<<(BB * NN * NN / 2) / 256, 256>>>(p_AC, p_BD, p_attn, out_attn);
        else
            softmax16<false><<<(BB * NN * NN / 2) / 256, 256>>>(p_AC, p_BD, p_attn, nullptr);
        // attn @ v (fp16 out)
        attnv_mma<<<dim3(8, BB * HH), 256, MG_SMEM>>>(p_attn, p_qkv, p_av);
        // out projection + bias + residual (fp32 residual stream)
        mgemm<float,true,true,false><<<dim3(8, 16), 256, MG_SMEM>>>(
            p_av, p_woutT + (size_t)l * DD * HD, p_x, DD, HD, b_out + l * DD, xin);
        ln_kernel<<<M, 128>>>(p_x, ln2_g + l * DD, ln2_b + l * DD, p_xn);
        // FF1 + bias + exact GELU (fp16 out)
        mgemm<__half,true,false,true><<<dim3(32, 16), 256, MG_SMEM>>>(
            p_xn, p_wff1T + (size_t)l * FFD * DD, p_h1, FFD, DD, b_ff1 + l * FFD, nullptr);
        // FF2 + bias + residual; last layer writes straight to d_out
        float* xdst = (l == DEPTH - 1) ? out_x : p_x;
        mgemm<float,true,true,false><<<dim3(8, 16), 256, MG_SMEM>>>(
            p_h1, p_wff2T + (size_t)l * DD * FFD, xdst, DD, FFD, b_ff2 + l * DD, p_x);
    }
}

// round 13
// speedup vs baseline: 2.5829x; 1.2471x over previous
#include <cuda_runtime.h>
#include <cuda_fp16.h>
#include <math.h>
#include <stdint.h>

#define BB 2
#define NN 1024
#define DD 512
#define HH 8
#define DHH 64
#define HD 512
#define FFD 2048
#define DEPTH 4

// ---------------- device scratch ----------------
__device__ float  g_x  [BB*NN*DD];              // fp32 residual stream
__device__ __half g_xn [BB*NN*DD];
__device__ __half g_qkv[BB*NN*3*HD];
__device__ __half g_ws [BB*NN*HD];
__device__ __half g_AC16 [(size_t)BB*HH*NN*NN];
__device__ __half g_BD16 [(size_t)BB*HH*NN*NN];
__device__ __half g_attn16[(size_t)BB*HH*NN*NN];
__device__ __half g_av [BB*NN*HD];
__device__ __half g_h1 [BB*NN*FFD];
__device__ __half g_rcat [BB*NN * 3*DD];
__device__ __half g_pf16 [HD];
__device__ __half g_wqkvT[DEPTH * 3*HD * DD];
__device__ __half g_wcatT[DEPTH * HD * 3*DD];
__device__ __half g_woutT[DEPTH * DD * HD];
__device__ __half g_wff1T[DEPTH * FFD * DD];
__device__ __half g_wff2T[DEPTH * DD * FFD];

__device__ __forceinline__ uint32_t f22h(float a, float b) {
    __half2 h = __floats2half2_rn(a, b);
    return *reinterpret_cast<uint32_t*>(&h);
}
__device__ __forceinline__ uint32_t hadd2u(uint32_t a, uint32_t b) {
    __half2 r = __hadd2(*(__half2*)&a, *(__half2*)&b);
    return *reinterpret_cast<uint32_t*>(&r);
}
__device__ __forceinline__ void mma16(float* d, const uint32_t* a, const uint32_t* b) {
    asm volatile("mma.sync.aligned.m16n8k16.row.col.f32.f16.f16.f32 "
        "{%0,%1,%2,%3}, {%4,%5,%6,%7}, {%8,%9}, {%0,%1,%2,%3};"
        : "+f"(d[0]), "+f"(d[1]), "+f"(d[2]), "+f"(d[3])
        : "r"(a[0]), "r"(a[1]), "r"(a[2]), "r"(a[3]), "r"(b[0]), "r"(b[1]));
}
#define LDSM4(R0,R1,R2,R3,ADDR) \
    asm volatile("ldmatrix.sync.aligned.m8n8.x4.shared.b16 {%0,%1,%2,%3}, [%4];" \
        : "=r"(R0), "=r"(R1), "=r"(R2), "=r"(R3) : "r"(ADDR))

// ---------------- packing ----------------
__global__ void pack_r_kernel(const float* __restrict__ rt, const float* __restrict__ rc,
                              const float* __restrict__ rp) {
    int idx = blockIdx.x * 256 + threadIdx.x;
    int m = idx / (3 * DD), k = idx % (3 * DD);
    float v;
    if (k < DD)            v = rt[m * DD + k];
    else if (k < 2 * DD)   v = rc[m * DD + k - DD];
    else                   v = rp[m * DD + k - 2 * DD];
    g_rcat[idx] = __float2half(v);
}
__global__ void pack_pf_kernel(const float* __restrict__ pf) {
    int i = blockIdx.x * 256 + threadIdx.x;
    if (i < HD) g_pf16[i] = __float2half(pf[i]);
}

// ---------------- weight transpose: src [R,C] fp32 -> dst [C, dstStride] fp16 ----------------
__global__ void transpose_batch(const float* __restrict__ src, __half* __restrict__ dst,
                                int R, int C, int dstStride, int colBase, size_t dstLayer) {
    __shared__ float t[32][33];
    size_t soff = (size_t)blockIdx.z * R * C;
    size_t doff = (size_t)blockIdx.z * dstLayer;
    int c0 = blockIdx.x * 32, r0 = blockIdx.y * 32;
    int x = threadIdx.x, y = threadIdx.y;
#pragma unroll
    for (int i = 0; i < 32; i += 8)
        t[y + i][x] = src[soff + (size_t)(r0 + y + i) * C + c0 + x];
    __syncthreads();
#pragma unroll
    for (int i = 0; i < 32; i += 8)
        dst[doff + (size_t)(c0 + y + i) * dstStride + colBase + r0 + x] = __float2half(t[x][y + i]);
}

// ---------------- layernorm: fp32 in -> fp16 out ----------------
__global__ void ln_kernel(const float* __restrict__ x, const float* __restrict__ g,
                          const float* __restrict__ bta, __half* __restrict__ y) {
    __shared__ float red[128];
    int row = blockIdx.x;
    int tid = threadIdx.x;
    const float4* xr = (const float4*)(x + (size_t)row * DD);
    float4 v = xr[tid];
    red[tid] = v.x + v.y + v.z + v.w;
    __syncthreads();
    for (int o = 64; o > 0; o >>= 1) { if (tid < o) red[tid] += red[tid + o]; __syncthreads(); }
    float mean = red[0] * (1.0f / DD);
    __syncthreads();
    float dx = v.x - mean, dy = v.y - mean, dz = v.z - mean, dw = v.w - mean;
    red[tid] = dx*dx + dy*dy + dz*dz + dw*dw;
    __syncthreads();
    for (int o = 64; o > 0; o >>= 1) { if (tid < o) red[tid] += red[tid + o]; __syncthreads(); }
    float rstd = rsqrtf(red[0] * (1.0f / DD) + 1e-5f);
    float4 gv = ((const float4*)g)[tid];
    float4 bv = ((const float4*)bta)[tid];
    uint2 o2;
    o2.x = f22h(dx * rstd * gv.x + bv.x, dy * rstd * gv.y + bv.y);
    o2.y = f22h(dz * rstd * gv.z + bv.z, dw * rstd * gv.w + bv.w);
    *(uint2*)(y + (size_t)row * DD + tid * 4) = o2;
}

__device__ __forceinline__ float gelu_exact(float v) {
    return 0.5f * v * (1.0f + erff(v * 0.70710678118654752f));
}

// ---------------- fp16 mma GEMM with ldmatrix: C[M,Nc] = A[M,K] @ Bt[Nc,K]^T ----------------
// 128x64 CTA tile, 256 threads, BK=32. A row-major 80B stride, B row-major 80B stride.
#define A_STRIDE 80
#define B_STRIDE 80
#define A_BYTES (128 * A_STRIDE)          // 10240
#define B_BYTES (64 * B_STRIDE)           // 5120
#define MG_SMEM (2 * (A_BYTES + B_BYTES)) // 30720

template<class CT, bool BIAS, bool RES, bool GELU_>
__global__ void __launch_bounds__(256, 2)
mgemm(const __half* __restrict__ A, const __half* __restrict__ Bt, CT* __restrict__ C,
      int Nc, int K, const float* __restrict__ bias, const float* __restrict__ res) {
    extern __shared__ char smc[];
    const uint32_t sbase = (uint32_t)__cvta_generic_to_shared(smc);
    const uint32_t aOff[2] = { 0, A_BYTES };
    const uint32_t bOff[2] = { 2 * A_BYTES, 2 * A_BYTES + B_BYTES };

    const int tid = threadIdx.x;
    const int wid = tid >> 5, lid = tid & 31;
    const int row0 = blockIdx.y * 128;
    const int col0 = blockIdx.x * 64;

    const int arow = tid >> 1;
    const int aO   = (tid & 1) * 32;     // byte offset within row
    const int brow = tid >> 2;
    const int bO   = (tid & 3) * 16;
    const __half* gA = A  + (size_t)(row0 + arow) * K + (tid & 1) * 16;
    const __half* gB = Bt + (size_t)(col0 + brow) * K + (tid & 3) * 8;

    float acc[2][4][4];
#pragma unroll
    for (int mt = 0; mt < 2; mt++)
#pragma unroll
        for (int nt = 0; nt < 4; nt++)
#pragma unroll
            for (int r = 0; r < 4; r++) acc[mt][nt][r] = 0.f;

    uint4 ua, ub, vb;
    auto loadA = [&](const __half* src) { ua = *(const uint4*)src; ub = *(const uint4*)(src + 8); };
    auto loadB = [&](const __half* src) { vb = *(const uint4*)src; };
    auto stA = [&](int p) {
        char* d = smc + aOff[p] + arow * A_STRIDE + aO;
        *(uint4*)d = ua; *(uint4*)(d + 16) = ub;
    };
    auto stB = [&](int p) {
        *(uint4*)(smc + bOff[p] + brow * B_STRIDE + bO) = vb;
    };

    const int nch = K >> 5;
    loadA(gA); loadB(gB);
    stA(0); stB(0);
    __syncthreads();

    const int wm = (wid & 3) * 32;
    const int wn = (wid >> 2) * 32;
    // ldmatrix lane addressing
    const uint32_t aLane = (lid & 15) * A_STRIDE + (lid >> 4) * 16;
    const uint32_t bLane = (wn + lid) * B_STRIDE;

    int p = 0;
    for (int c = 0; c < nch; c++) {
        if (c + 1 < nch) {
            loadA(gA + (size_t)(c + 1) * 32);
            loadB(gB + (size_t)(c + 1) * 32);
        }
        const uint32_t aS = sbase + aOff[p];
        const uint32_t bS = sbase + bOff[p];
#pragma unroll
        for (int s = 0; s < 2; s++) {
            const uint32_t kO = s * 32;
            uint32_t afr[2][4];
#pragma unroll
            for (int mt = 0; mt < 2; mt++)
                LDSM4(afr[mt][0], afr[mt][1], afr[mt][2], afr[mt][3],
                      aS + (wm + mt * 16) * A_STRIDE + aLane + kO);
            uint32_t b0[4], b1[4];
            LDSM4(b0[0], b0[1], b0[2], b0[3], bS + bLane + kO);
            LDSM4(b1[0], b1[1], b1[2], b1[3], bS + bLane + kO + 16);
#pragma unroll
            for (int mt = 0; mt < 2; mt++)
#pragma unroll
                for (int nt = 0; nt < 4; nt++) {
                    uint32_t bfr[2] = { b0[nt], b1[nt] };
                    mma16(acc[mt][nt], afr[mt], bfr);
                }
        }
        if (c + 1 < nch) { stA(1 - p); stB(1 - p); }
        __syncthreads();
        p ^= 1;
    }

    const int g  = lid >> 2;
    const int tg = lid & 3;
#pragma unroll
    for (int mt = 0; mt < 2; mt++) {
#pragma unroll
        for (int rh = 0; rh < 2; rh++) {
            int row = row0 + wm + mt * 16 + g + rh * 8;
#pragma unroll
            for (int nt = 0; nt < 4; nt++) {
                int col = col0 + wn + nt * 8 + tg * 2;
                size_t idx = (size_t)row * Nc + col;
                float v0 = acc[mt][nt][rh * 2 + 0];
                float v1 = acc[mt][nt][rh * 2 + 1];
                if (BIAS)  { float2 bv = *(const float2*)(bias + col); v0 += bv.x; v1 += bv.y; }
                if (RES)   { float2 rv = *(const float2*)(res + idx); v0 += rv.x; v1 += rv.y; }
                if (GELU_) { v0 = gelu_exact(v0); v1 = gelu_exact(v1); }
                if constexpr (sizeof(CT) == 2) {
                    *(__half2*)((__half*)C + idx) = __floats2half2_rn(v0, v1);
                } else {
                    *(float2*)((float*)C + idx) = make_float2(v0, v1);
                }
            }
        }
    }
}

// ---------------- scores via fp16 mma + ldmatrix (per b,h; K=64) ----------------
#define SC_STRIDE 144
#define SC_MAT (64 * SC_STRIDE)           // 9216 B
#define SC_SMEM (3 * SC_MAT)              // 27648 B
__global__ void __launch_bounds__(256, 4)
scores_mma(const __half* __restrict__ qkv, const __half* __restrict__ ws,
           __half* __restrict__ AC, __half* __restrict__ BD) {
    extern __shared__ char smc[];
    const uint32_t sbase = (uint32_t)__cvta_generic_to_shared(smc);
    const int bh = blockIdx.z;
    const int b = bh >> 3, h = bh & 7;
    const int i0 = blockIdx.y << 6, j0 = blockIdx.x << 6;
    const int tid = threadIdx.x;

    const int r  = tid >> 2;
    const int d0 = (tid & 3) << 4;     // half base
    const int rowO = r * SC_STRIDE + (tid & 3) * 32;
    const __half* qb = qkv + (size_t)(b * NN + i0 + r) * (3 * HD) + h * DHH + d0;
    const __half* kb = qkv + (size_t)(b * NN + j0 + r) * (3 * HD) + HD + h * DHH + d0;
    const __half* wb = ws  + (size_t)(b * NN + j0 + r) * HD + h * DHH + d0;
    const __half* pf = g_pf16 + h * DHH + d0;
    {
        uint4 q0 = *(const uint4*)qb, q1 = *(const uint4*)(qb + 8);
        uint4 p0 = *(const uint4*)pf, p1 = *(const uint4*)(pf + 8);
        q0.x = hadd2u(q0.x, p0.x); q0.y = hadd2u(q0.y, p0.y);
        q0.z = hadd2u(q0.z, p0.z); q0.w = hadd2u(q0.w, p0.w);
        q1.x = hadd2u(q1.x, p1.x); q1.y = hadd2u(q1.y, p1.y);
        q1.z = hadd2u(q1.z, p1.z); q1.w = hadd2u(q1.w, p1.w);
        *(uint4*)(smc + rowO)      = q0;
        *(uint4*)(smc + rowO + 16) = q1;
        uint4 k0 = *(const uint4*)kb, k1 = *(const uint4*)(kb + 8);
        *(uint4*)(smc + SC_MAT + rowO)      = k0;
        *(uint4*)(smc + SC_MAT + rowO + 16) = k1;
        uint4 w0 = *(const uint4*)wb, w1 = *(const uint4*)(wb + 8);
        *(uint4*)(smc + 2 * SC_MAT + rowO)      = w0;
        *(uint4*)(smc + 2 * SC_MAT + rowO + 16) = w1;
    }
    __syncthreads();

    const int wid = tid >> 5, lid = tid & 31;
    const int grp = wid >> 2;
    const int w2  = wid & 3;
    const int wm  = (w2 & 1) * 32;
    const int wn  = (w2 >> 1) * 32;
    const uint32_t aS = sbase;                         // Q
    const uint32_t bS = sbase + (grp ? 2 * SC_MAT : SC_MAT);  // Ws or Ks
    const uint32_t aLane = (lid & 15) * SC_STRIDE + (lid >> 4) * 16;
    const uint32_t bLane = (wn + lid) * SC_STRIDE;

    float acc[2][4][4];
#pragma unroll
    for (int mt = 0; mt < 2; mt++)
#pragma unroll
        for (int nt = 0; nt < 4; nt++)
#pragma unroll
            for (int q = 0; q < 4; q++) acc[mt][nt][q] = 0.f;

#pragma unroll
    for (int s = 0; s < 4; s++) {
        const uint32_t kO = s * 32;
        uint32_t afr[2][4];
#pragma unroll
        for (int mt = 0; mt < 2; mt++)
            LDSM4(afr[mt][0], afr[mt][1], afr[mt][2], afr[mt][3],
                  aS + (wm + mt * 16) * SC_STRIDE + aLane + kO);
        uint32_t b0[4], b1[4];
        LDSM4(b0[0], b0[1], b0[2], b0[3], bS + bLane + kO);
        LDSM4(b1[0], b1[1], b1[2], b1[3], bS + bLane + kO + 16);
#pragma unroll
        for (int mt = 0; mt < 2; mt++)
#pragma unroll
            for (int nt = 0; nt < 4; nt++) {
                uint32_t bfr[2] = { b0[nt], b1[nt] };
                mma16(acc[mt][nt], afr[mt], bfr);
            }
    }

    __half* Out = grp ? BD : AC;
    const size_t base = ((size_t)bh << 20);
    const int g = lid >> 2, tg = lid & 3;
#pragma unroll
    for (int mt = 0; mt < 2; mt++) {
#pragma unroll
        for (int rh = 0; rh < 2; rh++) {
            int i = i0 + wm + mt * 16 + g + rh * 8;
#pragma unroll
            for (int nt = 0; nt < 4; nt++) {
                int j = j0 + wn + nt * 8 + tg * 2;
                __half2 h2 = __floats2half2_rn(acc[mt][nt][rh * 2 + 0], acc[mt][nt][rh * 2 + 1]);
                *(__half2*)(Out + base + ((size_t)i << 10) + j) = h2;
            }
        }
    }
}

// ---------------- dots + rel_shift + softmax over heads (fp16 in/out) ----------------
template<bool LAST>
__global__ void softmax16(const __half* __restrict__ AC, const __half* __restrict__ BD,
                          __half* __restrict__ attn, float* __restrict__ out_attn) {
    int gid = blockIdx.x * 256 + threadIdx.x;
    int b = gid >> 19;
    int ijp = gid & ((1 << 19) - 1);
    int ij = ijp << 1;
    int i = ij >> 10, j = ij & 1023;

    int m0 = (i + 1) * NN + j;
    int i2a = m0 / (NN + 1);
    int ka  = m0 - i2a * (NN + 1);
    int i2b, kb;
    if (ka == NN) { i2b = i2a + 1; kb = 0; }
    else          { i2b = i2a;     kb = ka + 1; }

    size_t pb = ((size_t)(b * HH)) << 20;
    size_t sa = ((size_t)i2a << 10) + (ka - 1);
    size_t sb = ((size_t)i2b << 10) + (kb - 1);

    float va[8], vb[8];
#pragma unroll
    for (int h = 0; h < 8; h++) {
        size_t hp = pb + ((size_t)h << 20);
        __half2 ac2 = *(const __half2*)(AC + hp + ij);
        float bda = (ka != 0) ? __half2float(BD[hp + sa]) : 0.f;
        float bdb = (kb != 0) ? __half2float(BD[hp + sb]) : 0.f;
        va[h] = (__low2float(ac2)  + bda * (1.0f / 3.0f)) * 0.125f;
        vb[h] = (__high2float(ac2) + bdb * (1.0f / 3.0f)) * 0.125f;
    }
    float mxa = va[0], mxb = vb[0];
#pragma unroll
    for (int h = 1; h < 8; h++) { mxa = fmaxf(mxa, va[h]); mxb = fmaxf(mxb, vb[h]); }
    float sa_ = 0.f, sb_ = 0.f;
#pragma unroll
    for (int h = 0; h < 8; h++) {
        va[h] = __expf(va[h] - mxa); sa_ += va[h];
        vb[h] = __expf(vb[h] - mxb); sb_ += vb[h];
    }
    float ia = 1.0f / sa_, ib = 1.0f / sb_;
#pragma unroll
    for (int h = 0; h < 8; h++) {
        size_t hp = pb + ((size_t)h << 20);
        float oa = va[h] * ia, ob = vb[h] * ib;
        *(__half2*)(attn + hp + ij) = __floats2half2_rn(oa, ob);
        if (LAST) {
            float2 o2 = make_float2(oa, ob);
            *(float2*)(out_attn + hp + ij) = o2;
        }
    }
}

// ---------------- attn(fp16) @ v(fp16) -> av(fp16): ldmatrix A, legacy B ----------------
#define VBST 72                            // u32 stride for V buffer
#define VB_BYTES (16 * VBST * 4)           // 4608 B
#define AV_SMEM (2 * A_BYTES + 2 * VB_BYTES)  // 29696 B
__global__ void __launch_bounds__(256, 2)
attnv_mma(const __half* __restrict__ attn, const __half* __restrict__ qkv,
          __half* __restrict__ av) {
    extern __shared__ char smc[];
    const uint32_t sbase = (uint32_t)__cvta_generic_to_shared(smc);
    const uint32_t aOff[2] = { 0, A_BYTES };
    uint32_t* vB[2] = { (uint32_t*)(smc + 2 * A_BYTES), (uint32_t*)(smc + 2 * A_BYTES + VB_BYTES) };

    const int bh = blockIdx.y;
    const int b = bh >> 3, h = bh & 7;
    const int i0 = blockIdx.x << 7;
    const int tid = threadIdx.x;
    const int wid = tid >> 5, lid = tid & 31;

    const int arow = tid >> 1;
    const int aO   = (tid & 1) * 32;
    const int jp   = tid >> 4;
    const int d0   = (tid & 15) * 4;
    const __half* gA = attn + ((size_t)bh << 20) + ((size_t)(i0 + arow) << 10) + (tid & 1) * 16;
    const __half* gV = qkv + 2 * HD + h * DHH + d0;

    float acc[2][4][4];
#pragma unroll
    for (int mt = 0; mt < 2; mt++)
#pragma unroll
        for (int nt = 0; nt < 4; nt++)
#pragma unroll
            for (int q = 0; q < 4; q++) acc[mt][nt][q] = 0.f;

    uint4 ua, ub;
    uint32_t bv2[4];
    auto loadA = [&](const __half* src) { ua = *(const uint4*)src; ub = *(const uint4*)(src + 8); };
    auto loadV = [&](int jbase) {
        const __half* v0 = gV + (size_t)(b * NN + jbase + 2 * jp) * (3 * HD);
        const __half* v1 = v0 + 3 * HD;
        uint2 a = *(const uint2*)v0;
        uint2 c = *(const uint2*)v1;
        __half2 a0 = *(__half2*)&a.x, a1 = *(__half2*)&a.y;
        __half2 c0 = *(__half2*)&c.x, c1 = *(__half2*)&c.y;
        __half2 r0 = __halves2half2(__low2half(a0),  __low2half(c0));
        __half2 r1 = __halves2half2(__high2half(a0), __high2half(c0));
        __half2 r2 = __halves2half2(__low2half(a1),  __low2half(c1));
        __half2 r3 = __halves2half2(__high2half(a1), __high2half(c1));
        bv2[0] = *(uint32_t*)&r0; bv2[1] = *(uint32_t*)&r1;
        bv2[2] = *(uint32_t*)&r2; bv2[3] = *(uint32_t*)&r3;
    };
    auto stA = [&](int p) {
        char* d = smc + aOff[p] + arow * A_STRIDE + aO;
        *(uint4*)d = ua; *(uint4*)(d + 16) = ub;
    };

    const int nch = NN >> 5;
    loadA(gA); loadV(0);
    stA(0);
    *(uint4*)&vB[0][jp * VBST + d0] = make_uint4(bv2[0], bv2[1], bv2[2], bv2[3]);
    __syncthreads();

    const int wm = (wid & 3) * 32;
    const int wn = (wid >> 2) * 32;
    const int g  = lid >> 2;
    const int tg = lid & 3;
    const uint32_t aLane = (lid & 15) * A_STRIDE + (lid >> 4) * 16;

    int p = 0;
    for (int c = 0; c < nch; c++) {
        if (c + 1 < nch) {
            loadA(gA + (size_t)(c + 1) * 32);
            loadV((c + 1) * 32);
        }
        const uint32_t aS = sbase + aOff[p];
        const uint32_t* cB = vB[p];
#pragma unroll
        for (int s = 0; s < 2; s++) {
            const int k0 = s * 8;
            uint32_t afr[2][4];
#pragma unroll
            for (int mt = 0; mt < 2; mt++)
                LDSM4(afr[mt][0], afr[mt][1], afr[mt][2], afr[mt][3],
                      aS + (wm + mt * 16) * A_STRIDE + aLane + s * 32);
            uint32_t bfr[4][2];
#pragma unroll
            for (int nt = 0; nt < 4; nt++) {
                int cn = wn + nt * 8 + g;
                bfr[nt][0] = cB[(k0 + tg)     * VBST + cn];
                bfr[nt][1] = cB[(k0 + tg + 4) * VBST + cn];
            }
#pragma unroll
            for (int mt = 0; mt < 2; mt++)
#pragma unroll
                for (int nt = 0; nt < 4; nt++)
                    mma16(acc[mt][nt], afr[mt], bfr[nt]);
        }
        if (c + 1 < nch) {
            stA(1 - p);
            *(uint4*)&vB[1 - p][jp * VBST + d0] = make_uint4(bv2[0], bv2[1], bv2[2], bv2[3]);
        }
        __syncthreads();
        p ^= 1;
    }

#pragma unroll
    for (int mt = 0; mt < 2; mt++) {
#pragma unroll
        for (int rh = 0; rh < 2; rh++) {
            int row = i0 + wm + mt * 16 + g + rh * 8;
#pragma unroll
            for (int nt = 0; nt < 4; nt++) {
                int col = wn + nt * 8 + tg * 2;
                __half2 h2 = __floats2half2_rn(acc[mt][nt][rh * 2 + 0], acc[mt][nt][rh * 2 + 1]);
                *(__half2*)(av + (size_t)(b * NN + row) * HD + h * DHH + col) = h2;
            }
        }
    }
}

// ---------------- host orchestration ----------------
extern "C" void kernel_launch(void* const* d_in, const int* in_sizes, int n_in,
                              void* d_out, int out_size) {
    (void)in_sizes; (void)n_in; (void)out_size;
    const float* in_x   = (const float*)d_in[0];
    const float* r_t    = (const float*)d_in[1];
    const float* r_c    = (const float*)d_in[2];
    const float* r_p    = (const float*)d_in[3];
    const float* bias_pf= (const float*)d_in[4];
    const float* ln1_g  = (const float*)d_in[5];
    const float* ln1_b  = (const float*)d_in[6];
    const float* w_qkv  = (const float*)d_in[7];
    const float* w_out  = (const float*)d_in[8];
    const float* b_out  = (const float*)d_in[9];
    const float* w_kt   = (const float*)d_in[10];
    const float* w_kc   = (const float*)d_in[11];
    const float* w_kp   = (const float*)d_in[12];
    const float* ln2_g  = (const float*)d_in[13];
    const float* ln2_b  = (const float*)d_in[14];
    const float* w_ff1  = (const float*)d_in[15];
    const float* b_ff1  = (const float*)d_in[16];
    const float* w_ff2  = (const float*)d_in[17];
    const float* b_ff2  = (const float*)d_in[18];

    float* out_x    = (float*)d_out;
    float* out_attn = out_x + (size_t)BB * NN * DD;

    float *p_x;
    __half *p_xn, *p_qkv, *p_ws, *p_av, *p_h1;
    __half *p_AC, *p_BD, *p_attn, *p_rcat;
    __half *p_wqkvT, *p_wcatT, *p_woutT, *p_wff1T, *p_wff2T;
    cudaGetSymbolAddress((void**)&p_x,   g_x);
    cudaGetSymbolAddress((void**)&p_xn,  g_xn);
    cudaGetSymbolAddress((void**)&p_qkv, g_qkv);
    cudaGetSymbolAddress((void**)&p_ws,  g_ws);
    cudaGetSymbolAddress((void**)&p_AC,  g_AC16);
    cudaGetSymbolAddress((void**)&p_BD,  g_BD16);
    cudaGetSymbolAddress((void**)&p_attn,g_attn16);
    cudaGetSymbolAddress((void**)&p_av,  g_av);
    cudaGetSymbolAddress((void**)&p_h1,  g_h1);
    cudaGetSymbolAddress((void**)&p_rcat, g_rcat);
    cudaGetSymbolAddress((void**)&p_wqkvT, g_wqkvT);
    cudaGetSymbolAddress((void**)&p_wcatT, g_wcatT);
    cudaGetSymbolAddress((void**)&p_woutT, g_woutT);
    cudaGetSymbolAddress((void**)&p_wff1T, g_wff1T);
    cudaGetSymbolAddress((void**)&p_wff2T, g_wff2T);

    cudaFuncSetAttribute((const void*)mgemm<__half,false,false,false>, cudaFuncAttributeMaxDynamicSharedMemorySize, MG_SMEM);
    cudaFuncSetAttribute((const void*)mgemm<float,true,true,false>,    cudaFuncAttributeMaxDynamicSharedMemorySize, MG_SMEM);
    cudaFuncSetAttribute((const void*)mgemm<__half,true,false,true>,   cudaFuncAttributeMaxDynamicSharedMemorySize, MG_SMEM);
    cudaFuncSetAttribute((const void*)scores_mma, cudaFuncAttributeMaxDynamicSharedMemorySize, SC_SMEM);
    cudaFuncSetAttribute((const void*)attnv_mma,  cudaFuncAttributeMaxDynamicSharedMemorySize, AV_SMEM);

    const int M = BB * NN;   // 2048
    dim3 t32(32, 8);

    // one-time packing / transposes (fp32 -> fp16)
    pack_r_kernel<<<(BB * NN * 3 * DD) / 256, 256>>>(r_t, r_c, r_p);
    pack_pf_kernel<<<2, 256>>>(bias_pf);
    transpose_batch<<<dim3(48, 16, DEPTH), t32>>>(w_qkv, p_wqkvT, DD, 3*HD, DD, 0, (size_t)3*HD*DD);
    transpose_batch<<<dim3(16, 16, DEPTH), t32>>>(w_kt, p_wcatT, DD, HD, 3*DD, 0,      (size_t)HD*3*DD);
    transpose_batch<<<dim3(16, 16, DEPTH), t32>>>(w_kc, p_wcatT, DD, HD, 3*DD, DD,     (size_t)HD*3*DD);
    transpose_batch<<<dim3(16, 16, DEPTH), t32>>>(w_kp, p_wcatT, DD, HD, 3*DD, 2*DD,   (size_t)HD*3*DD);
    transpose_batch<<<dim3(16, 16, DEPTH), t32>>>(w_out, p_woutT, HD, DD, HD, 0,       (size_t)DD*HD);
    transpose_batch<<<dim3(64, 16, DEPTH), t32>>>(w_ff1, p_wff1T, DD, FFD, DD, 0,      (size_t)FFD*DD);
    transpose_batch<<<dim3(16, 64, DEPTH), t32>>>(w_ff2, p_wff2T, FFD, DD, FFD, 0,     (size_t)DD*FFD);

    for (int l = 0; l < DEPTH; l++) {
        const float* xin = (l == 0) ? in_x : p_x;
        ln_kernel<<<M, 128>>>(xin, ln1_g + l * DD, ln1_b + l * DD, p_xn);
        mgemm<__half,false,false,false><<<dim3(24, 16), 256, MG_SMEM>>>(
            p_xn, p_wqkvT + (size_t)l * 3*HD * DD, p_qkv, 3 * HD, DD, nullptr, nullptr);
        mgemm<__half,false,false,false><<<dim3(8, 16), 256, MG_SMEM>>>(
            p_rcat, p_wcatT + (size_t)l * HD * 3*DD, p_ws, HD, 3 * DD, nullptr, nullptr);
        scores_mma<<<dim3(16, 16, BB * HH), 256, SC_SMEM>>>(p_qkv, p_ws, p_AC, p_BD);
        if (l == DEPTH - 1)
            softmax16<true><<<(BB * NN * NN / 2) / 256, 256>>>(p_AC, p_BD, p_attn, out_attn);
        else
            softmax16<false><<<(BB * NN * NN / 2) / 256, 256>>>(p_AC, p_BD, p_attn, nullptr);
        attnv_mma<<<dim3(8, BB * HH), 256, AV_SMEM>>>(p_attn, p_qkv, p_av);
        mgemm<float,true,true,false><<<dim3(8, 16), 256, MG_SMEM>>>(
            p_av, p_woutT + (size_t)l * DD * HD, p_x, DD, HD, b_out + l * DD, xin);
        ln_kernel<<<M, 128>>>(p_x, ln2_g + l * DD, ln2_b + l * DD, p_xn);
        mgemm<__half,true,false,true><<<dim3(32, 16), 256, MG_SMEM>>>(
            p_xn, p_wff1T + (size_t)l * FFD * DD, p_h1, FFD, DD, b_ff1 + l * FFD, nullptr);
        float* xdst = (l == DEPTH - 1) ? out_x : p_x;
        mgemm<float,true,true,false><<<dim3(8, 16), 256, MG_SMEM>>>(
            p_h1, p_wff2T + (size_t)l * DD * FFD, xdst, DD, FFD, b_ff2 + l * DD, p_x);
    }
}

// round 15
// speedup vs baseline: 2.8972x; 1.1217x over previous
#include <cuda_runtime.h>
#include <cuda_fp16.h>
#include <math.h>
#include <stdint.h>

#define BB 2
#define NN 1024
#define DD 512
#define HH 8
#define DHH 64
#define HD 512
#define FFD 2048
#define DEPTH 4

// ---------------- device scratch ----------------
__device__ float  g_x  [BB*NN*DD];              // fp32 residual stream
__device__ __half g_xn [BB*NN*DD];
__device__ __half g_qkv[BB*NN*3*HD];
__device__ __half g_ws [DEPTH * BB*NN*HD];      // all 4 layers, batched upfront
__device__ __half g_AC16 [(size_t)BB*HH*NN*NN];
__device__ __half g_BD16 [(size_t)BB*HH*NN*NN];
__device__ __half g_attn16[(size_t)BB*HH*NN*NN];
__device__ __half g_av [BB*NN*HD];
__device__ __half g_h1 [BB*NN*FFD];
__device__ __half g_rcat [BB*NN * 3*DD];
__device__ __half g_pf16 [HD];
__device__ __half g_wqkvT[DEPTH * 3*HD * DD];
__device__ __half g_wcatT[DEPTH * HD * 3*DD];
__device__ __half g_woutT[DEPTH * DD * HD];
__device__ __half g_wff1T[DEPTH * FFD * DD];
__device__ __half g_wff2T[DEPTH * DD * FFD];

__device__ __forceinline__ uint32_t f22h(float a, float b) {
    __half2 h = __floats2half2_rn(a, b);
    return *reinterpret_cast<uint32_t*>(&h);
}
__device__ __forceinline__ uint32_t hadd2u(uint32_t a, uint32_t b) {
    __half2 r = __hadd2(*(__half2*)&a, *(__half2*)&b);
    return *reinterpret_cast<uint32_t*>(&r);
}
__device__ __forceinline__ void mma16(float* d, const uint32_t* a, const uint32_t* b) {
    asm volatile("mma.sync.aligned.m16n8k16.row.col.f32.f16.f16.f32 "
        "{%0,%1,%2,%3}, {%4,%5,%6,%7}, {%8,%9}, {%0,%1,%2,%3};"
        : "+f"(d[0]), "+f"(d[1]), "+f"(d[2]), "+f"(d[3])
        : "r"(a[0]), "r"(a[1]), "r"(a[2]), "r"(a[3]), "r"(b[0]), "r"(b[1]));
}
#define LDSM4(R0,R1,R2,R3,ADDR) \
    asm volatile("ldmatrix.sync.aligned.m8n8.x4.shared.b16 {%0,%1,%2,%3}, [%4];" \
        : "=r"(R0), "=r"(R1), "=r"(R2), "=r"(R3) : "r"(ADDR))

// ---------------- packing ----------------
__global__ void pack_r_kernel(const float* __restrict__ rt, const float* __restrict__ rc,
                              const float* __restrict__ rp) {
    int idx = blockIdx.x * 256 + threadIdx.x;
    int m = idx / (3 * DD), k = idx % (3 * DD);
    float v;
    if (k < DD)            v = rt[m * DD + k];
    else if (k < 2 * DD)   v = rc[m * DD + k - DD];
    else                   v = rp[m * DD + k - 2 * DD];
    g_rcat[idx] = __float2half(v);
}
__global__ void pack_pf_kernel(const float* __restrict__ pf) {
    int i = blockIdx.x * 256 + threadIdx.x;
    if (i < HD) g_pf16[i] = __float2half(pf[i]);
}

// ---------------- weight transpose: src [R,C] fp32 -> dst [C, dstStride] fp16 ----------------
__global__ void transpose_batch(const float* __restrict__ src, __half* __restrict__ dst,
                                int R, int C, int dstStride, int colBase, size_t dstLayer) {
    __shared__ float t[32][33];
    size_t soff = (size_t)blockIdx.z * R * C;
    size_t doff = (size_t)blockIdx.z * dstLayer;
    int c0 = blockIdx.x * 32, r0 = blockIdx.y * 32;
    int x = threadIdx.x, y = threadIdx.y;
#pragma unroll
    for (int i = 0; i < 32; i += 8)
        t[y + i][x] = src[soff + (size_t)(r0 + y + i) * C + c0 + x];
    __syncthreads();
#pragma unroll
    for (int i = 0; i < 32; i += 8)
        dst[doff + (size_t)(c0 + y + i) * dstStride + colBase + r0 + x] = __float2half(t[x][y + i]);
}

// ---------------- layernorm: fp32 in -> fp16 out ----------------
__global__ void ln_kernel(const float* __restrict__ x, const float* __restrict__ g,
                          const float* __restrict__ bta, __half* __restrict__ y) {
    __shared__ float red[128];
    int row = blockIdx.x;
    int tid = threadIdx.x;
    const float4* xr = (const float4*)(x + (size_t)row * DD);
    float4 v = xr[tid];
    red[tid] = v.x + v.y + v.z + v.w;
    __syncthreads();
    for (int o = 64; o > 0; o >>= 1) { if (tid < o) red[tid] += red[tid + o]; __syncthreads(); }
    float mean = red[0] * (1.0f / DD);
    __syncthreads();
    float dx = v.x - mean, dy = v.y - mean, dz = v.z - mean, dw = v.w - mean;
    red[tid] = dx*dx + dy*dy + dz*dz + dw*dw;
    __syncthreads();
    for (int o = 64; o > 0; o >>= 1) { if (tid < o) red[tid] += red[tid + o]; __syncthreads(); }
    float rstd = rsqrtf(red[0] * (1.0f / DD) + 1e-5f);
    float4 gv = ((const float4*)g)[tid];
    float4 bv = ((const float4*)bta)[tid];
    uint2 o2;
    o2.x = f22h(dx * rstd * gv.x + bv.x, dy * rstd * gv.y + bv.y);
    o2.y = f22h(dz * rstd * gv.z + bv.z, dw * rstd * gv.w + bv.w);
    *(uint2*)(y + (size_t)row * DD + tid * 4) = o2;
}

__device__ __forceinline__ float gelu_exact(float v) {
    return 0.5f * v * (1.0f + erff(v * 0.70710678118654752f));
}

// ---------------- fp16 mma GEMM, ldmatrix, BK=64: C = A[M,K] @ Bt[Nc,K]^T ----------------
// 128x64 CTA tile, 256 threads. Row-major smem tiles, 144B stride (conflict-free).
#define A_STRIDE 144
#define A_BYTES (128 * A_STRIDE)          // 18432
#define B_STRIDE 144
#define B_BYTES (64 * B_STRIDE)           // 9216
#define MG_SMEM (2 * (A_BYTES + B_BYTES)) // 55296

template<class CT, bool BIAS, bool RES, bool GELU_>
__global__ void __launch_bounds__(256, 2)
mgemm(const __half* __restrict__ A, const __half* __restrict__ Bt, CT* __restrict__ C,
      int Nc, int K, const float* __restrict__ bias, const float* __restrict__ res,
      size_t bzStride, size_t czStride) {
    extern __shared__ char smc[];
    const uint32_t sbase = (uint32_t)__cvta_generic_to_shared(smc);
    const uint32_t aOff[2] = { 0, A_BYTES };
    const uint32_t bOff[2] = { 2 * A_BYTES, 2 * A_BYTES + B_BYTES };

    const int tid = threadIdx.x;
    const int wid = tid >> 5, lid = tid & 31;
    const int row0 = blockIdx.y * 128;
    const int col0 = blockIdx.x * 64;
    const size_t cz = (size_t)blockIdx.z * czStride;

    const int arow = tid >> 1;
    const int aO   = (tid & 1) * 64;     // byte offset within row (2 threads per 128B row)
    const int brow = tid >> 2;
    const int bO   = (tid & 3) * 32;
    const __half* gA = A  + (size_t)(row0 + arow) * K + (tid & 1) * 32;
    const __half* gB = Bt + (size_t)blockIdx.z * bzStride + (size_t)(col0 + brow) * K + (tid & 3) * 16;

    float acc[2][4][4];
#pragma unroll
    for (int mt = 0; mt < 2; mt++)
#pragma unroll
        for (int nt = 0; nt < 4; nt++)
#pragma unroll
            for (int r = 0; r < 4; r++) acc[mt][nt][r] = 0.f;

    uint4 a0, a1, a2, a3, b0, b1;
    auto loadA = [&](const __half* src) {
        a0 = *(const uint4*)src;        a1 = *(const uint4*)(src + 8);
        a2 = *(const uint4*)(src + 16); a3 = *(const uint4*)(src + 24);
    };
    auto loadB = [&](const __half* src) {
        b0 = *(const uint4*)src; b1 = *(const uint4*)(src + 8);
    };
    auto stA = [&](int p) {
        char* d = smc + aOff[p] + arow * A_STRIDE + aO;
        *(uint4*)d = a0; *(uint4*)(d + 16) = a1;
        *(uint4*)(d + 32) = a2; *(uint4*)(d + 48) = a3;
    };
    auto stB = [&](int p) {
        char* d = smc + bOff[p] + brow * B_STRIDE + bO;
        *(uint4*)d = b0; *(uint4*)(d + 16) = b1;
    };

    const int nch = K >> 6;
    loadA(gA); loadB(gB);
    stA(0); stB(0);
    __syncthreads();

    const int wm = (wid & 3) * 32;
    const int wn = (wid >> 2) * 32;
    const uint32_t aLane = (lid & 15) * A_STRIDE + (lid >> 4) * 16;
    const uint32_t bLane = (wn + lid) * B_STRIDE;

    int p = 0;
    for (int c = 0; c < nch; c++) {
        if (c + 1 < nch) {
            loadA(gA + (size_t)(c + 1) * 64);
            loadB(gB + (size_t)(c + 1) * 64);
        }
        const uint32_t aS = sbase + aOff[p];
        const uint32_t bS = sbase + bOff[p];
#pragma unroll
        for (int s = 0; s < 4; s++) {
            const uint32_t kO = s * 32;
            uint32_t afr[2][4];
#pragma unroll
            for (int mt = 0; mt < 2; mt++)
                LDSM4(afr[mt][0], afr[mt][1], afr[mt][2], afr[mt][3],
                      aS + (wm + mt * 16) * A_STRIDE + aLane + kO);
            uint32_t bb0[4], bb1[4];
            LDSM4(bb0[0], bb0[1], bb0[2], bb0[3], bS + bLane + kO);
            LDSM4(bb1[0], bb1[1], bb1[2], bb1[3], bS + bLane + kO + 16);
#pragma unroll
            for (int mt = 0; mt < 2; mt++)
#pragma unroll
                for (int nt = 0; nt < 4; nt++) {
                    uint32_t bfr[2] = { bb0[nt], bb1[nt] };
                    mma16(acc[mt][nt], afr[mt], bfr);
                }
        }
        if (c + 1 < nch) { stA(1 - p); stB(1 - p); }
        __syncthreads();
        p ^= 1;
    }

    const int g  = lid >> 2;
    const int tg = lid & 3;
#pragma unroll
    for (int mt = 0; mt < 2; mt++) {
#pragma unroll
        for (int rh = 0; rh < 2; rh++) {
            int row = row0 + wm + mt * 16 + g + rh * 8;
#pragma unroll
            for (int nt = 0; nt < 4; nt++) {
                int col = col0 + wn + nt * 8 + tg * 2;
                size_t idx = cz + (size_t)row * Nc + col;
                float v0 = acc[mt][nt][rh * 2 + 0];
                float v1 = acc[mt][nt][rh * 2 + 1];
                if (BIAS)  { float2 bv = *(const float2*)(bias + col); v0 += bv.x; v1 += bv.y; }
                if (RES)   { float2 rv = *(const float2*)(res + (size_t)row * Nc + col); v0 += rv.x; v1 += rv.y; }
                if (GELU_) { v0 = gelu_exact(v0); v1 = gelu_exact(v1); }
                if constexpr (sizeof(CT) == 2) {
                    *(__half2*)((__half*)C + idx) = __floats2half2_rn(v0, v1);
                } else {
                    *(float2*)((float*)C + idx) = make_float2(v0, v1);
                }
            }
        }
    }
}

// ---------------- scores via fp16 mma + ldmatrix (per b,h; K=64) ----------------
#define SC_STRIDE 144
#define SC_MAT (64 * SC_STRIDE)           // 9216 B
#define SC_SMEM (3 * SC_MAT)              // 27648 B
__global__ void __launch_bounds__(256, 4)
scores_mma(const __half* __restrict__ qkv, const __half* __restrict__ ws,
           __half* __restrict__ AC, __half* __restrict__ BD) {
    extern __shared__ char smc[];
    const uint32_t sbase = (uint32_t)__cvta_generic_to_shared(smc);
    const int bh = blockIdx.z;
    const int b = bh >> 3, h = bh & 7;
    const int i0 = blockIdx.y << 6, j0 = blockIdx.x << 6;
    const int tid = threadIdx.x;

    const int r  = tid >> 2;
    const int d0 = (tid & 3) << 4;
    const int rowO = r * SC_STRIDE + (tid & 3) * 32;
    const __half* qb = qkv + (size_t)(b * NN + i0 + r) * (3 * HD) + h * DHH + d0;
    const __half* kb = qkv + (size_t)(b * NN + j0 + r) * (3 * HD) + HD + h * DHH + d0;
    const __half* wb = ws  + (size_t)(b * NN + j0 + r) * HD + h * DHH + d0;
    const __half* pf = g_pf16 + h * DHH + d0;
    {
        uint4 q0 = *(const uint4*)qb, q1 = *(const uint4*)(qb + 8);
        uint4 p0 = *(const uint4*)pf, p1 = *(const uint4*)(pf + 8);
        q0.x = hadd2u(q0.x, p0.x); q0.y = hadd2u(q0.y, p0.y);
        q0.z = hadd2u(q0.z, p0.z); q0.w = hadd2u(q0.w, p0.w);
        q1.x = hadd2u(q1.x, p1.x); q1.y = hadd2u(q1.y, p1.y);
        q1.z = hadd2u(q1.z, p1.z); q1.w = hadd2u(q1.w, p1.w);
        *(uint4*)(smc + rowO)      = q0;
        *(uint4*)(smc + rowO + 16) = q1;
        uint4 k0 = *(const uint4*)kb, k1 = *(const uint4*)(kb + 8);
        *(uint4*)(smc + SC_MAT + rowO)      = k0;
        *(uint4*)(smc + SC_MAT + rowO + 16) = k1;
        uint4 w0 = *(const uint4*)wb, w1 = *(const uint4*)(wb + 8);
        *(uint4*)(smc + 2 * SC_MAT + rowO)      = w0;
        *(uint4*)(smc + 2 * SC_MAT + rowO + 16) = w1;
    }
    __syncthreads();

    const int wid = tid >> 5, lid = tid & 31;
    const int grp = wid >> 2;
    const int w2  = wid & 3;
    const int wm  = (w2 & 1) * 32;
    const int wn  = (w2 >> 1) * 32;
    const uint32_t aS = sbase;
    const uint32_t bS = sbase + (grp ? 2 * SC_MAT : SC_MAT);
    const uint32_t aLane = (lid & 15) * SC_STRIDE + (lid >> 4) * 16;
    const uint32_t bLane = (wn + lid) * SC_STRIDE;

    float acc[2][4][4];
#pragma unroll
    for (int mt = 0; mt < 2; mt++)
#pragma unroll
        for (int nt = 0; nt < 4; nt++)
#pragma unroll
            for (int q = 0; q < 4; q++) acc[mt][nt][q] = 0.f;

#pragma unroll
    for (int s = 0; s < 4; s++) {
        const uint32_t kO = s * 32;
        uint32_t afr[2][4];
#pragma unroll
        for (int mt = 0; mt < 2; mt++)
            LDSM4(afr[mt][0], afr[mt][1], afr[mt][2], afr[mt][3],
                  aS + (wm + mt * 16) * SC_STRIDE + aLane + kO);
        uint32_t b0[4], b1[4];
        LDSM4(b0[0], b0[1], b0[2], b0[3], bS + bLane + kO);
        LDSM4(b1[0], b1[1], b1[2], b1[3], bS + bLane + kO + 16);
#pragma unroll
        for (int mt = 0; mt < 2; mt++)
#pragma unroll
            for (int nt = 0; nt < 4; nt++) {
                uint32_t bfr[2] = { b0[nt], b1[nt] };
                mma16(acc[mt][nt], afr[mt], bfr);
            }
    }

    __half* Out = grp ? BD : AC;
    const size_t base = ((size_t)bh << 20);
    const int g = lid >> 2, tg = lid & 3;
#pragma unroll
    for (int mt = 0; mt < 2; mt++) {
#pragma unroll
        for (int rh = 0; rh < 2; rh++) {
            int i = i0 + wm + mt * 16 + g + rh * 8;
#pragma unroll
            for (int nt = 0; nt < 4; nt++) {
                int j = j0 + wn + nt * 8 + tg * 2;
                __half2 h2 = __floats2half2_rn(acc[mt][nt][rh * 2 + 0], acc[mt][nt][rh * 2 + 1]);
                *(__half2*)(Out + base + ((size_t)i << 10) + j) = h2;
            }
        }
    }
}

// ---------------- dots + rel_shift + softmax over heads (fp16 in/out) ----------------
template<bool LAST>
__global__ void softmax16(const __half* __restrict__ AC, const __half* __restrict__ BD,
                          __half* __restrict__ attn, float* __restrict__ out_attn) {
    int gid = blockIdx.x * 256 + threadIdx.x;
    int b = gid >> 19;
    int ijp = gid & ((1 << 19) - 1);
    int ij = ijp << 1;
    int i = ij >> 10, j = ij & 1023;

    int m0 = (i + 1) * NN + j;
    int i2a = m0 / (NN + 1);
    int ka  = m0 - i2a * (NN + 1);
    int i2b, kb;
    if (ka == NN) { i2b = i2a + 1; kb = 0; }
    else          { i2b = i2a;     kb = ka + 1; }

    size_t pb = ((size_t)(b * HH)) << 20;
    size_t sa = ((size_t)i2a << 10) + (ka - 1);
    size_t sb = ((size_t)i2b << 10) + (kb - 1);

    float va[8], vb[8];
#pragma unroll
    for (int h = 0; h < 8; h++) {
        size_t hp = pb + ((size_t)h << 20);
        __half2 ac2 = *(const __half2*)(AC + hp + ij);
        float bda = (ka != 0) ? __half2float(BD[hp + sa]) : 0.f;
        float bdb = (kb != 0) ? __half2float(BD[hp + sb]) : 0.f;
        va[h] = (__low2float(ac2)  + bda * (1.0f / 3.0f)) * 0.125f;
        vb[h] = (__high2float(ac2) + bdb * (1.0f / 3.0f)) * 0.125f;
    }
    float mxa = va[0], mxb = vb[0];
#pragma unroll
    for (int h = 1; h < 8; h++) { mxa = fmaxf(mxa, va[h]); mxb = fmaxf(mxb, vb[h]); }
    float sa_ = 0.f, sb_ = 0.f;
#pragma unroll
    for (int h = 0; h < 8; h++) {
        va[h] = __expf(va[h] - mxa); sa_ += va[h];
        vb[h] = __expf(vb[h] - mxb); sb_ += vb[h];
    }
    float ia = 1.0f / sa_, ib = 1.0f / sb_;
#pragma unroll
    for (int h = 0; h < 8; h++) {
        size_t hp = pb + ((size_t)h << 20);
        float oa = va[h] * ia, ob = vb[h] * ib;
        *(__half2*)(attn + hp + ij) = __floats2half2_rn(oa, ob);
        if (LAST) {
            float2 o2 = make_float2(oa, ob);
            *(float2*)(out_attn + hp + ij) = o2;
        }
    }
}

// ---------------- attn(fp16) @ v(fp16) -> av(fp16): ldmatrix A, legacy B (unchanged) ----------------
#define AT_STRIDE 80
#define AT_BYTES (128 * AT_STRIDE)         // 10240
#define VBST 72
#define VB_BYTES (16 * VBST * 4)           // 4608
#define AV_SMEM (2 * AT_BYTES + 2 * VB_BYTES)
__global__ void __launch_bounds__(256, 2)
attnv_mma(const __half* __restrict__ attn, const __half* __restrict__ qkv,
          __half* __restrict__ av) {
    extern __shared__ char smc[];
    const uint32_t sbase = (uint32_t)__cvta_generic_to_shared(smc);
    const uint32_t aOff[2] = { 0, AT_BYTES };
    uint32_t* vB[2] = { (uint32_t*)(smc + 2 * AT_BYTES), (uint32_t*)(smc + 2 * AT_BYTES + VB_BYTES) };

    const int bh = blockIdx.y;
    const int b = bh >> 3, h = bh & 7;
    const int i0 = blockIdx.x << 7;
    const int tid = threadIdx.x;
    const int wid = tid >> 5, lid = tid & 31;

    const int arow = tid >> 1;
    const int aO   = (tid & 1) * 32;
    const int jp   = tid >> 4;
    const int d0   = (tid & 15) * 4;
    const __half* gA = attn + ((size_t)bh << 20) + ((size_t)(i0 + arow) << 10) + (tid & 1) * 16;
    const __half* gV = qkv + 2 * HD + h * DHH + d0;

    float acc[2][4][4];
#pragma unroll
    for (int mt = 0; mt < 2; mt++)
#pragma unroll
        for (int nt = 0; nt < 4; nt++)
#pragma unroll
            for (int q = 0; q < 4; q++) acc[mt][nt][q] = 0.f;

    uint4 ua, ub;
    uint32_t bv2[4];
    auto loadA = [&](const __half* src) { ua = *(const uint4*)src; ub = *(const uint4*)(src + 8); };
    auto loadV = [&](int jbase) {
        const __half* v0 = gV + (size_t)(b * NN + jbase + 2 * jp) * (3 * HD);
        const __half* v1 = v0 + 3 * HD;
        uint2 a = *(const uint2*)v0;
        uint2 c = *(const uint2*)v1;
        __half2 a0 = *(__half2*)&a.x, a1 = *(__half2*)&a.y;
        __half2 c0 = *(__half2*)&c.x, c1 = *(__half2*)&c.y;
        __half2 r0 = __halves2half2(__low2half(a0),  __low2half(c0));
        __half2 r1 = __halves2half2(__high2half(a0), __high2half(c0));
        __half2 r2 = __halves2half2(__low2half(a1),  __low2half(c1));
        __half2 r3 = __halves2half2(__high2half(a1), __high2half(c1));
        bv2[0] = *(uint32_t*)&r0; bv2[1] = *(uint32_t*)&r1;
        bv2[2] = *(uint32_t*)&r2; bv2[3] = *(uint32_t*)&r3;
    };
    auto stA = [&](int p) {
        char* d = smc + aOff[p] + arow * AT_STRIDE + aO;
        *(uint4*)d = ua; *(uint4*)(d + 16) = ub;
    };

    const int nch = NN >> 5;
    loadA(gA); loadV(0);
    stA(0);
    *(uint4*)&vB[0][jp * VBST + d0] = make_uint4(bv2[0], bv2[1], bv2[2], bv2[3]);
    __syncthreads();

    const int wm = (wid & 3) * 32;
    const int wn = (wid >> 2) * 32;
    const int g  = lid >> 2;
    const int tg = lid & 3;
    const uint32_t aLane = (lid & 15) * AT_STRIDE + (lid >> 4) * 16;

    int p = 0;
    for (int c = 0; c < nch; c++) {
        if (c + 1 < nch) {
            loadA(gA + (size_t)(c + 1) * 32);
            loadV((c + 1) * 32);
        }
        const uint32_t aS = sbase + aOff[p];
        const uint32_t* cB = vB[p];
#pragma unroll
        for (int s = 0; s < 2; s++) {
            const int k0 = s * 8;
            uint32_t afr[2][4];
#pragma unroll
            for (int mt = 0; mt < 2; mt++)
                LDSM4(afr[mt][0], afr[mt][1], afr[mt][2], afr[mt][3],
                      aS + (wm + mt * 16) * AT_STRIDE + aLane + s * 32);
            uint32_t bfr[4][2];
#pragma unroll
            for (int nt = 0; nt < 4; nt++) {
                int cn = wn + nt * 8 + g;
                bfr[nt][0] = cB[(k0 + tg)     * VBST + cn];
                bfr[nt][1] = cB[(k0 + tg + 4) * VBST + cn];
            }
#pragma unroll
            for (int mt = 0; mt < 2; mt++)
#pragma unroll
                for (int nt = 0; nt < 4; nt++)
                    mma16(acc[mt][nt], afr[mt], bfr[nt]);
        }
        if (c + 1 < nch) {
            stA(1 - p);
            *(uint4*)&vB[1 - p][jp * VBST + d0] = make_uint4(bv2[0], bv2[1], bv2[2], bv2[3]);
        }
        __syncthreads();
        p ^= 1;
    }

#pragma unroll
    for (int mt = 0; mt < 2; mt++) {
#pragma unroll
        for (int rh = 0; rh < 2; rh++) {
            int row = i0 + wm + mt * 16 + g + rh * 8;
#pragma unroll
            for (int nt = 0; nt < 4; nt++) {
                int col = wn + nt * 8 + tg * 2;
                __half2 h2 = __floats2half2_rn(acc[mt][nt][rh * 2 + 0], acc[mt][nt][rh * 2 + 1]);
                *(__half2*)(av + (size_t)(b * NN + row) * HD + h * DHH + col) = h2;
            }
        }
    }
}

// ---------------- host orchestration ----------------
extern "C" void kernel_launch(void* const* d_in, const int* in_sizes, int n_in,
                              void* d_out, int out_size) {
    (void)in_sizes; (void)n_in; (void)out_size;
    const float* in_x   = (const float*)d_in[0];
    const float* r_t    = (const float*)d_in[1];
    const float* r_c    = (const float*)d_in[2];
    const float* r_p    = (const float*)d_in[3];
    const float* bias_pf= (const float*)d_in[4];
    const float* ln1_g  = (const float*)d_in[5];
    const float* ln1_b  = (const float*)d_in[6];
    const float* w_qkv  = (const float*)d_in[7];
    const float* w_out  = (const float*)d_in[8];
    const float* b_out  = (const float*)d_in[9];
    const float* w_kt   = (const float*)d_in[10];
    const float* w_kc   = (const float*)d_in[11];
    const float* w_kp   = (const float*)d_in[12];
    const float* ln2_g  = (const float*)d_in[13];
    const float* ln2_b  = (const float*)d_in[14];
    const float* w_ff1  = (const float*)d_in[15];
    const float* b_ff1  = (const float*)d_in[16];
    const float* w_ff2  = (const float*)d_in[17];
    const float* b_ff2  = (const float*)d_in[18];

    float* out_x    = (float*)d_out;
    float* out_attn = out_x + (size_t)BB * NN * DD;

    float *p_x;
    __half *p_xn, *p_qkv, *p_ws, *p_av, *p_h1;
    __half *p_AC, *p_BD, *p_attn, *p_rcat;
    __half *p_wqkvT, *p_wcatT, *p_woutT, *p_wff1T, *p_wff2T;
    cudaGetSymbolAddress((void**)&p_x,   g_x);
    cudaGetSymbolAddress((void**)&p_xn,  g_xn);
    cudaGetSymbolAddress((void**)&p_qkv, g_qkv);
    cudaGetSymbolAddress((void**)&p_ws,  g_ws);
    cudaGetSymbolAddress((void**)&p_AC,  g_AC16);
    cudaGetSymbolAddress((void**)&p_BD,  g_BD16);
    cudaGetSymbolAddress((void**)&p_attn,g_attn16);
    cudaGetSymbolAddress((void**)&p_av,  g_av);
    cudaGetSymbolAddress((void**)&p_h1,  g_h1);
    cudaGetSymbolAddress((void**)&p_rcat, g_rcat);
    cudaGetSymbolAddress((void**)&p_wqkvT, g_wqkvT);
    cudaGetSymbolAddress((void**)&p_wcatT, g_wcatT);
    cudaGetSymbolAddress((void**)&p_woutT, g_woutT);
    cudaGetSymbolAddress((void**)&p_wff1T, g_wff1T);
    cudaGetSymbolAddress((void**)&p_wff2T, g_wff2T);

    cudaFuncSetAttribute((const void*)mgemm<__half,false,false,false>, cudaFuncAttributeMaxDynamicSharedMemorySize, MG_SMEM);
    cudaFuncSetAttribute((const void*)mgemm<float,true,true,false>,    cudaFuncAttributeMaxDynamicSharedMemorySize, MG_SMEM);
    cudaFuncSetAttribute((const void*)mgemm<__half,true,false,true>,   cudaFuncAttributeMaxDynamicSharedMemorySize, MG_SMEM);
    cudaFuncSetAttribute((const void*)scores_mma, cudaFuncAttributeMaxDynamicSharedMemorySize, SC_SMEM);
    cudaFuncSetAttribute((const void*)attnv_mma,  cudaFuncAttributeMaxDynamicSharedMemorySize, AV_SMEM);

    const int M = BB * NN;   // 2048
    dim3 t32(32, 8);

    // one-time packing / transposes (fp32 -> fp16)
    pack_r_kernel<<<(BB * NN * 3 * DD) / 256, 256>>>(r_t, r_c, r_p);
    pack_pf_kernel<<<2, 256>>>(bias_pf);
    transpose_batch<<<dim3(48, 16, DEPTH), t32>>>(w_qkv, p_wqkvT, DD, 3*HD, DD, 0, (size_t)3*HD*DD);
    transpose_batch<<<dim3(16, 16, DEPTH), t32>>>(w_kt, p_wcatT, DD, HD, 3*DD, 0,      (size_t)HD*3*DD);
    transpose_batch<<<dim3(16, 16, DEPTH), t32>>>(w_kc, p_wcatT, DD, HD, 3*DD, DD,     (size_t)HD*3*DD);
    transpose_batch<<<dim3(16, 16, DEPTH), t32>>>(w_kp, p_wcatT, DD, HD, 3*DD, 2*DD,   (size_t)HD*3*DD);
    transpose_batch<<<dim3(16, 16, DEPTH), t32>>>(w_out, p_woutT, HD, DD, HD, 0,       (size_t)DD*HD);
    transpose_batch<<<dim3(64, 16, DEPTH), t32>>>(w_ff1, p_wff1T, DD, FFD, DD, 0,      (size_t)FFD*DD);
    transpose_batch<<<dim3(16, 64, DEPTH), t32>>>(w_ff2, p_wff2T, FFD, DD, FFD, 0,     (size_t)DD*FFD);

    // ws for ALL layers in one batched launch (layer-invariant input)
    mgemm<__half,false,false,false><<<dim3(8, 16, DEPTH), 256, MG_SMEM>>>(
        p_rcat, p_wcatT, p_ws, HD, 3 * DD, nullptr, nullptr,
        (size_t)HD * 3 * DD, (size_t)M * HD);

    for (int l = 0; l < DEPTH; l++) {
        const float* xin = (l == 0) ? in_x : p_x;
        ln_kernel<<<M, 128>>>(xin, ln1_g + l * DD, ln1_b + l * DD, p_xn);
        mgemm<__half,false,false,false><<<dim3(24, 16), 256, MG_SMEM>>>(
            p_xn, p_wqkvT + (size_t)l * 3*HD * DD, p_qkv, 3 * HD, DD, nullptr, nullptr, 0, 0);
        scores_mma<<<dim3(16, 16, BB * HH), 256, SC_SMEM>>>(
            p_qkv, p_ws + (size_t)l * M * HD, p_AC, p_BD);
        if (l == DEPTH - 1)
            softmax16<true><<<(BB * NN * NN / 2) / 256, 256>>>(p_AC, p_BD, p_attn, out_attn);
        else
            softmax16<false><<<(BB * NN * NN / 2) / 256, 256>>>(p_AC, p_BD, p_attn, nullptr);
        attnv_mma<<<dim3(8, BB * HH), 256, AV_SMEM>>>(p_attn, p_qkv, p_av);
        mgemm<float,true,true,false><<<dim3(8, 16), 256, MG_SMEM>>>(
            p_av, p_woutT + (size_t)l * DD * HD, p_x, DD, HD, b_out + l * DD, xin, 0, 0);
        ln_kernel<<<M, 128>>>(p_x, ln2_g + l * DD, ln2_b + l * DD, p_xn);
        mgemm<__half,true,false,true><<<dim3(32, 16), 256, MG_SMEM>>>(
            p_xn, p_wff1T + (size_t)l * FFD * DD, p_h1, FFD, DD, b_ff1 + l * FFD, nullptr, 0, 0);
        float* xdst = (l == DEPTH - 1) ? out_x : p_x;
        mgemm<float,true,true,false><<<dim3(8, 16), 256, MG_SMEM>>>(
            p_h1, p_wff2T + (size_t)l * DD * FFD, xdst, DD, FFD, b_ff2 + l * DD, p_x, 0, 0);
    }
}